// round 1
// baseline (speedup 1.0000x reference)
#include <cuda_runtime.h>
#include <cuda_bf16.h>
#include <math.h>

#define Bv 2
#define Tv 2048
#define Dv 1024
#define Hv 16
#define HDv 64
#define SCv 64
#define STv 16
#define Mrows (Bv*Tv)   // 4096
#define EPSR 1.1920929e-07f

// ---------------- scratch (device globals; no allocation allowed) ----------
__device__ float g_h   [Mrows*Dv];
__device__ float g_qkv [Mrows*3*Dv];
__device__ float g_attn[Mrows*Dv];
__device__ float g_x1  [Mrows*Dv];
__device__ float g_h2  [Mrows*Dv];
__device__ float g_z   [Mrows*SCv];
__device__ float g_gate[Mrows*SCv];
__device__ float g_Bi  [Mrows*STv];
__device__ float g_Ci  [Mrows*STv];
__device__ float g_dt  [Mrows*SCv];
__device__ float g_y   [Mrows*SCv];

// ---------------- RMSNorm ----------------
__global__ __launch_bounds__(256) void rmsnorm_kernel(
    const float* __restrict__ x, const float* __restrict__ w, float* __restrict__ o)
{
    int row = blockIdx.x;
    const float4* xr = (const float4*)(x + (size_t)row*Dv);
    float4 v = xr[threadIdx.x];
    float ss = v.x*v.x + v.y*v.y + v.z*v.z + v.w*v.w;
    #pragma unroll
    for (int off=16; off; off>>=1) ss += __shfl_xor_sync(0xffffffffu, ss, off);
    __shared__ float sm[8];
    int wid = threadIdx.x>>5, lane = threadIdx.x&31;
    if (lane==0) sm[wid] = ss;
    __syncthreads();
    float tot = sm[0]+sm[1]+sm[2]+sm[3]+sm[4]+sm[5]+sm[6]+sm[7];
    float scale = rsqrtf(tot*(1.0f/Dv) + EPSR);
    const float4* wr = (const float4*)w;
    float4 wv = wr[threadIdx.x];
    float4 ov = make_float4(v.x*scale*wv.x, v.y*scale*wv.y, v.z*scale*wv.z, v.w*scale*wv.w);
    ((float4*)(o + (size_t)row*Dv))[threadIdx.x] = ov;
}

// ---------------- Generic tiled SGEMM: C[M,N] = A[M,K] @ W[N,K]^T (+bias)(+act)(+res)
// act: 0 none, 1 silu, 2 softplus. bias/res may be null.
__global__ __launch_bounds__(256) void gemm64_kernel(
    const float* __restrict__ A, const float* __restrict__ W,
    const float* __restrict__ bias, const float* __restrict__ res,
    float* __restrict__ C, int M, int N, int K, int act)
{
    __shared__ float As[16][68];
    __shared__ float Ws[16][68];
    const int tid = threadIdx.x;
    const int bm = blockIdx.y*64, bn = blockIdx.x*64;
    const int lr = tid>>2;          // 0..63
    const int lc = (tid&3)<<2;      // 0,4,8,12
    const int ty = tid>>4, tx = tid&15;
    float acc[4][4];
    #pragma unroll
    for (int i=0;i<4;i++)
        #pragma unroll
        for (int j=0;j<4;j++) acc[i][j]=0.f;

    for (int k0=0; k0<K; k0+=16) {
        float4 a = *(const float4*)&A[(size_t)(bm+lr)*K + k0 + lc];
        As[lc+0][lr]=a.x; As[lc+1][lr]=a.y; As[lc+2][lr]=a.z; As[lc+3][lr]=a.w;
        float4 w = make_float4(0.f,0.f,0.f,0.f);
        if (bn+lr < N) w = *(const float4*)&W[(size_t)(bn+lr)*K + k0 + lc];
        Ws[lc+0][lr]=w.x; Ws[lc+1][lr]=w.y; Ws[lc+2][lr]=w.z; Ws[lc+3][lr]=w.w;
        __syncthreads();
        #pragma unroll
        for (int k=0;k<16;k++){
            float4 av = *(const float4*)&As[k][ty*4];
            float4 wv = *(const float4*)&Ws[k][tx*4];
            float aa[4] = {av.x,av.y,av.z,av.w};
            float ww[4] = {wv.x,wv.y,wv.z,wv.w};
            #pragma unroll
            for (int i=0;i<4;i++)
                #pragma unroll
                for (int j=0;j<4;j++) acc[i][j] = fmaf(aa[i], ww[j], acc[i][j]);
        }
        __syncthreads();
    }

    const int col = bn + tx*4;
    if (col < N) {
        float4 bv = make_float4(0,0,0,0);
        if (bias) bv = *(const float4*)&bias[col];
        #pragma unroll
        for (int i=0;i<4;i++){
            int row = bm + ty*4 + i;
            float c[4];
            #pragma unroll
            for (int j=0;j<4;j++) c[j] = acc[i][j];
            if (bias) { c[0]+=bv.x; c[1]+=bv.y; c[2]+=bv.z; c[3]+=bv.w; }
            if (act==1) {
                #pragma unroll
                for (int j=0;j<4;j++) c[j] = c[j] / (1.f + expf(-c[j]));
            } else if (act==2) {
                #pragma unroll
                for (int j=0;j<4;j++) c[j] = (c[j] > 20.f) ? c[j] : log1pf(expf(c[j]));
            }
            if (res) {
                float4 rv = *(const float4*)&res[(size_t)row*N + col];
                c[0]+=rv.x; c[1]+=rv.y; c[2]+=rv.z; c[3]+=rv.w;
            }
            *(float4*)&C[(size_t)row*N + col] = make_float4(c[0],c[1],c[2],c[3]);
        }
    }
}

// ---------------- Flash attention (fp32, causal) ----------------
// grid (T/64, H, B), 256 threads, dynamic smem = 4*64*68*4 bytes
__global__ __launch_bounds__(256) void attn_kernel(
    const float* __restrict__ qkv, float* __restrict__ out)
{
    extern __shared__ float smem[];
    float* Qs = smem;             // 64*68
    float* Ks = Qs + 64*68;
    float* Vs = Ks + 64*68;
    float* Ps = Vs + 64*68;
    const int tid = threadIdx.x;
    const int qt = blockIdx.x, h = blockIdx.y, b = blockIdx.z;
    const int ty = tid>>4, tx = tid&15;

    #pragma unroll
    for (int i=0;i<4;i++){
        int t4 = tid + i*256;
        int r = t4>>4, c4 = (t4&15)<<2;
        *(float4*)&Qs[r*68 + c4] =
            *(const float4*)&qkv[((size_t)(b*Tv + qt*64 + r))*(3*Dv) + h*HDv + c4];
    }

    float m[4], l[4], O[4][4];
    #pragma unroll
    for (int i=0;i<4;i++){
        m[i] = -1e30f; l[i] = 0.f;
        #pragma unroll
        for (int j=0;j<4;j++) O[i][j] = 0.f;
    }

    for (int kt=0; kt<=qt; ++kt) {
        __syncthreads();
        #pragma unroll
        for (int i=0;i<4;i++){
            int t4 = tid + i*256;
            int r = t4>>4, c4 = (t4&15)<<2;
            size_t base = ((size_t)(b*Tv + kt*64 + r))*(3*Dv) + h*HDv + c4;
            *(float4*)&Ks[r*68 + c4] = *(const float4*)&qkv[base + Dv];
            *(float4*)&Vs[r*68 + c4] = *(const float4*)&qkv[base + 2*Dv];
        }
        __syncthreads();

        float S[4][4];
        #pragma unroll
        for (int i=0;i<4;i++)
            #pragma unroll
            for (int j=0;j<4;j++) S[i][j] = 0.f;

        #pragma unroll
        for (int d4=0; d4<16; d4++){
            float4 qv[4], kv[4];
            #pragma unroll
            for (int i=0;i<4;i++) qv[i] = *(const float4*)&Qs[(ty*4+i)*68 + d4*4];
            #pragma unroll
            for (int j=0;j<4;j++) kv[j] = *(const float4*)&Ks[(tx*4+j)*68 + d4*4];
            #pragma unroll
            for (int i=0;i<4;i++){
                #pragma unroll
                for (int j=0;j<4;j++){
                    S[i][j] = fmaf(qv[i].x, kv[j].x, S[i][j]);
                    S[i][j] = fmaf(qv[i].y, kv[j].y, S[i][j]);
                    S[i][j] = fmaf(qv[i].z, kv[j].z, S[i][j]);
                    S[i][j] = fmaf(qv[i].w, kv[j].w, S[i][j]);
                }
            }
        }

        #pragma unroll
        for (int i=0;i<4;i++){
            int qg = qt*64 + ty*4 + i;
            #pragma unroll
            for (int j=0;j<4;j++){
                int kg = kt*64 + tx*4 + j;
                S[i][j] = (kg <= qg) ? S[i][j]*0.125f : -1e30f;
            }
            float rm = fmaxf(fmaxf(S[i][0],S[i][1]), fmaxf(S[i][2],S[i][3]));
            #pragma unroll
            for (int o=8;o>0;o>>=1) rm = fmaxf(rm, __shfl_xor_sync(0xffffffffu, rm, o, 16));
            float mn = fmaxf(m[i], rm);
            float corr = expf(m[i]-mn);
            float p[4]; float rs = 0.f;
            #pragma unroll
            for (int j=0;j<4;j++){ p[j] = expf(S[i][j]-mn); rs += p[j]; }
            #pragma unroll
            for (int o=8;o>0;o>>=1) rs += __shfl_xor_sync(0xffffffffu, rs, o, 16);
            l[i] = l[i]*corr + rs;
            m[i] = mn;
            #pragma unroll
            for (int j=0;j<4;j++) O[i][j] *= corr;
            *(float4*)&Ps[(ty*4+i)*68 + tx*4] = make_float4(p[0],p[1],p[2],p[3]);
        }
        __syncthreads();

        #pragma unroll 8
        for (int k=0;k<64;k++){
            float4 v = *(const float4*)&Vs[k*68 + tx*4];
            #pragma unroll
            for (int i=0;i<4;i++){
                float pk = Ps[(ty*4+i)*68 + k];
                O[i][0] = fmaf(pk, v.x, O[i][0]);
                O[i][1] = fmaf(pk, v.y, O[i][1]);
                O[i][2] = fmaf(pk, v.z, O[i][2]);
                O[i][3] = fmaf(pk, v.w, O[i][3]);
            }
        }
    }

    #pragma unroll
    for (int i=0;i<4;i++){
        float inv = 1.f / l[i];
        *(float4*)&out[((size_t)(b*Tv + qt*64 + ty*4 + i))*Dv + h*HDv + tx*4] =
            make_float4(O[i][0]*inv, O[i][1]*inv, O[i][2]*inv, O[i][3]*inv);
    }
}

// ---------------- Selective scan ----------------
// 128 channels (b,sc) x 16 lanes (st). 8 blocks x 256 threads.
__global__ __launch_bounds__(256) void scan_kernel(
    const float* __restrict__ dt, const float* __restrict__ z,
    const float* __restrict__ Bi, const float* __restrict__ Ci,
    const float* __restrict__ gate, const float* __restrict__ A_log,
    float* __restrict__ y)
{
    int tid = threadIdx.x;
    int lc = tid>>4, st = tid&15;
    int chan = blockIdx.x*16 + lc;
    int b = chan>>6, sc = chan&63;
    float A = -expf(A_log[sc*STv + st]);
    float state = 0.f;
    size_t base64 = ((size_t)b*Tv)*SCv + sc;
    size_t base16 = ((size_t)b*Tv)*STv + st;

    float dtc = dt[base64], zc = z[base64], Bc = Bi[base16], Cc = Ci[base16];
    for (int t=0; t<Tv; t++){
        float dtn=0.f, zn=0.f, Bn=0.f, Cn=0.f;
        if (t+1 < Tv){
            dtn = dt[base64 + (size_t)(t+1)*SCv];
            zn  = z [base64 + (size_t)(t+1)*SCv];
            Bn  = Bi[base16 + (size_t)(t+1)*STv];
            Cn  = Ci[base16 + (size_t)(t+1)*STv];
        }
        float ab = 1.0f + dtc*A;
        state = fmaf(ab, state, (dtc*zc)*Bc);
        float p = state*Cc;
        #pragma unroll
        for (int o=8;o>0;o>>=1) p += __shfl_xor_sync(0xffffffffu, p, o, 16);
        if (st==0) y[base64 + (size_t)t*SCv] = p * gate[base64 + (size_t)t*SCv];
        dtc=dtn; zc=zn; Bc=Bn; Cc=Cn;
    }
}

// ---------------- launch ----------------
extern "C" void kernel_launch(void* const* d_in, const int* in_sizes, int n_in,
                              void* d_out, int out_size)
{
    const float* x      = (const float*)d_in[0];
    const float* qkv_w  = (const float*)d_in[1];
    const float* o_w    = (const float*)d_in[2];
    const float* n1w    = (const float*)d_in[3];
    const float* n2w    = (const float*)d_in[4];
    const float* in_w   = (const float*)d_in[5];
    const float* out_w  = (const float*)d_in[6];
    const float* A_log  = (const float*)d_in[7];
    const float* Bp_w   = (const float*)d_in[8];
    const float* Cp_w   = (const float*)d_in[9];
    const float* dt_w   = (const float*)d_in[10];
    const float* dt_b   = (const float*)d_in[11];
    const float* gate_w = (const float*)d_in[12];
    float* out = (float*)d_out;

    float *h,*qkv,*attn,*x1,*h2,*zb,*gateb,*Bib,*Cib,*dtb,*yb;
    cudaGetSymbolAddress((void**)&h,    g_h);
    cudaGetSymbolAddress((void**)&qkv,  g_qkv);
    cudaGetSymbolAddress((void**)&attn, g_attn);
    cudaGetSymbolAddress((void**)&x1,   g_x1);
    cudaGetSymbolAddress((void**)&h2,   g_h2);
    cudaGetSymbolAddress((void**)&zb,   g_z);
    cudaGetSymbolAddress((void**)&gateb,g_gate);
    cudaGetSymbolAddress((void**)&Bib,  g_Bi);
    cudaGetSymbolAddress((void**)&Cib,  g_Ci);
    cudaGetSymbolAddress((void**)&dtb,  g_dt);
    cudaGetSymbolAddress((void**)&yb,   g_y);

    const int attn_smem = 4*64*68*4;  // 69632 B
    cudaFuncSetAttribute(attn_kernel, cudaFuncAttributeMaxDynamicSharedMemorySize, attn_smem);

    // 1. rmsnorm1
    rmsnorm_kernel<<<Mrows, 256>>>(x, n1w, h);
    // 2. qkv = h @ qkv_w^T   [4096, 3072]
    gemm64_kernel<<<dim3(48,64), 256>>>(h, qkv_w, nullptr, nullptr, qkv, Mrows, 3*Dv, Dv, 0);
    // 3. attention
    attn_kernel<<<dim3(Tv/64, Hv, Bv), 256, attn_smem>>>(qkv, attn);
    // 4. x1 = x + attn @ o_w^T
    gemm64_kernel<<<dim3(16,64), 256>>>(attn, o_w, nullptr, x, x1, Mrows, Dv, Dv, 0);
    // 5. rmsnorm2
    rmsnorm_kernel<<<Mrows, 256>>>(x1, n2w, h2);
    // 6. z = h2 @ in_w^T   [4096, 64]
    gemm64_kernel<<<dim3(1,64), 256>>>(h2, in_w, nullptr, nullptr, zb, Mrows, SCv, Dv, 0);
    // 7. gate = silu(h2 @ gate_w^T)
    gemm64_kernel<<<dim3(1,64), 256>>>(h2, gate_w, nullptr, nullptr, gateb, Mrows, SCv, Dv, 1);
    // 8. Bi = z @ Bp_w^T  [4096,16]
    gemm64_kernel<<<dim3(1,64), 256>>>(zb, Bp_w, nullptr, nullptr, Bib, Mrows, STv, SCv, 0);
    // 9. Ci = z @ Cp_w^T
    gemm64_kernel<<<dim3(1,64), 256>>>(zb, Cp_w, nullptr, nullptr, Cib, Mrows, STv, SCv, 0);
    // 10. dt = softplus(z @ dt_w^T + dt_b)
    gemm64_kernel<<<dim3(1,64), 256>>>(zb, dt_w, dt_b, nullptr, dtb, Mrows, SCv, SCv, 2);
    // 11. scan -> y (already multiplied by gate)
    scan_kernel<<<8, 256>>>(dtb, zb, Bib, Cib, gateb, A_log, yb);
    // 12. out = x1 + y @ out_w^T
    gemm64_kernel<<<dim3(16,64), 256>>>(yb, out_w, nullptr, x1, out, Mrows, Dv, SCv, 0);
}

// round 2
// speedup vs baseline: 1.4253x; 1.4253x over previous
#include <cuda_runtime.h>
#include <cuda_bf16.h>
#include <mma.h>
#include <math.h>

using namespace nvcuda;

#define Bv 2
#define Tv 2048
#define Dv 1024
#define Hv 16
#define HDv 64
#define SCv 64
#define STv 16
#define Mrows (Bv*Tv)   // 4096
#define EPSR 1.1920929e-07f

// ---------------- scratch (device globals; no allocation allowed) ----------
__device__ float g_h   [Mrows*Dv];
__device__ float g_qkv [Mrows*3*Dv];
__device__ float g_attn[Mrows*Dv];
__device__ float g_x1  [Mrows*Dv];
__device__ float g_h2  [Mrows*Dv];
__device__ float g_z   [Mrows*SCv];
__device__ float g_gate[Mrows*SCv];
__device__ float g_Bi  [Mrows*STv];
__device__ float g_Ci  [Mrows*STv];
__device__ float g_dt  [Mrows*SCv];
__device__ float g_y   [Mrows*SCv];

// ---------------- RMSNorm ----------------
__global__ __launch_bounds__(256) void rmsnorm_kernel(
    const float* __restrict__ x, const float* __restrict__ w, float* __restrict__ o)
{
    int row = blockIdx.x;
    const float4* xr = (const float4*)(x + (size_t)row*Dv);
    float4 v = xr[threadIdx.x];
    float ss = v.x*v.x + v.y*v.y + v.z*v.z + v.w*v.w;
    #pragma unroll
    for (int off=16; off; off>>=1) ss += __shfl_xor_sync(0xffffffffu, ss, off);
    __shared__ float sm[8];
    int wid = threadIdx.x>>5, lane = threadIdx.x&31;
    if (lane==0) sm[wid] = ss;
    __syncthreads();
    float tot = sm[0]+sm[1]+sm[2]+sm[3]+sm[4]+sm[5]+sm[6]+sm[7];
    float scale = rsqrtf(tot*(1.0f/Dv) + EPSR);
    const float4* wr = (const float4*)w;
    float4 wv = wr[threadIdx.x];
    float4 ov = make_float4(v.x*scale*wv.x, v.y*scale*wv.y, v.z*scale*wv.z, v.w*scale*wv.w);
    ((float4*)(o + (size_t)row*Dv))[threadIdx.x] = ov;
}

// ---------------- TF32 tensor-core GEMM: C[M,N] = A[M,K] @ W[N,K]^T ----------
// Block tile 128x128, K-chunk 16. 8 warps: warp grid 4(M) x 2(N), warp tile 32x64.
// act: 0 none, 1 silu (elementwise on fragments). res: optional residual [M,N].
__global__ __launch_bounds__(256, 2) void gemm_tf32(
    const float* __restrict__ A, const float* __restrict__ W,
    const float* __restrict__ res, float* __restrict__ C,
    int M, int N, int K, int act)
{
    __shared__ float As[128*20];
    __shared__ float Ws[128*20];

    const int tid = threadIdx.x;
    const int w   = tid >> 5;
    const int wm  = w >> 1;        // 0..3
    const int wn  = w & 1;         // 0..1
    const int bm  = blockIdx.y * 128;
    const int bn  = blockIdx.x * 128;

    wmma::fragment<wmma::accumulator, 16, 16, 8, float> acc[2][4];
    #pragma unroll
    for (int i = 0; i < 2; i++)
        #pragma unroll
        for (int j = 0; j < 4; j++)
            wmma::fill_fragment(acc[i][j], 0.0f);

    const int lr  = tid >> 2;         // 0..63
    const int lc4 = (tid & 3) << 2;   // 0,4,8,12

    float4 a0, a1, b0, b1;

    // prologue load k0=0
    {
        a0 = *(const float4*)&A[(size_t)(bm + lr) * K + lc4];
        a1 = *(const float4*)&A[(size_t)(bm + lr + 64) * K + lc4];
        b0 = (bn + lr      < N) ? *(const float4*)&W[(size_t)(bn + lr)      * K + lc4] : make_float4(0,0,0,0);
        b1 = (bn + lr + 64 < N) ? *(const float4*)&W[(size_t)(bn + lr + 64) * K + lc4] : make_float4(0,0,0,0);
    }
    As[lr*20 + lc4 + 0] = wmma::__float_to_tf32(a0.x);
    As[lr*20 + lc4 + 1] = wmma::__float_to_tf32(a0.y);
    As[lr*20 + lc4 + 2] = wmma::__float_to_tf32(a0.z);
    As[lr*20 + lc4 + 3] = wmma::__float_to_tf32(a0.w);
    As[(lr+64)*20 + lc4 + 0] = wmma::__float_to_tf32(a1.x);
    As[(lr+64)*20 + lc4 + 1] = wmma::__float_to_tf32(a1.y);
    As[(lr+64)*20 + lc4 + 2] = wmma::__float_to_tf32(a1.z);
    As[(lr+64)*20 + lc4 + 3] = wmma::__float_to_tf32(a1.w);
    Ws[lr*20 + lc4 + 0] = wmma::__float_to_tf32(b0.x);
    Ws[lr*20 + lc4 + 1] = wmma::__float_to_tf32(b0.y);
    Ws[lr*20 + lc4 + 2] = wmma::__float_to_tf32(b0.z);
    Ws[lr*20 + lc4 + 3] = wmma::__float_to_tf32(b0.w);
    Ws[(lr+64)*20 + lc4 + 0] = wmma::__float_to_tf32(b1.x);
    Ws[(lr+64)*20 + lc4 + 1] = wmma::__float_to_tf32(b1.y);
    Ws[(lr+64)*20 + lc4 + 2] = wmma::__float_to_tf32(b1.z);
    Ws[(lr+64)*20 + lc4 + 3] = wmma::__float_to_tf32(b1.w);
    __syncthreads();

    for (int k0 = 0; k0 < K; k0 += 16) {
        const bool more = (k0 + 16) < K;
        if (more) {
            int kn = k0 + 16;
            a0 = *(const float4*)&A[(size_t)(bm + lr) * K + kn + lc4];
            a1 = *(const float4*)&A[(size_t)(bm + lr + 64) * K + kn + lc4];
            b0 = (bn + lr      < N) ? *(const float4*)&W[(size_t)(bn + lr)      * K + kn + lc4] : make_float4(0,0,0,0);
            b1 = (bn + lr + 64 < N) ? *(const float4*)&W[(size_t)(bn + lr + 64) * K + kn + lc4] : make_float4(0,0,0,0);
        }

        #pragma unroll
        for (int ks = 0; ks < 16; ks += 8) {
            wmma::fragment<wmma::matrix_a, 16, 16, 8, wmma::precision::tf32, wmma::row_major> fa[2];
            wmma::fragment<wmma::matrix_b, 16, 16, 8, wmma::precision::tf32, wmma::col_major> fb[4];
            #pragma unroll
            for (int i = 0; i < 2; i++)
                wmma::load_matrix_sync(fa[i], &As[(wm*32 + i*16)*20 + ks], 20);
            #pragma unroll
            for (int j = 0; j < 4; j++)
                wmma::load_matrix_sync(fb[j], &Ws[(wn*64 + j*16)*20 + ks], 20);
            #pragma unroll
            for (int i = 0; i < 2; i++)
                #pragma unroll
                for (int j = 0; j < 4; j++)
                    wmma::mma_sync(acc[i][j], fa[i], fb[j], acc[i][j]);
        }

        if (more) {
            __syncthreads();
            As[lr*20 + lc4 + 0] = wmma::__float_to_tf32(a0.x);
            As[lr*20 + lc4 + 1] = wmma::__float_to_tf32(a0.y);
            As[lr*20 + lc4 + 2] = wmma::__float_to_tf32(a0.z);
            As[lr*20 + lc4 + 3] = wmma::__float_to_tf32(a0.w);
            As[(lr+64)*20 + lc4 + 0] = wmma::__float_to_tf32(a1.x);
            As[(lr+64)*20 + lc4 + 1] = wmma::__float_to_tf32(a1.y);
            As[(lr+64)*20 + lc4 + 2] = wmma::__float_to_tf32(a1.z);
            As[(lr+64)*20 + lc4 + 3] = wmma::__float_to_tf32(a1.w);
            Ws[lr*20 + lc4 + 0] = wmma::__float_to_tf32(b0.x);
            Ws[lr*20 + lc4 + 1] = wmma::__float_to_tf32(b0.y);
            Ws[lr*20 + lc4 + 2] = wmma::__float_to_tf32(b0.z);
            Ws[lr*20 + lc4 + 3] = wmma::__float_to_tf32(b0.w);
            Ws[(lr+64)*20 + lc4 + 0] = wmma::__float_to_tf32(b1.x);
            Ws[(lr+64)*20 + lc4 + 1] = wmma::__float_to_tf32(b1.y);
            Ws[(lr+64)*20 + lc4 + 2] = wmma::__float_to_tf32(b1.z);
            Ws[(lr+64)*20 + lc4 + 3] = wmma::__float_to_tf32(b1.w);
            __syncthreads();
        }
    }

    // epilogue: optional residual add + silu, then store
    #pragma unroll
    for (int i = 0; i < 2; i++) {
        #pragma unroll
        for (int j = 0; j < 4; j++) {
            int row = bm + wm*32 + i*16;
            int col = bn + wn*64 + j*16;
            if (col < N) {
                if (res) {
                    wmma::fragment<wmma::accumulator, 16, 16, 8, float> r;
                    wmma::load_matrix_sync(r, &res[(size_t)row * N + col], N, wmma::mem_row_major);
                    #pragma unroll
                    for (int e = 0; e < r.num_elements; e++) acc[i][j].x[e] += r.x[e];
                }
                if (act == 1) {
                    #pragma unroll
                    for (int e = 0; e < acc[i][j].num_elements; e++) {
                        float v = acc[i][j].x[e];
                        acc[i][j].x[e] = v / (1.0f + expf(-v));
                    }
                }
                wmma::store_matrix_sync(&C[(size_t)row * N + col], acc[i][j], N, wmma::mem_row_major);
            }
        }
    }
}

// ---------------- fp32 SGEMM (small matmuls: Bi, Ci, dt) ----------------
__global__ __launch_bounds__(256) void gemm64_kernel(
    const float* __restrict__ A, const float* __restrict__ W,
    const float* __restrict__ bias, const float* __restrict__ res,
    float* __restrict__ C, int M, int N, int K, int act)
{
    __shared__ float As[16][68];
    __shared__ float Ws[16][68];
    const int tid = threadIdx.x;
    const int bm = blockIdx.y*64, bn = blockIdx.x*64;
    const int lr = tid>>2;
    const int lc = (tid&3)<<2;
    const int ty = tid>>4, tx = tid&15;
    float acc[4][4];
    #pragma unroll
    for (int i=0;i<4;i++)
        #pragma unroll
        for (int j=0;j<4;j++) acc[i][j]=0.f;

    for (int k0=0; k0<K; k0+=16) {
        float4 a = *(const float4*)&A[(size_t)(bm+lr)*K + k0 + lc];
        As[lc+0][lr]=a.x; As[lc+1][lr]=a.y; As[lc+2][lr]=a.z; As[lc+3][lr]=a.w;
        float4 w = make_float4(0.f,0.f,0.f,0.f);
        if (bn+lr < N) w = *(const float4*)&W[(size_t)(bn+lr)*K + k0 + lc];
        Ws[lc+0][lr]=w.x; Ws[lc+1][lr]=w.y; Ws[lc+2][lr]=w.z; Ws[lc+3][lr]=w.w;
        __syncthreads();
        #pragma unroll
        for (int k=0;k<16;k++){
            float4 av = *(const float4*)&As[k][ty*4];
            float4 wv = *(const float4*)&Ws[k][tx*4];
            float aa[4] = {av.x,av.y,av.z,av.w};
            float ww[4] = {wv.x,wv.y,wv.z,wv.w};
            #pragma unroll
            for (int i=0;i<4;i++)
                #pragma unroll
                for (int j=0;j<4;j++) acc[i][j] = fmaf(aa[i], ww[j], acc[i][j]);
        }
        __syncthreads();
    }

    const int col = bn + tx*4;
    if (col < N) {
        float4 bv = make_float4(0,0,0,0);
        if (bias) bv = *(const float4*)&bias[col];
        #pragma unroll
        for (int i=0;i<4;i++){
            int row = bm + ty*4 + i;
            float c[4];
            #pragma unroll
            for (int j=0;j<4;j++) c[j] = acc[i][j];
            if (bias) { c[0]+=bv.x; c[1]+=bv.y; c[2]+=bv.z; c[3]+=bv.w; }
            if (act==1) {
                #pragma unroll
                for (int j=0;j<4;j++) c[j] = c[j] / (1.f + expf(-c[j]));
            } else if (act==2) {
                #pragma unroll
                for (int j=0;j<4;j++) c[j] = (c[j] > 20.f) ? c[j] : log1pf(expf(c[j]));
            }
            if (res) {
                float4 rv = *(const float4*)&res[(size_t)row*N + col];
                c[0]+=rv.x; c[1]+=rv.y; c[2]+=rv.z; c[3]+=rv.w;
            }
            *(float4*)&C[(size_t)row*N + col] = make_float4(c[0],c[1],c[2],c[3]);
        }
    }
}

// ---------------- Flash attention, TF32 tensor cores ----------------
// grid (T/64, H, B), 256 threads (8 warps). O accumulated in smem (rescale per row).
__global__ __launch_bounds__(256) void attn_tf32_kernel(
    const float* __restrict__ qkv, float* __restrict__ out)
{
    extern __shared__ float sm[];
    float* Qs = sm;                 // [64][68] tf32
    float* Ks = Qs + 64*68;         // [64][68] tf32
    float* Vs = Ks + 64*68;         // [64][68] tf32
    float* Ss = Vs + 64*68;         // [64][68] fp32 (scores / PV out)
    float* Ps = Ss + 64*68;         // [64][68] tf32 probs
    float* Os = Ps + 64*68;         // [64][68] fp32 output accum
    float* corr_s = Os + 64*68;     // [64]

    const int tid = threadIdx.x;
    const int qt = blockIdx.x, h = blockIdx.y, b = blockIdx.z;
    const int w  = tid >> 5;
    const int ty = tid >> 4, tx = tid & 15;
    const int fi = w >> 1;          // 0..3 (16-row band)
    const int fj0 = (w & 1) * 2;    // 0 or 2

    // load Q (tf32), zero O
    #pragma unroll
    for (int i = 0; i < 4; i++) {
        int t4 = tid + i*256;
        int r = t4 >> 4, c4 = (t4 & 15) << 2;
        float4 v = *(const float4*)&qkv[((size_t)(b*Tv + qt*64 + r))*(3*Dv) + h*HDv + c4];
        Qs[r*68 + c4 + 0] = wmma::__float_to_tf32(v.x);
        Qs[r*68 + c4 + 1] = wmma::__float_to_tf32(v.y);
        Qs[r*68 + c4 + 2] = wmma::__float_to_tf32(v.z);
        Qs[r*68 + c4 + 3] = wmma::__float_to_tf32(v.w);
        *(float4*)&Os[r*68 + c4] = make_float4(0.f,0.f,0.f,0.f);
    }

    float m[4], l[4];
    #pragma unroll
    for (int i = 0; i < 4; i++) { m[i] = -1e30f; l[i] = 0.f; }

    for (int kt = 0; kt <= qt; ++kt) {
        __syncthreads();
        // load K, V (tf32)
        #pragma unroll
        for (int i = 0; i < 4; i++) {
            int t4 = tid + i*256;
            int r = t4 >> 4, c4 = (t4 & 15) << 2;
            size_t base = ((size_t)(b*Tv + kt*64 + r))*(3*Dv) + h*HDv + c4;
            float4 kv = *(const float4*)&qkv[base + Dv];
            float4 vv = *(const float4*)&qkv[base + 2*Dv];
            Ks[r*68 + c4 + 0] = wmma::__float_to_tf32(kv.x);
            Ks[r*68 + c4 + 1] = wmma::__float_to_tf32(kv.y);
            Ks[r*68 + c4 + 2] = wmma::__float_to_tf32(kv.z);
            Ks[r*68 + c4 + 3] = wmma::__float_to_tf32(kv.w);
            Vs[r*68 + c4 + 0] = wmma::__float_to_tf32(vv.x);
            Vs[r*68 + c4 + 1] = wmma::__float_to_tf32(vv.y);
            Vs[r*68 + c4 + 2] = wmma::__float_to_tf32(vv.z);
            Vs[r*68 + c4 + 3] = wmma::__float_to_tf32(vv.w);
        }
        __syncthreads();

        // S = Q @ K^T  (each warp: 2 fragments of 16x16)
        #pragma unroll
        for (int s = 0; s < 2; s++) {
            int fj = fj0 + s;
            wmma::fragment<wmma::accumulator, 16, 16, 8, float> c;
            wmma::fill_fragment(c, 0.f);
            #pragma unroll
            for (int kk = 0; kk < 64; kk += 8) {
                wmma::fragment<wmma::matrix_a, 16, 16, 8, wmma::precision::tf32, wmma::row_major> fa;
                wmma::fragment<wmma::matrix_b, 16, 16, 8, wmma::precision::tf32, wmma::col_major> fb;
                wmma::load_matrix_sync(fa, &Qs[fi*16*68 + kk], 68);
                wmma::load_matrix_sync(fb, &Ks[fj*16*68 + kk], 68);
                wmma::mma_sync(c, fa, fb, c);
            }
            wmma::store_matrix_sync(&Ss[fi*16*68 + fj*16], c, 68, wmma::mem_row_major);
        }
        __syncthreads();

        // online softmax (scalar)
        #pragma unroll
        for (int i = 0; i < 4; i++) {
            int row = ty*4 + i;
            int qg = qt*64 + row;
            float4 sv = *(const float4*)&Ss[row*68 + tx*4];
            float S4[4] = {sv.x, sv.y, sv.z, sv.w};
            #pragma unroll
            for (int j = 0; j < 4; j++) {
                int kg = kt*64 + tx*4 + j;
                S4[j] = (kg <= qg) ? S4[j]*0.125f : -1e30f;
            }
            float rm = fmaxf(fmaxf(S4[0],S4[1]), fmaxf(S4[2],S4[3]));
            #pragma unroll
            for (int o = 8; o > 0; o >>= 1) rm = fmaxf(rm, __shfl_xor_sync(0xffffffffu, rm, o, 16));
            float mn = fmaxf(m[i], rm);
            float corr = expf(m[i] - mn);
            float p[4]; float rs = 0.f;
            #pragma unroll
            for (int j = 0; j < 4; j++) { p[j] = expf(S4[j] - mn); rs += p[j]; }
            #pragma unroll
            for (int o = 8; o > 0; o >>= 1) rs += __shfl_xor_sync(0xffffffffu, rs, o, 16);
            l[i] = l[i]*corr + rs;
            m[i] = mn;
            float4 pv = make_float4(wmma::__float_to_tf32(p[0]), wmma::__float_to_tf32(p[1]),
                                    wmma::__float_to_tf32(p[2]), wmma::__float_to_tf32(p[3]));
            *(float4*)&Ps[row*68 + tx*4] = pv;
            if (tx == 0) corr_s[row] = corr;
        }
        __syncthreads();

        // PV = P @ V  -> Ss (overwrite)
        #pragma unroll
        for (int s = 0; s < 2; s++) {
            int fj = fj0 + s;
            wmma::fragment<wmma::accumulator, 16, 16, 8, float> c;
            wmma::fill_fragment(c, 0.f);
            #pragma unroll
            for (int kk = 0; kk < 64; kk += 8) {
                wmma::fragment<wmma::matrix_a, 16, 16, 8, wmma::precision::tf32, wmma::row_major> fa;
                wmma::fragment<wmma::matrix_b, 16, 16, 8, wmma::precision::tf32, wmma::row_major> fb;
                wmma::load_matrix_sync(fa, &Ps[fi*16*68 + kk], 68);
                wmma::load_matrix_sync(fb, &Vs[kk*68 + fj*16], 68);
                wmma::mma_sync(c, fa, fb, c);
            }
            wmma::store_matrix_sync(&Ss[fi*16*68 + fj*16], c, 68, wmma::mem_row_major);
        }
        __syncthreads();

        // O = O*corr + PV
        #pragma unroll
        for (int i = 0; i < 4; i++) {
            int t4 = tid + i*256;
            int r = t4 >> 4, c4 = (t4 & 15) << 2;
            float cr = corr_s[r];
            float4 o = *(const float4*)&Os[r*68 + c4];
            float4 p = *(const float4*)&Ss[r*68 + c4];
            o.x = fmaf(o.x, cr, p.x);
            o.y = fmaf(o.y, cr, p.y);
            o.z = fmaf(o.z, cr, p.z);
            o.w = fmaf(o.w, cr, p.w);
            *(float4*)&Os[r*68 + c4] = o;
        }
    }
    __syncthreads();

    // final write: O / l
    #pragma unroll
    for (int i = 0; i < 4; i++) {
        int row = ty*4 + i;
        float inv = 1.f / l[i];
        float4 o = *(const float4*)&Os[row*68 + tx*4];
        *(float4*)&out[((size_t)(b*Tv + qt*64 + row))*Dv + h*HDv + tx*4] =
            make_float4(o.x*inv, o.y*inv, o.z*inv, o.w*inv);
    }
}

// ---------------- Selective scan ----------------
__global__ __launch_bounds__(256) void scan_kernel(
    const float* __restrict__ dt, const float* __restrict__ z,
    const float* __restrict__ Bi, const float* __restrict__ Ci,
    const float* __restrict__ gate, const float* __restrict__ A_log,
    float* __restrict__ y)
{
    int tid = threadIdx.x;
    int lc = tid>>4, st = tid&15;
    int chan = blockIdx.x*16 + lc;
    int b = chan>>6, sc = chan&63;
    float A = -expf(A_log[sc*STv + st]);
    float state = 0.f;
    size_t base64 = ((size_t)b*Tv)*SCv + sc;
    size_t base16 = ((size_t)b*Tv)*STv + st;

    float dtc = dt[base64], zc = z[base64], Bc = Bi[base16], Cc = Ci[base16];
    for (int t=0; t<Tv; t++){
        float dtn=0.f, zn=0.f, Bn=0.f, Cn=0.f;
        if (t+1 < Tv){
            dtn = dt[base64 + (size_t)(t+1)*SCv];
            zn  = z [base64 + (size_t)(t+1)*SCv];
            Bn  = Bi[base16 + (size_t)(t+1)*STv];
            Cn  = Ci[base16 + (size_t)(t+1)*STv];
        }
        float ab = 1.0f + dtc*A;
        state = fmaf(ab, state, (dtc*zc)*Bc);
        float p = state*Cc;
        #pragma unroll
        for (int o=8;o>0;o>>=1) p += __shfl_xor_sync(0xffffffffu, p, o, 16);
        if (st==0) y[base64 + (size_t)t*SCv] = p * gate[base64 + (size_t)t*SCv];
        dtc=dtn; zc=zn; Bc=Bn; Cc=Cn;
    }
}

// ---------------- launch ----------------
extern "C" void kernel_launch(void* const* d_in, const int* in_sizes, int n_in,
                              void* d_out, int out_size)
{
    const float* x      = (const float*)d_in[0];
    const float* qkv_w  = (const float*)d_in[1];
    const float* o_w    = (const float*)d_in[2];
    const float* n1w    = (const float*)d_in[3];
    const float* n2w    = (const float*)d_in[4];
    const float* in_w   = (const float*)d_in[5];
    const float* out_w  = (const float*)d_in[6];
    const float* A_log  = (const float*)d_in[7];
    const float* Bp_w   = (const float*)d_in[8];
    const float* Cp_w   = (const float*)d_in[9];
    const float* dt_w   = (const float*)d_in[10];
    const float* dt_b   = (const float*)d_in[11];
    const float* gate_w = (const float*)d_in[12];
    float* out = (float*)d_out;

    float *h,*qkv,*attn,*x1,*h2,*zb,*gateb,*Bib,*Cib,*dtb,*yb;
    cudaGetSymbolAddress((void**)&h,    g_h);
    cudaGetSymbolAddress((void**)&qkv,  g_qkv);
    cudaGetSymbolAddress((void**)&attn, g_attn);
    cudaGetSymbolAddress((void**)&x1,   g_x1);
    cudaGetSymbolAddress((void**)&h2,   g_h2);
    cudaGetSymbolAddress((void**)&zb,   g_z);
    cudaGetSymbolAddress((void**)&gateb,g_gate);
    cudaGetSymbolAddress((void**)&Bib,  g_Bi);
    cudaGetSymbolAddress((void**)&Cib,  g_Ci);
    cudaGetSymbolAddress((void**)&dtb,  g_dt);
    cudaGetSymbolAddress((void**)&yb,   g_y);

    const int attn_smem = (6*64*68 + 64) * 4;   // ~104.7 KB
    cudaFuncSetAttribute(attn_tf32_kernel, cudaFuncAttributeMaxDynamicSharedMemorySize, attn_smem);

    // 1. rmsnorm1
    rmsnorm_kernel<<<Mrows, 256>>>(x, n1w, h);
    // 2. qkv = h @ qkv_w^T   [4096, 3072]
    gemm_tf32<<<dim3(24, 32), 256>>>(h, qkv_w, nullptr, qkv, Mrows, 3*Dv, Dv, 0);
    // 3. attention
    attn_tf32_kernel<<<dim3(Tv/64, Hv, Bv), 256, attn_smem>>>(qkv, attn);
    // 4. x1 = x + attn @ o_w^T
    gemm_tf32<<<dim3(8, 32), 256>>>(attn, o_w, x, x1, Mrows, Dv, Dv, 0);
    // 5. rmsnorm2
    rmsnorm_kernel<<<Mrows, 256>>>(x1, n2w, h2);
    // 6. z = h2 @ in_w^T   [4096, 64]
    gemm_tf32<<<dim3(1, 32), 256>>>(h2, in_w, nullptr, zb, Mrows, SCv, Dv, 0);
    // 7. gate = silu(h2 @ gate_w^T)
    gemm_tf32<<<dim3(1, 32), 256>>>(h2, gate_w, nullptr, gateb, Mrows, SCv, Dv, 1);
    // 8. Bi = z @ Bp_w^T  [4096,16]
    gemm64_kernel<<<dim3(1,64), 256>>>(zb, Bp_w, nullptr, nullptr, Bib, Mrows, STv, SCv, 0);
    // 9. Ci = z @ Cp_w^T
    gemm64_kernel<<<dim3(1,64), 256>>>(zb, Cp_w, nullptr, nullptr, Cib, Mrows, STv, SCv, 0);
    // 10. dt = softplus(z @ dt_w^T + dt_b)
    gemm64_kernel<<<dim3(1,64), 256>>>(zb, dt_w, dt_b, nullptr, dtb, Mrows, SCv, SCv, 2);
    // 11. scan -> y (already multiplied by gate)
    scan_kernel<<<8, 256>>>(dtb, zb, Bib, Cib, gateb, A_log, yb);
    // 12. out = x1 + y @ out_w^T
    gemm_tf32<<<dim3(8, 32), 256>>>(yb, out_w, x1, out, Mrows, Dv, SCv, 0);
}

// round 4
// speedup vs baseline: 1.7303x; 1.2140x over previous
#include <cuda_runtime.h>
#include <cuda_bf16.h>
#include <mma.h>
#include <math.h>
#include <cstdint>

using namespace nvcuda;

#define Bv 2
#define Tv 2048
#define Dv 1024
#define Hv 16
#define HDv 64
#define SCv 64
#define STv 16
#define Mrows (Bv*Tv)   // 4096
#define EPSR 1.1920929e-07f

// ---------------- scratch (device globals; no allocation allowed) ----------
__device__ float g_h   [Mrows*Dv];
__device__ float g_qkv [Mrows*3*Dv];
__device__ float g_attn[Mrows*Dv];
__device__ float g_x1  [Mrows*Dv];
__device__ float g_h2  [Mrows*Dv];
__device__ float g_z   [Mrows*SCv];
__device__ float g_gate[Mrows*SCv];
__device__ float g_Bi  [Mrows*STv];
__device__ float g_Ci  [Mrows*STv];
__device__ float g_dt  [Mrows*SCv];
__device__ float g_y   [Mrows*SCv];

__device__ __forceinline__ uint32_t f2tf32(float x) {
    uint32_t r;
    asm("cvt.rna.tf32.f32 %0, %1;" : "=r"(r) : "f"(x));
    return r;
}

__device__ __forceinline__ void mma_tf32(float& d0, float& d1, float& d2, float& d3,
                                         uint32_t a0, uint32_t a1, uint32_t a2, uint32_t a3,
                                         uint32_t b0, uint32_t b1) {
    asm volatile(
        "mma.sync.aligned.m16n8k8.row.col.f32.tf32.tf32.f32 "
        "{%0,%1,%2,%3}, {%4,%5,%6,%7}, {%8,%9}, {%0,%1,%2,%3};"
        : "+f"(d0), "+f"(d1), "+f"(d2), "+f"(d3)
        : "r"(a0), "r"(a1), "r"(a2), "r"(a3), "r"(b0), "r"(b1));
}

// ---------------- RMSNorm ----------------
__global__ __launch_bounds__(256) void rmsnorm_kernel(
    const float* __restrict__ x, const float* __restrict__ w, float* __restrict__ o)
{
    int row = blockIdx.x;
    const float4* xr = (const float4*)(x + (size_t)row*Dv);
    float4 v = xr[threadIdx.x];
    float ss = v.x*v.x + v.y*v.y + v.z*v.z + v.w*v.w;
    #pragma unroll
    for (int off=16; off; off>>=1) ss += __shfl_xor_sync(0xffffffffu, ss, off);
    __shared__ float sm[8];
    int wid = threadIdx.x>>5, lane = threadIdx.x&31;
    if (lane==0) sm[wid] = ss;
    __syncthreads();
    float tot = sm[0]+sm[1]+sm[2]+sm[3]+sm[4]+sm[5]+sm[6]+sm[7];
    float scale = rsqrtf(tot*(1.0f/Dv) + EPSR);
    const float4* wr = (const float4*)w;
    float4 wv = wr[threadIdx.x];
    float4 ov = make_float4(v.x*scale*wv.x, v.y*scale*wv.y, v.z*scale*wv.z, v.w*scale*wv.w);
    ((float4*)(o + (size_t)row*Dv))[threadIdx.x] = ov;
}

// ---------------- TF32 tensor-core GEMM: C[M,N] = A[M,K] @ W[N,K]^T ----------
__global__ __launch_bounds__(256, 2) void gemm_tf32(
    const float* __restrict__ A, const float* __restrict__ W,
    const float* __restrict__ res, float* __restrict__ C,
    int M, int N, int K, int act)
{
    __shared__ float As[128*20];
    __shared__ float Ws[128*20];

    const int tid = threadIdx.x;
    const int w   = tid >> 5;
    const int wm  = w >> 1;
    const int wn  = w & 1;
    const int bm  = blockIdx.y * 128;
    const int bn  = blockIdx.x * 128;

    wmma::fragment<wmma::accumulator, 16, 16, 8, float> acc[2][4];
    #pragma unroll
    for (int i = 0; i < 2; i++)
        #pragma unroll
        for (int j = 0; j < 4; j++)
            wmma::fill_fragment(acc[i][j], 0.0f);

    const int lr  = tid >> 2;
    const int lc4 = (tid & 3) << 2;

    float4 a0, a1, b0, b1;
    {
        a0 = *(const float4*)&A[(size_t)(bm + lr) * K + lc4];
        a1 = *(const float4*)&A[(size_t)(bm + lr + 64) * K + lc4];
        b0 = (bn + lr      < N) ? *(const float4*)&W[(size_t)(bn + lr)      * K + lc4] : make_float4(0,0,0,0);
        b1 = (bn + lr + 64 < N) ? *(const float4*)&W[(size_t)(bn + lr + 64) * K + lc4] : make_float4(0,0,0,0);
    }
    As[lr*20 + lc4 + 0] = wmma::__float_to_tf32(a0.x);
    As[lr*20 + lc4 + 1] = wmma::__float_to_tf32(a0.y);
    As[lr*20 + lc4 + 2] = wmma::__float_to_tf32(a0.z);
    As[lr*20 + lc4 + 3] = wmma::__float_to_tf32(a0.w);
    As[(lr+64)*20 + lc4 + 0] = wmma::__float_to_tf32(a1.x);
    As[(lr+64)*20 + lc4 + 1] = wmma::__float_to_tf32(a1.y);
    As[(lr+64)*20 + lc4 + 2] = wmma::__float_to_tf32(a1.z);
    As[(lr+64)*20 + lc4 + 3] = wmma::__float_to_tf32(a1.w);
    Ws[lr*20 + lc4 + 0] = wmma::__float_to_tf32(b0.x);
    Ws[lr*20 + lc4 + 1] = wmma::__float_to_tf32(b0.y);
    Ws[lr*20 + lc4 + 2] = wmma::__float_to_tf32(b0.z);
    Ws[lr*20 + lc4 + 3] = wmma::__float_to_tf32(b0.w);
    Ws[(lr+64)*20 + lc4 + 0] = wmma::__float_to_tf32(b1.x);
    Ws[(lr+64)*20 + lc4 + 1] = wmma::__float_to_tf32(b1.y);
    Ws[(lr+64)*20 + lc4 + 2] = wmma::__float_to_tf32(b1.z);
    Ws[(lr+64)*20 + lc4 + 3] = wmma::__float_to_tf32(b1.w);
    __syncthreads();

    for (int k0 = 0; k0 < K; k0 += 16) {
        const bool more = (k0 + 16) < K;
        if (more) {
            int kn = k0 + 16;
            a0 = *(const float4*)&A[(size_t)(bm + lr) * K + kn + lc4];
            a1 = *(const float4*)&A[(size_t)(bm + lr + 64) * K + kn + lc4];
            b0 = (bn + lr      < N) ? *(const float4*)&W[(size_t)(bn + lr)      * K + kn + lc4] : make_float4(0,0,0,0);
            b1 = (bn + lr + 64 < N) ? *(const float4*)&W[(size_t)(bn + lr + 64) * K + kn + lc4] : make_float4(0,0,0,0);
        }

        #pragma unroll
        for (int ks = 0; ks < 16; ks += 8) {
            wmma::fragment<wmma::matrix_a, 16, 16, 8, wmma::precision::tf32, wmma::row_major> fa[2];
            wmma::fragment<wmma::matrix_b, 16, 16, 8, wmma::precision::tf32, wmma::col_major> fb[4];
            #pragma unroll
            for (int i = 0; i < 2; i++)
                wmma::load_matrix_sync(fa[i], &As[(wm*32 + i*16)*20 + ks], 20);
            #pragma unroll
            for (int j = 0; j < 4; j++)
                wmma::load_matrix_sync(fb[j], &Ws[(wn*64 + j*16)*20 + ks], 20);
            #pragma unroll
            for (int i = 0; i < 2; i++)
                #pragma unroll
                for (int j = 0; j < 4; j++)
                    wmma::mma_sync(acc[i][j], fa[i], fb[j], acc[i][j]);
        }

        if (more) {
            __syncthreads();
            As[lr*20 + lc4 + 0] = wmma::__float_to_tf32(a0.x);
            As[lr*20 + lc4 + 1] = wmma::__float_to_tf32(a0.y);
            As[lr*20 + lc4 + 2] = wmma::__float_to_tf32(a0.z);
            As[lr*20 + lc4 + 3] = wmma::__float_to_tf32(a0.w);
            As[(lr+64)*20 + lc4 + 0] = wmma::__float_to_tf32(a1.x);
            As[(lr+64)*20 + lc4 + 1] = wmma::__float_to_tf32(a1.y);
            As[(lr+64)*20 + lc4 + 2] = wmma::__float_to_tf32(a1.z);
            As[(lr+64)*20 + lc4 + 3] = wmma::__float_to_tf32(a1.w);
            Ws[lr*20 + lc4 + 0] = wmma::__float_to_tf32(b0.x);
            Ws[lr*20 + lc4 + 1] = wmma::__float_to_tf32(b0.y);
            Ws[lr*20 + lc4 + 2] = wmma::__float_to_tf32(b0.z);
            Ws[lr*20 + lc4 + 3] = wmma::__float_to_tf32(b0.w);
            Ws[(lr+64)*20 + lc4 + 0] = wmma::__float_to_tf32(b1.x);
            Ws[(lr+64)*20 + lc4 + 1] = wmma::__float_to_tf32(b1.y);
            Ws[(lr+64)*20 + lc4 + 2] = wmma::__float_to_tf32(b1.z);
            Ws[(lr+64)*20 + lc4 + 3] = wmma::__float_to_tf32(b1.w);
            __syncthreads();
        }
    }

    #pragma unroll
    for (int i = 0; i < 2; i++) {
        #pragma unroll
        for (int j = 0; j < 4; j++) {
            int row = bm + wm*32 + i*16;
            int col = bn + wn*64 + j*16;
            if (col < N) {
                if (res) {
                    wmma::fragment<wmma::accumulator, 16, 16, 8, float> r;
                    wmma::load_matrix_sync(r, &res[(size_t)row * N + col], N, wmma::mem_row_major);
                    #pragma unroll
                    for (int e = 0; e < r.num_elements; e++) acc[i][j].x[e] += r.x[e];
                }
                if (act == 1) {
                    #pragma unroll
                    for (int e = 0; e < acc[i][j].num_elements; e++) {
                        float v = acc[i][j].x[e];
                        acc[i][j].x[e] = v / (1.0f + __expf(-v));
                    }
                }
                wmma::store_matrix_sync(&C[(size_t)row * N + col], acc[i][j], N, wmma::mem_row_major);
            }
        }
    }
}

// ---------------- fp32 SGEMM (small matmuls: Bi, Ci, dt) ----------------
__global__ __launch_bounds__(256) void gemm64_kernel(
    const float* __restrict__ A, const float* __restrict__ W,
    const float* __restrict__ bias, const float* __restrict__ res,
    float* __restrict__ C, int M, int N, int K, int act)
{
    __shared__ float As[16][68];
    __shared__ float Ws[16][68];
    const int tid = threadIdx.x;
    const int bm = blockIdx.y*64, bn = blockIdx.x*64;
    const int lr = tid>>2;
    const int lc = (tid&3)<<2;
    const int ty = tid>>4, tx = tid&15;
    float acc[4][4];
    #pragma unroll
    for (int i=0;i<4;i++)
        #pragma unroll
        for (int j=0;j<4;j++) acc[i][j]=0.f;

    for (int k0=0; k0<K; k0+=16) {
        float4 a = *(const float4*)&A[(size_t)(bm+lr)*K + k0 + lc];
        As[lc+0][lr]=a.x; As[lc+1][lr]=a.y; As[lc+2][lr]=a.z; As[lc+3][lr]=a.w;
        float4 w = make_float4(0.f,0.f,0.f,0.f);
        if (bn+lr < N) w = *(const float4*)&W[(size_t)(bn+lr)*K + k0 + lc];
        Ws[lc+0][lr]=w.x; Ws[lc+1][lr]=w.y; Ws[lc+2][lr]=w.z; Ws[lc+3][lr]=w.w;
        __syncthreads();
        #pragma unroll
        for (int k=0;k<16;k++){
            float4 av = *(const float4*)&As[k][ty*4];
            float4 wv = *(const float4*)&Ws[k][tx*4];
            float aa[4] = {av.x,av.y,av.z,av.w};
            float ww[4] = {wv.x,wv.y,wv.z,wv.w};
            #pragma unroll
            for (int i=0;i<4;i++)
                #pragma unroll
                for (int j=0;j<4;j++) acc[i][j] = fmaf(aa[i], ww[j], acc[i][j]);
        }
        __syncthreads();
    }

    const int col = bn + tx*4;
    if (col < N) {
        float4 bv = make_float4(0,0,0,0);
        if (bias) bv = *(const float4*)&bias[col];
        #pragma unroll
        for (int i=0;i<4;i++){
            int row = bm + ty*4 + i;
            float c[4];
            #pragma unroll
            for (int j=0;j<4;j++) c[j] = acc[i][j];
            if (bias) { c[0]+=bv.x; c[1]+=bv.y; c[2]+=bv.z; c[3]+=bv.w; }
            if (act==1) {
                #pragma unroll
                for (int j=0;j<4;j++) c[j] = c[j] / (1.f + __expf(-c[j]));
            } else if (act==2) {
                #pragma unroll
                for (int j=0;j<4;j++) c[j] = (c[j] > 20.f) ? c[j] : log1pf(__expf(c[j]));
            }
            if (res) {
                float4 rv = *(const float4*)&res[(size_t)row*N + col];
                c[0]+=rv.x; c[1]+=rv.y; c[2]+=rv.z; c[3]+=rv.w;
            }
            *(float4*)&C[(size_t)row*N + col] = make_float4(c[0],c[1],c[2],c[3]);
        }
    }
}

// ---------------- Flash attention v2: raw mma.m16n8k8 tf32, register softmax ----
// grid (T/128, H, B), 256 threads (8 warps). Warp w owns q-rows [128*qb+16w, +16).
#define KS_LD 68
#define VS_LD 72
#define PS_LD 68
__global__ __launch_bounds__(256, 1) void attn_mma_kernel(
    const float* __restrict__ qkv, float* __restrict__ out)
{
    extern __shared__ uint32_t smu[];
    uint32_t* Ks = smu;                       // 64*68
    uint32_t* Vs = Ks + 64*KS_LD;             // 64*72
    uint32_t* Ps = Vs + 64*VS_LD;             // 8*16*68

    const int tid = threadIdx.x;
    const int w   = tid >> 5;
    const int l   = tid & 31;
    const int r4  = l >> 2;     // 0..7
    const int q   = l & 3;      // 0..3
    const int qb  = blockIdx.x, h = blockIdx.y, b = blockIdx.z;
    const int qrow0 = qb*128 + w*16;
    uint32_t* Pw = Ps + w*16*PS_LD;

    // ---- load Q into A fragments (pre-scaled by 1/sqrt(hd)=0.125) ----
    uint32_t qa[8][4];
    {
        const float* Qbase = qkv + ((size_t)(b*Tv + qrow0))*(3*Dv) + h*HDv;
        #pragma unroll
        for (int kc = 0; kc < 8; kc++) {
            qa[kc][0] = f2tf32(0.125f * Qbase[(size_t)(r4    )*(3*Dv) + kc*8 + q    ]);
            qa[kc][1] = f2tf32(0.125f * Qbase[(size_t)(r4 + 8)*(3*Dv) + kc*8 + q    ]);
            qa[kc][2] = f2tf32(0.125f * Qbase[(size_t)(r4    )*(3*Dv) + kc*8 + q + 4]);
            qa[kc][3] = f2tf32(0.125f * Qbase[(size_t)(r4 + 8)*(3*Dv) + kc*8 + q + 4]);
        }
    }

    float o[8][4];
    #pragma unroll
    for (int nc = 0; nc < 8; nc++)
        #pragma unroll
        for (int e = 0; e < 4; e++) o[nc][e] = 0.f;
    float mA = -1e30f, mB = -1e30f, lA = 0.f, lB = 0.f;

    const int ntiles = 2*qb + 2;
    for (int kt = 0; kt < ntiles; kt++) {
        const int kbase = kt*64;
        __syncthreads();
        // ---- load K,V tile into smem (tf32 bits) ----
        #pragma unroll
        for (int i = 0; i < 4; i++) {
            int idx = tid + i*256;           // 0..1023
            int r = idx >> 4, c4 = (idx & 15) << 2;
            size_t base = ((size_t)(b*Tv + kbase + r))*(3*Dv) + h*HDv + c4;
            float4 kv = *(const float4*)&qkv[base + Dv];
            float4 vv = *(const float4*)&qkv[base + 2*Dv];
            uint4 kb = make_uint4(f2tf32(kv.x), f2tf32(kv.y), f2tf32(kv.z), f2tf32(kv.w));
            uint4 vb = make_uint4(f2tf32(vv.x), f2tf32(vv.y), f2tf32(vv.z), f2tf32(vv.w));
            *(uint4*)&Ks[r*KS_LD + c4] = kb;
            *(uint4*)&Vs[r*VS_LD + c4] = vb;
        }
        __syncthreads();

        // ---- S = Q @ K^T  (16 x 64 per warp) ----
        float s[8][4];
        #pragma unroll
        for (int nc = 0; nc < 8; nc++) {
            s[nc][0] = 0.f; s[nc][1] = 0.f; s[nc][2] = 0.f; s[nc][3] = 0.f;
            #pragma unroll
            for (int kc = 0; kc < 8; kc++) {
                uint32_t kb0 = Ks[(nc*8 + r4)*KS_LD + kc*8 + q];
                uint32_t kb1 = Ks[(nc*8 + r4)*KS_LD + kc*8 + q + 4];
                mma_tf32(s[nc][0], s[nc][1], s[nc][2], s[nc][3],
                         qa[kc][0], qa[kc][1], qa[kc][2], qa[kc][3], kb0, kb1);
            }
        }

        // ---- causal mask (only needed near diagonal) ----
        if (kbase + 63 > qrow0) {
            int rowA = qrow0 + r4, rowB = qrow0 + r4 + 8;
            #pragma unroll
            for (int nc = 0; nc < 8; nc++) {
                int c0 = kbase + nc*8 + 2*q, c1 = c0 + 1;
                if (c0 > rowA) s[nc][0] = -1e30f;
                if (c1 > rowA) s[nc][1] = -1e30f;
                if (c0 > rowB) s[nc][2] = -1e30f;
                if (c1 > rowB) s[nc][3] = -1e30f;
            }
        }

        // ---- online softmax in registers ----
        float rmA = -1e30f, rmB = -1e30f;
        #pragma unroll
        for (int nc = 0; nc < 8; nc++) {
            rmA = fmaxf(rmA, fmaxf(s[nc][0], s[nc][1]));
            rmB = fmaxf(rmB, fmaxf(s[nc][2], s[nc][3]));
        }
        rmA = fmaxf(rmA, __shfl_xor_sync(0xffffffffu, rmA, 1));
        rmA = fmaxf(rmA, __shfl_xor_sync(0xffffffffu, rmA, 2));
        rmB = fmaxf(rmB, __shfl_xor_sync(0xffffffffu, rmB, 1));
        rmB = fmaxf(rmB, __shfl_xor_sync(0xffffffffu, rmB, 2));
        float mnA = fmaxf(mA, rmA), mnB = fmaxf(mB, rmB);
        float corrA = __expf(mA - mnA), corrB = __expf(mB - mnB);
        mA = mnA; mB = mnB;

        float rsA = 0.f, rsB = 0.f;
        #pragma unroll
        for (int nc = 0; nc < 8; nc++) {
            float p0 = __expf(s[nc][0] - mnA);
            float p1 = __expf(s[nc][1] - mnA);
            float p2 = __expf(s[nc][2] - mnB);
            float p3 = __expf(s[nc][3] - mnB);
            rsA += p0 + p1; rsB += p2 + p3;
            uint2 pr0 = make_uint2(f2tf32(p0), f2tf32(p1));
            uint2 pr1 = make_uint2(f2tf32(p2), f2tf32(p3));
            *(uint2*)&Pw[(r4    )*PS_LD + nc*8 + 2*q] = pr0;
            *(uint2*)&Pw[(r4 + 8)*PS_LD + nc*8 + 2*q] = pr1;
        }
        rsA += __shfl_xor_sync(0xffffffffu, rsA, 1);
        rsA += __shfl_xor_sync(0xffffffffu, rsA, 2);
        rsB += __shfl_xor_sync(0xffffffffu, rsB, 1);
        rsB += __shfl_xor_sync(0xffffffffu, rsB, 2);
        lA = lA*corrA + rsA;
        lB = lB*corrB + rsB;

        #pragma unroll
        for (int nc = 0; nc < 8; nc++) {
            o[nc][0] *= corrA; o[nc][1] *= corrA;
            o[nc][2] *= corrB; o[nc][3] *= corrB;
        }

        __syncwarp();

        // ---- O += P @ V  (16x64 += 16x64 @ 64x64) ----
        #pragma unroll
        for (int kc = 0; kc < 8; kc++) {
            uint32_t pa0 = Pw[(r4    )*PS_LD + kc*8 + q    ];
            uint32_t pa1 = Pw[(r4 + 8)*PS_LD + kc*8 + q    ];
            uint32_t pa2 = Pw[(r4    )*PS_LD + kc*8 + q + 4];
            uint32_t pa3 = Pw[(r4 + 8)*PS_LD + kc*8 + q + 4];
            #pragma unroll
            for (int nc = 0; nc < 8; nc++) {
                uint32_t vb0 = Vs[(kc*8 + q    )*VS_LD + nc*8 + r4];
                uint32_t vb1 = Vs[(kc*8 + q + 4)*VS_LD + nc*8 + r4];
                mma_tf32(o[nc][0], o[nc][1], o[nc][2], o[nc][3],
                         pa0, pa1, pa2, pa3, vb0, vb1);
            }
        }
    }

    // ---- write O / l ----
    float invA = 1.f / lA, invB = 1.f / lB;
    float* obaseA = out + ((size_t)(b*Tv + qrow0 + r4    ))*Dv + h*HDv;
    float* obaseB = out + ((size_t)(b*Tv + qrow0 + r4 + 8))*Dv + h*HDv;
    #pragma unroll
    for (int nc = 0; nc < 8; nc++) {
        int c = nc*8 + 2*q;
        *(float2*)&obaseA[c] = make_float2(o[nc][0]*invA, o[nc][1]*invA);
        *(float2*)&obaseB[c] = make_float2(o[nc][2]*invB, o[nc][3]*invB);
    }
}

// ---------------- Selective scan ----------------
__global__ __launch_bounds__(256) void scan_kernel(
    const float* __restrict__ dt, const float* __restrict__ z,
    const float* __restrict__ Bi, const float* __restrict__ Ci,
    const float* __restrict__ gate, const float* __restrict__ A_log,
    float* __restrict__ y)
{
    int tid = threadIdx.x;
    int lc = tid>>4, st = tid&15;
    int chan = blockIdx.x*16 + lc;
    int b = chan>>6, sc = chan&63;
    float A = -__expf(A_log[sc*STv + st]);
    float state = 0.f;
    size_t base64 = ((size_t)b*Tv)*SCv + sc;
    size_t base16 = ((size_t)b*Tv)*STv + st;

    float dtc = dt[base64], zc = z[base64], Bc = Bi[base16], Cc = Ci[base16];
    for (int t=0; t<Tv; t++){
        float dtn=0.f, zn=0.f, Bn=0.f, Cn=0.f;
        if (t+1 < Tv){
            dtn = dt[base64 + (size_t)(t+1)*SCv];
            zn  = z [base64 + (size_t)(t+1)*SCv];
            Bn  = Bi[base16 + (size_t)(t+1)*STv];
            Cn  = Ci[base16 + (size_t)(t+1)*STv];
        }
        float ab = 1.0f + dtc*A;
        state = fmaf(ab, state, (dtc*zc)*Bc);
        float p = state*Cc;
        #pragma unroll
        for (int o=8;o>0;o>>=1) p += __shfl_xor_sync(0xffffffffu, p, o, 16);
        if (st==0) y[base64 + (size_t)t*SCv] = p * gate[base64 + (size_t)t*SCv];
        dtc=dtn; zc=zn; Bc=Bn; Cc=Cn;
    }
}

// ---------------- launch ----------------
extern "C" void kernel_launch(void* const* d_in, const int* in_sizes, int n_in,
                              void* d_out, int out_size)
{
    const float* x      = (const float*)d_in[0];
    const float* qkv_w  = (const float*)d_in[1];
    const float* o_w    = (const float*)d_in[2];
    const float* n1w    = (const float*)d_in[3];
    const float* n2w    = (const float*)d_in[4];
    const float* in_w   = (const float*)d_in[5];
    const float* out_w  = (const float*)d_in[6];
    const float* A_log  = (const float*)d_in[7];
    const float* Bp_w   = (const float*)d_in[8];
    const float* Cp_w   = (const float*)d_in[9];
    const float* dt_w   = (const float*)d_in[10];
    const float* dt_b   = (const float*)d_in[11];
    const float* gate_w = (const float*)d_in[12];
    float* out = (float*)d_out;

    float *h,*qkv,*attn,*x1,*h2,*zb,*gateb,*Bib,*Cib,*dtb,*yb;
    cudaGetSymbolAddress((void**)&h,    g_h);
    cudaGetSymbolAddress((void**)&qkv,  g_qkv);
    cudaGetSymbolAddress((void**)&attn, g_attn);
    cudaGetSymbolAddress((void**)&x1,   g_x1);
    cudaGetSymbolAddress((void**)&h2,   g_h2);
    cudaGetSymbolAddress((void**)&zb,   g_z);
    cudaGetSymbolAddress((void**)&gateb,g_gate);
    cudaGetSymbolAddress((void**)&Bib,  g_Bi);
    cudaGetSymbolAddress((void**)&Cib,  g_Ci);
    cudaGetSymbolAddress((void**)&dtb,  g_dt);
    cudaGetSymbolAddress((void**)&yb,   g_y);

    const int attn_smem = (64*KS_LD + 64*VS_LD + 8*16*PS_LD) * 4;  // 70656 B
    cudaFuncSetAttribute(attn_mma_kernel, cudaFuncAttributeMaxDynamicSharedMemorySize, attn_smem);

    // 1. rmsnorm1
    rmsnorm_kernel<<<Mrows, 256>>>(x, n1w, h);
    // 2. qkv = h @ qkv_w^T   [4096, 3072]
    gemm_tf32<<<dim3(24, 32), 256>>>(h, qkv_w, nullptr, qkv, Mrows, 3*Dv, Dv, 0);
    // 3. attention
    attn_mma_kernel<<<dim3(Tv/128, Hv, Bv), 256, attn_smem>>>(qkv, attn);
    // 4. x1 = x + attn @ o_w^T
    gemm_tf32<<<dim3(8, 32), 256>>>(attn, o_w, x, x1, Mrows, Dv, Dv, 0);
    // 5. rmsnorm2
    rmsnorm_kernel<<<Mrows, 256>>>(x1, n2w, h2);
    // 6. z = h2 @ in_w^T   [4096, 64]
    gemm_tf32<<<dim3(1, 32), 256>>>(h2, in_w, nullptr, zb, Mrows, SCv, Dv, 0);
    // 7. gate = silu(h2 @ gate_w^T)
    gemm_tf32<<<dim3(1, 32), 256>>>(h2, gate_w, nullptr, gateb, Mrows, SCv, Dv, 1);
    // 8. Bi = z @ Bp_w^T  [4096,16]
    gemm64_kernel<<<dim3(1,64), 256>>>(zb, Bp_w, nullptr, nullptr, Bib, Mrows, STv, SCv, 0);
    // 9. Ci = z @ Cp_w^T
    gemm64_kernel<<<dim3(1,64), 256>>>(zb, Cp_w, nullptr, nullptr, Cib, Mrows, STv, SCv, 0);
    // 10. dt = softplus(z @ dt_w^T + dt_b)
    gemm64_kernel<<<dim3(1,64), 256>>>(zb, dt_w, dt_b, nullptr, dtb, Mrows, SCv, SCv, 2);
    // 11. scan -> y (already multiplied by gate)
    scan_kernel<<<8, 256>>>(dtb, zb, Bib, Cib, gateb, A_log, yb);
    // 12. out = x1 + y @ out_w^T
    gemm_tf32<<<dim3(8, 32), 256>>>(yb, out_w, x1, out, Mrows, Dv, SCv, 0);
}

// round 5
// speedup vs baseline: 2.4676x; 1.4261x over previous
#include <cuda_runtime.h>
#include <cuda_bf16.h>
#include <mma.h>
#include <math.h>
#include <cstdint>

using namespace nvcuda;

#define Bv 2
#define Tv 2048
#define Dv 1024
#define Hv 16
#define HDv 64
#define SCv 64
#define STv 16
#define Mrows (Bv*Tv)   // 4096
#define EPSR 1.1920929e-07f

// ---------------- scratch (device globals; no allocation allowed) ----------
__device__ float g_h   [Mrows*Dv];
__device__ float g_qkv [Mrows*3*Dv];
__device__ float g_attn[Mrows*Dv];
__device__ float g_x1  [Mrows*Dv];
__device__ float g_h2  [Mrows*Dv];
__device__ float g_z   [Mrows*SCv];
__device__ float g_gate[Mrows*SCv];
__device__ float g_Bi  [Mrows*STv];
__device__ float g_Ci  [Mrows*STv];
__device__ float g_dt  [Mrows*SCv];
__device__ float g_y   [Mrows*SCv];
// scan scratch: [chan][chunk][st]
__device__ float g_scanA[128*16*16];
__device__ float g_scanB[128*16*16];
__device__ float g_scanS[128*16*16];

__device__ __forceinline__ uint32_t f2tf32(float x) {
    uint32_t r;
    asm("cvt.rna.tf32.f32 %0, %1;" : "=r"(r) : "f"(x));
    return r;
}

__device__ __forceinline__ void mma_tf32(float& d0, float& d1, float& d2, float& d3,
                                         uint32_t a0, uint32_t a1, uint32_t a2, uint32_t a3,
                                         uint32_t b0, uint32_t b1) {
    asm volatile(
        "mma.sync.aligned.m16n8k8.row.col.f32.tf32.tf32.f32 "
        "{%0,%1,%2,%3}, {%4,%5,%6,%7}, {%8,%9}, {%0,%1,%2,%3};"
        : "+f"(d0), "+f"(d1), "+f"(d2), "+f"(d3)
        : "r"(a0), "r"(a1), "r"(a2), "r"(a3), "r"(b0), "r"(b1));
}

__device__ __forceinline__ void cp16(float* dst, const float* src) {
    uint32_t d = (uint32_t)__cvta_generic_to_shared(dst);
    asm volatile("cp.async.cg.shared.global [%0], [%1], 16;" :: "r"(d), "l"(src));
}

// ---------------- RMSNorm ----------------
__global__ __launch_bounds__(256) void rmsnorm_kernel(
    const float* __restrict__ x, const float* __restrict__ w, float* __restrict__ o)
{
    int row = blockIdx.x;
    const float4* xr = (const float4*)(x + (size_t)row*Dv);
    float4 v = xr[threadIdx.x];
    float ss = v.x*v.x + v.y*v.y + v.z*v.z + v.w*v.w;
    #pragma unroll
    for (int off=16; off; off>>=1) ss += __shfl_xor_sync(0xffffffffu, ss, off);
    __shared__ float sm[8];
    int wid = threadIdx.x>>5, lane = threadIdx.x&31;
    if (lane==0) sm[wid] = ss;
    __syncthreads();
    float tot = sm[0]+sm[1]+sm[2]+sm[3]+sm[4]+sm[5]+sm[6]+sm[7];
    float scale = rsqrtf(tot*(1.0f/Dv) + EPSR);
    const float4* wr = (const float4*)w;
    float4 wv = wr[threadIdx.x];
    float4 ov = make_float4(v.x*scale*wv.x, v.y*scale*wv.y, v.z*scale*wv.z, v.w*scale*wv.w);
    ((float4*)(o + (size_t)row*Dv))[threadIdx.x] = ov;
}

// ---------------- TF32 tensor-core GEMM: C = A[M,K] @ [W;W2][N,K]^T ----------
// Columns [0,nsplit) come from W -> stored to C (ld=nsplit if split else N).
// Columns [nsplit,N) come from W2 -> stored to C2 (ld=N-nsplit), act2=1 => silu.
// res: optional residual added to first range (ld=N).
__global__ __launch_bounds__(256, 2) void gemm_tf32(
    const float* __restrict__ A, const float* __restrict__ W, const float* __restrict__ W2,
    const float* __restrict__ res, float* __restrict__ C, float* __restrict__ C2,
    int M, int N, int nsplit, int K, int act2)
{
    __shared__ float As[128*20];
    __shared__ float Ws[128*20];

    const int tid = threadIdx.x;
    const int w   = tid >> 5;
    const int wm  = w >> 1;
    const int wn  = w & 1;
    const int bm  = blockIdx.y * 128;
    const int bn  = blockIdx.x * 128;

    wmma::fragment<wmma::accumulator, 16, 16, 8, float> acc[2][4];
    #pragma unroll
    for (int i = 0; i < 2; i++)
        #pragma unroll
        for (int j = 0; j < 4; j++)
            wmma::fill_fragment(acc[i][j], 0.0f);

    const int lr  = tid >> 2;
    const int lc4 = (tid & 3) << 2;

    int r0 = bn + lr, r1 = bn + lr + 64;
    const float* wr0 = (r0 < nsplit) ? &W[(size_t)r0*K] : &W2[(size_t)(r0 - nsplit)*K];
    const float* wr1 = (r1 < nsplit) ? &W[(size_t)r1*K] : &W2[(size_t)(r1 - nsplit)*K];

    float4 a0, a1, b0, b1;
    {
        a0 = *(const float4*)&A[(size_t)(bm + lr) * K + lc4];
        a1 = *(const float4*)&A[(size_t)(bm + lr + 64) * K + lc4];
        b0 = *(const float4*)&wr0[lc4];
        b1 = *(const float4*)&wr1[lc4];
    }
    As[lr*20 + lc4 + 0] = wmma::__float_to_tf32(a0.x);
    As[lr*20 + lc4 + 1] = wmma::__float_to_tf32(a0.y);
    As[lr*20 + lc4 + 2] = wmma::__float_to_tf32(a0.z);
    As[lr*20 + lc4 + 3] = wmma::__float_to_tf32(a0.w);
    As[(lr+64)*20 + lc4 + 0] = wmma::__float_to_tf32(a1.x);
    As[(lr+64)*20 + lc4 + 1] = wmma::__float_to_tf32(a1.y);
    As[(lr+64)*20 + lc4 + 2] = wmma::__float_to_tf32(a1.z);
    As[(lr+64)*20 + lc4 + 3] = wmma::__float_to_tf32(a1.w);
    Ws[lr*20 + lc4 + 0] = wmma::__float_to_tf32(b0.x);
    Ws[lr*20 + lc4 + 1] = wmma::__float_to_tf32(b0.y);
    Ws[lr*20 + lc4 + 2] = wmma::__float_to_tf32(b0.z);
    Ws[lr*20 + lc4 + 3] = wmma::__float_to_tf32(b0.w);
    Ws[(lr+64)*20 + lc4 + 0] = wmma::__float_to_tf32(b1.x);
    Ws[(lr+64)*20 + lc4 + 1] = wmma::__float_to_tf32(b1.y);
    Ws[(lr+64)*20 + lc4 + 2] = wmma::__float_to_tf32(b1.z);
    Ws[(lr+64)*20 + lc4 + 3] = wmma::__float_to_tf32(b1.w);
    __syncthreads();

    for (int k0 = 0; k0 < K; k0 += 16) {
        const bool more = (k0 + 16) < K;
        if (more) {
            int kn = k0 + 16;
            a0 = *(const float4*)&A[(size_t)(bm + lr) * K + kn + lc4];
            a1 = *(const float4*)&A[(size_t)(bm + lr + 64) * K + kn + lc4];
            b0 = *(const float4*)&wr0[kn + lc4];
            b1 = *(const float4*)&wr1[kn + lc4];
        }

        #pragma unroll
        for (int ks = 0; ks < 16; ks += 8) {
            wmma::fragment<wmma::matrix_a, 16, 16, 8, wmma::precision::tf32, wmma::row_major> fa[2];
            wmma::fragment<wmma::matrix_b, 16, 16, 8, wmma::precision::tf32, wmma::col_major> fb[4];
            #pragma unroll
            for (int i = 0; i < 2; i++)
                wmma::load_matrix_sync(fa[i], &As[(wm*32 + i*16)*20 + ks], 20);
            #pragma unroll
            for (int j = 0; j < 4; j++)
                wmma::load_matrix_sync(fb[j], &Ws[(wn*64 + j*16)*20 + ks], 20);
            #pragma unroll
            for (int i = 0; i < 2; i++)
                #pragma unroll
                for (int j = 0; j < 4; j++)
                    wmma::mma_sync(acc[i][j], fa[i], fb[j], acc[i][j]);
        }

        if (more) {
            __syncthreads();
            As[lr*20 + lc4 + 0] = wmma::__float_to_tf32(a0.x);
            As[lr*20 + lc4 + 1] = wmma::__float_to_tf32(a0.y);
            As[lr*20 + lc4 + 2] = wmma::__float_to_tf32(a0.z);
            As[lr*20 + lc4 + 3] = wmma::__float_to_tf32(a0.w);
            As[(lr+64)*20 + lc4 + 0] = wmma::__float_to_tf32(a1.x);
            As[(lr+64)*20 + lc4 + 1] = wmma::__float_to_tf32(a1.y);
            As[(lr+64)*20 + lc4 + 2] = wmma::__float_to_tf32(a1.z);
            As[(lr+64)*20 + lc4 + 3] = wmma::__float_to_tf32(a1.w);
            Ws[lr*20 + lc4 + 0] = wmma::__float_to_tf32(b0.x);
            Ws[lr*20 + lc4 + 1] = wmma::__float_to_tf32(b0.y);
            Ws[lr*20 + lc4 + 2] = wmma::__float_to_tf32(b0.z);
            Ws[lr*20 + lc4 + 3] = wmma::__float_to_tf32(b0.w);
            Ws[(lr+64)*20 + lc4 + 0] = wmma::__float_to_tf32(b1.x);
            Ws[(lr+64)*20 + lc4 + 1] = wmma::__float_to_tf32(b1.y);
            Ws[(lr+64)*20 + lc4 + 2] = wmma::__float_to_tf32(b1.z);
            Ws[(lr+64)*20 + lc4 + 3] = wmma::__float_to_tf32(b1.w);
            __syncthreads();
        }
    }

    const int ld1 = nsplit;          // first-range ld (== N for plain calls)
    const int ld2 = N - nsplit;      // second-range ld (0 for plain calls)
    #pragma unroll
    for (int i = 0; i < 2; i++) {
        #pragma unroll
        for (int j = 0; j < 4; j++) {
            int row = bm + wm*32 + i*16;
            int col = bn + wn*64 + j*16;
            if (col < nsplit) {
                if (res) {
                    wmma::fragment<wmma::accumulator, 16, 16, 8, float> r;
                    wmma::load_matrix_sync(r, &res[(size_t)row * N + col], N, wmma::mem_row_major);
                    #pragma unroll
                    for (int e = 0; e < r.num_elements; e++) acc[i][j].x[e] += r.x[e];
                }
                wmma::store_matrix_sync(&C[(size_t)row * ld1 + col], acc[i][j], ld1, wmma::mem_row_major);
            } else {
                if (act2 == 1) {
                    #pragma unroll
                    for (int e = 0; e < acc[i][j].num_elements; e++) {
                        float v = acc[i][j].x[e];
                        acc[i][j].x[e] = v / (1.0f + __expf(-v));
                    }
                }
                wmma::store_matrix_sync(&C2[(size_t)row * ld2 + (col - nsplit)], acc[i][j], ld2, wmma::mem_row_major);
            }
        }
    }
}

// ---------------- fp32 SGEMM (small matmuls: Bi, Ci, dt) ----------------
__global__ __launch_bounds__(256) void gemm64_kernel(
    const float* __restrict__ A, const float* __restrict__ W,
    const float* __restrict__ bias, const float* __restrict__ res,
    float* __restrict__ C, int M, int N, int K, int act)
{
    __shared__ float As[16][68];
    __shared__ float Ws[16][68];
    const int tid = threadIdx.x;
    const int bm = blockIdx.y*64, bn = blockIdx.x*64;
    const int lr = tid>>2;
    const int lc = (tid&3)<<2;
    const int ty = tid>>4, tx = tid&15;
    float acc[4][4];
    #pragma unroll
    for (int i=0;i<4;i++)
        #pragma unroll
        for (int j=0;j<4;j++) acc[i][j]=0.f;

    for (int k0=0; k0<K; k0+=16) {
        float4 a = *(const float4*)&A[(size_t)(bm+lr)*K + k0 + lc];
        As[lc+0][lr]=a.x; As[lc+1][lr]=a.y; As[lc+2][lr]=a.z; As[lc+3][lr]=a.w;
        float4 w = make_float4(0.f,0.f,0.f,0.f);
        if (bn+lr < N) w = *(const float4*)&W[(size_t)(bn+lr)*K + k0 + lc];
        Ws[lc+0][lr]=w.x; Ws[lc+1][lr]=w.y; Ws[lc+2][lr]=w.z; Ws[lc+3][lr]=w.w;
        __syncthreads();
        #pragma unroll
        for (int k=0;k<16;k++){
            float4 av = *(const float4*)&As[k][ty*4];
            float4 wv = *(const float4*)&Ws[k][tx*4];
            float aa[4] = {av.x,av.y,av.z,av.w};
            float ww[4] = {wv.x,wv.y,wv.z,wv.w};
            #pragma unroll
            for (int i=0;i<4;i++)
                #pragma unroll
                for (int j=0;j<4;j++) acc[i][j] = fmaf(aa[i], ww[j], acc[i][j]);
        }
        __syncthreads();
    }

    const int col = bn + tx*4;
    if (col < N) {
        float4 bv = make_float4(0,0,0,0);
        if (bias) bv = *(const float4*)&bias[col];
        #pragma unroll
        for (int i=0;i<4;i++){
            int row = bm + ty*4 + i;
            float c[4];
            #pragma unroll
            for (int j=0;j<4;j++) c[j] = acc[i][j];
            if (bias) { c[0]+=bv.x; c[1]+=bv.y; c[2]+=bv.z; c[3]+=bv.w; }
            if (act==1) {
                #pragma unroll
                for (int j=0;j<4;j++) c[j] = c[j] / (1.f + __expf(-c[j]));
            } else if (act==2) {
                #pragma unroll
                for (int j=0;j<4;j++) c[j] = (c[j] > 20.f) ? c[j] : log1pf(__expf(c[j]));
            }
            if (res) {
                float4 rv = *(const float4*)&res[(size_t)row*N + col];
                c[0]+=rv.x; c[1]+=rv.y; c[2]+=rv.z; c[3]+=rv.w;
            }
            *(float4*)&C[(size_t)row*N + col] = make_float4(c[0],c[1],c[2],c[3]);
        }
    }
}

// ---------------- Flash attention v3: cp.async double-buffer, P via shuffles ----
#define KS_LD 68
#define VS_LD 72
#define STAGEF (64*KS_LD + 64*VS_LD)   // 8960 floats per stage
__global__ __launch_bounds__(256, 2) void attn_mma_kernel(
    const float* __restrict__ qkv, float* __restrict__ out)
{
    extern __shared__ float smf[];

    const int tid = threadIdx.x;
    const int w   = tid >> 5;
    const int l   = tid & 31;
    const int g   = l >> 2;     // 0..7
    const int q   = l & 3;      // 0..3
    const int qb  = (int)gridDim.x - 1 - (int)blockIdx.x;  // heavy CTAs first
    const int h = blockIdx.y, b = blockIdx.z;
    const int qrow0 = qb*128 + w*16;

    // ---- load Q into A fragments (scaled by 1/8, rna-rounded) ----
    uint32_t qa[8][4];
    {
        const float* Qbase = qkv + ((size_t)(b*Tv + qrow0))*(3*Dv) + h*HDv;
        #pragma unroll
        for (int kc = 0; kc < 8; kc++) {
            qa[kc][0] = f2tf32(0.125f * Qbase[(size_t)(g    )*(3*Dv) + kc*8 + q    ]);
            qa[kc][1] = f2tf32(0.125f * Qbase[(size_t)(g + 8)*(3*Dv) + kc*8 + q    ]);
            qa[kc][2] = f2tf32(0.125f * Qbase[(size_t)(g    )*(3*Dv) + kc*8 + q + 4]);
            qa[kc][3] = f2tf32(0.125f * Qbase[(size_t)(g + 8)*(3*Dv) + kc*8 + q + 4]);
        }
    }

    float o[8][4];
    #pragma unroll
    for (int nc = 0; nc < 8; nc++)
        #pragma unroll
        for (int e = 0; e < 4; e++) o[nc][e] = 0.f;
    float mA = -1e30f, mB = -1e30f, lA = 0.f, lB = 0.f;

    const int ntiles = 2*qb + 2;

    // prologue: issue tile 0
    {
        float* Kb = smf;
        float* Vb = Kb + 64*KS_LD;
        #pragma unroll
        for (int i = 0; i < 4; i++) {
            int idx = tid + i*256;
            int r = idx >> 4, c4 = (idx & 15) << 2;
            const float* src = qkv + ((size_t)(b*Tv + r))*(3*Dv) + h*HDv + c4;
            cp16(Kb + r*KS_LD + c4, src + Dv);
            cp16(Vb + r*VS_LD + c4, src + 2*Dv);
        }
        asm volatile("cp.async.commit_group;" ::);
    }

    for (int kt = 0; kt < ntiles; kt++) {
        const int kbase = kt*64;
        // prefetch next tile
        if (kt + 1 < ntiles) {
            float* Kb = smf + ((kt+1)&1)*STAGEF;
            float* Vb = Kb + 64*KS_LD;
            #pragma unroll
            for (int i = 0; i < 4; i++) {
                int idx = tid + i*256;
                int r = idx >> 4, c4 = (idx & 15) << 2;
                const float* src = qkv + ((size_t)(b*Tv + kbase + 64 + r))*(3*Dv) + h*HDv + c4;
                cp16(Kb + r*KS_LD + c4, src + Dv);
                cp16(Vb + r*VS_LD + c4, src + 2*Dv);
            }
            asm volatile("cp.async.commit_group;" ::);
            asm volatile("cp.async.wait_group 1;" ::);
        } else {
            asm volatile("cp.async.wait_group 0;" ::);
        }
        __syncthreads();

        const float* Kb = smf + (kt&1)*STAGEF;
        const float* Vb = Kb + 64*KS_LD;

        // ---- S = Q @ K^T  (16 x 64 per warp), K raw f32 bits (HW-truncated tf32) ----
        float s[8][4];
        #pragma unroll
        for (int nc = 0; nc < 8; nc++) {
            s[nc][0] = 0.f; s[nc][1] = 0.f; s[nc][2] = 0.f; s[nc][3] = 0.f;
            #pragma unroll
            for (int kc = 0; kc < 8; kc++) {
                uint32_t kb0 = __float_as_uint(Kb[(nc*8 + g)*KS_LD + kc*8 + q]);
                uint32_t kb1 = __float_as_uint(Kb[(nc*8 + g)*KS_LD + kc*8 + q + 4]);
                mma_tf32(s[nc][0], s[nc][1], s[nc][2], s[nc][3],
                         qa[kc][0], qa[kc][1], qa[kc][2], qa[kc][3], kb0, kb1);
            }
        }

        // ---- causal mask ----
        if (kbase + 63 > qrow0) {
            int rowA = qrow0 + g, rowB = qrow0 + g + 8;
            #pragma unroll
            for (int nc = 0; nc < 8; nc++) {
                int c0 = kbase + nc*8 + 2*q, c1 = c0 + 1;
                if (c0 > rowA) s[nc][0] = -1e30f;
                if (c1 > rowA) s[nc][1] = -1e30f;
                if (c0 > rowB) s[nc][2] = -1e30f;
                if (c1 > rowB) s[nc][3] = -1e30f;
            }
        }

        // ---- online softmax in registers ----
        float rmA = -1e30f, rmB = -1e30f;
        #pragma unroll
        for (int nc = 0; nc < 8; nc++) {
            rmA = fmaxf(rmA, fmaxf(s[nc][0], s[nc][1]));
            rmB = fmaxf(rmB, fmaxf(s[nc][2], s[nc][3]));
        }
        rmA = fmaxf(rmA, __shfl_xor_sync(0xffffffffu, rmA, 1));
        rmA = fmaxf(rmA, __shfl_xor_sync(0xffffffffu, rmA, 2));
        rmB = fmaxf(rmB, __shfl_xor_sync(0xffffffffu, rmB, 1));
        rmB = fmaxf(rmB, __shfl_xor_sync(0xffffffffu, rmB, 2));
        float mnA = fmaxf(mA, rmA), mnB = fmaxf(mB, rmB);
        float corrA = __expf(mA - mnA), corrB = __expf(mB - mnB);
        mA = mnA; mB = mnB;

        float rsA = 0.f, rsB = 0.f;
        #pragma unroll
        for (int nc = 0; nc < 8; nc++) {
            s[nc][0] = __expf(s[nc][0] - mnA);
            s[nc][1] = __expf(s[nc][1] - mnA);
            s[nc][2] = __expf(s[nc][2] - mnB);
            s[nc][3] = __expf(s[nc][3] - mnB);
            rsA += s[nc][0] + s[nc][1];
            rsB += s[nc][2] + s[nc][3];
        }
        rsA += __shfl_xor_sync(0xffffffffu, rsA, 1);
        rsA += __shfl_xor_sync(0xffffffffu, rsA, 2);
        rsB += __shfl_xor_sync(0xffffffffu, rsB, 1);
        rsB += __shfl_xor_sync(0xffffffffu, rsB, 2);
        lA = lA*corrA + rsA;
        lB = lB*corrB + rsB;

        #pragma unroll
        for (int nc = 0; nc < 8; nc++) {
            o[nc][0] *= corrA; o[nc][1] *= corrA;
            o[nc][2] *= corrB; o[nc][3] *= corrB;
        }

        // ---- O += P @ V : convert C-frag P -> A-frag via shuffles ----
        const int src0 = (l & 28) | (q >> 1);   // 4g + (q>>1)
        const bool odd = (q & 1);
        #pragma unroll
        for (int kc = 0; kc < 8; kc++) {
            float e0 = __shfl_sync(0xffffffffu, s[kc][0], src0);
            float e1 = __shfl_sync(0xffffffffu, s[kc][1], src0);
            float e2 = __shfl_sync(0xffffffffu, s[kc][2], src0);
            float e3 = __shfl_sync(0xffffffffu, s[kc][3], src0);
            float f0 = __shfl_sync(0xffffffffu, s[kc][0], src0 + 2);
            float f1 = __shfl_sync(0xffffffffu, s[kc][1], src0 + 2);
            float f2 = __shfl_sync(0xffffffffu, s[kc][2], src0 + 2);
            float f3 = __shfl_sync(0xffffffffu, s[kc][3], src0 + 2);
            uint32_t pa0 = f2tf32(odd ? e1 : e0);
            uint32_t pa1 = f2tf32(odd ? e3 : e2);
            uint32_t pa2 = f2tf32(odd ? f1 : f0);
            uint32_t pa3 = f2tf32(odd ? f3 : f2);
            #pragma unroll
            for (int nc = 0; nc < 8; nc++) {
                uint32_t vb0 = __float_as_uint(Vb[(kc*8 + q    )*VS_LD + nc*8 + g]);
                uint32_t vb1 = __float_as_uint(Vb[(kc*8 + q + 4)*VS_LD + nc*8 + g]);
                mma_tf32(o[nc][0], o[nc][1], o[nc][2], o[nc][3],
                         pa0, pa1, pa2, pa3, vb0, vb1);
            }
        }
        __syncthreads();   // all warps done with this buffer before it is refilled
    }

    // ---- write O / l ----
    float invA = 1.f / lA, invB = 1.f / lB;
    float* obaseA = out + ((size_t)(b*Tv + qrow0 + g    ))*Dv + h*HDv;
    float* obaseB = out + ((size_t)(b*Tv + qrow0 + g + 8))*Dv + h*HDv;
    #pragma unroll
    for (int nc = 0; nc < 8; nc++) {
        int c = nc*8 + 2*q;
        *(float2*)&obaseA[c] = make_float2(o[nc][0]*invA, o[nc][1]*invA);
        *(float2*)&obaseB[c] = make_float2(o[nc][2]*invB, o[nc][3]*invB);
    }
}

// ---------------- Parallel selective scan: 3 phases ----------------
// thread = (chan, chunk); chan = b*64+sc (128), chunk of 128 timesteps (16)
__global__ __launch_bounds__(256) void scan_phase1(
    const float* __restrict__ dt, const float* __restrict__ z,
    const float* __restrict__ Bi, const float* __restrict__ A_log)
{
    int gth = blockIdx.x*256 + threadIdx.x;     // 0..2047
    int chan = gth & 127, chunk = gth >> 7;
    int b = chan >> 6, sc = chan & 63;
    float A[16];
    #pragma unroll
    for (int st = 0; st < 16; st++) A[st] = -__expf(A_log[sc*STv + st]);
    float aP[16], bP[16];
    #pragma unroll
    for (int st = 0; st < 16; st++) { aP[st] = 1.f; bP[st] = 0.f; }
    int t0 = chunk*128;
    const float* dtp = dt + ((size_t)b*Tv + t0)*SCv + sc;
    const float* zp  = z  + ((size_t)b*Tv + t0)*SCv + sc;
    const float* Bp  = Bi + ((size_t)b*Tv + t0)*STv;
    for (int tt = 0; tt < 128; tt++) {
        float dtc = dtp[(size_t)tt*SCv];
        float zc  = zp [(size_t)tt*SCv];
        float dz  = dtc*zc;
        float4 B0 = *(const float4*)&Bp[tt*STv + 0];
        float4 B1 = *(const float4*)&Bp[tt*STv + 4];
        float4 B2 = *(const float4*)&Bp[tt*STv + 8];
        float4 B3 = *(const float4*)&Bp[tt*STv + 12];
        float Bvv[16] = {B0.x,B0.y,B0.z,B0.w, B1.x,B1.y,B1.z,B1.w,
                         B2.x,B2.y,B2.z,B2.w, B3.x,B3.y,B3.z,B3.w};
        #pragma unroll
        for (int st = 0; st < 16; st++) {
            float ab = fmaf(dtc, A[st], 1.f);
            aP[st] *= ab;
            bP[st] = fmaf(ab, bP[st], dz*Bvv[st]);
        }
    }
    int base = (chan*16 + chunk)*16;
    #pragma unroll
    for (int st = 0; st < 16; st++) { g_scanA[base+st] = aP[st]; g_scanB[base+st] = bP[st]; }
}

__global__ __launch_bounds__(256) void scan_phase2()
{
    int gth = blockIdx.x*256 + threadIdx.x;     // 0..2047
    int chan = gth >> 4, st = gth & 15;
    float s = 0.f;
    #pragma unroll
    for (int ch = 0; ch < 16; ch++) {
        int idx = (chan*16 + ch)*16 + st;
        g_scanS[idx] = s;
        s = fmaf(g_scanA[idx], s, g_scanB[idx]);
    }
}

__global__ __launch_bounds__(256) void scan_phase3(
    const float* __restrict__ dt, const float* __restrict__ z,
    const float* __restrict__ Bi, const float* __restrict__ Ci,
    const float* __restrict__ gate, const float* __restrict__ A_log,
    float* __restrict__ y)
{
    int gth = blockIdx.x*256 + threadIdx.x;
    int chan = gth & 127, chunk = gth >> 7;
    int b = chan >> 6, sc = chan & 63;
    float A[16];
    #pragma unroll
    for (int st = 0; st < 16; st++) A[st] = -__expf(A_log[sc*STv + st]);
    float state[16];
    {
        int base = (chan*16 + chunk)*16;
        #pragma unroll
        for (int st = 0; st < 16; st++) state[st] = g_scanS[base+st];
    }
    int t0 = chunk*128;
    const float* dtp = dt   + ((size_t)b*Tv + t0)*SCv + sc;
    const float* zp  = z    + ((size_t)b*Tv + t0)*SCv + sc;
    const float* gp  = gate + ((size_t)b*Tv + t0)*SCv + sc;
    const float* Bp  = Bi + ((size_t)b*Tv + t0)*STv;
    const float* Cp  = Ci + ((size_t)b*Tv + t0)*STv;
    float* yp = y + ((size_t)b*Tv + t0)*SCv + sc;
    for (int tt = 0; tt < 128; tt++) {
        float dtc = dtp[(size_t)tt*SCv];
        float zc  = zp [(size_t)tt*SCv];
        float dz  = dtc*zc;
        float4 B0 = *(const float4*)&Bp[tt*STv + 0];
        float4 B1 = *(const float4*)&Bp[tt*STv + 4];
        float4 B2 = *(const float4*)&Bp[tt*STv + 8];
        float4 B3 = *(const float4*)&Bp[tt*STv + 12];
        float4 C0 = *(const float4*)&Cp[tt*STv + 0];
        float4 C1 = *(const float4*)&Cp[tt*STv + 4];
        float4 C2 = *(const float4*)&Cp[tt*STv + 8];
        float4 C3 = *(const float4*)&Cp[tt*STv + 12];
        float Bvv[16] = {B0.x,B0.y,B0.z,B0.w, B1.x,B1.y,B1.z,B1.w,
                         B2.x,B2.y,B2.z,B2.w, B3.x,B3.y,B3.z,B3.w};
        float Cvv[16] = {C0.x,C0.y,C0.z,C0.w, C1.x,C1.y,C1.z,C1.w,
                         C2.x,C2.y,C2.z,C2.w, C3.x,C3.y,C3.z,C3.w};
        float p0 = 0.f, p1 = 0.f, p2 = 0.f, p3 = 0.f;
        #pragma unroll
        for (int st = 0; st < 16; st += 4) {
            float ab;
            ab = fmaf(dtc, A[st+0], 1.f); state[st+0] = fmaf(ab, state[st+0], dz*Bvv[st+0]); p0 = fmaf(state[st+0], Cvv[st+0], p0);
            ab = fmaf(dtc, A[st+1], 1.f); state[st+1] = fmaf(ab, state[st+1], dz*Bvv[st+1]); p1 = fmaf(state[st+1], Cvv[st+1], p1);
            ab = fmaf(dtc, A[st+2], 1.f); state[st+2] = fmaf(ab, state[st+2], dz*Bvv[st+2]); p2 = fmaf(state[st+2], Cvv[st+2], p2);
            ab = fmaf(dtc, A[st+3], 1.f); state[st+3] = fmaf(ab, state[st+3], dz*Bvv[st+3]); p3 = fmaf(state[st+3], Cvv[st+3], p3);
        }
        float p = (p0 + p1) + (p2 + p3);
        yp[(size_t)tt*SCv] = p * gp[(size_t)tt*SCv];
    }
}

// ---------------- launch ----------------
extern "C" void kernel_launch(void* const* d_in, const int* in_sizes, int n_in,
                              void* d_out, int out_size)
{
    const float* x      = (const float*)d_in[0];
    const float* qkv_w  = (const float*)d_in[1];
    const float* o_w    = (const float*)d_in[2];
    const float* n1w    = (const float*)d_in[3];
    const float* n2w    = (const float*)d_in[4];
    const float* in_w   = (const float*)d_in[5];
    const float* out_w  = (const float*)d_in[6];
    const float* A_log  = (const float*)d_in[7];
    const float* Bp_w   = (const float*)d_in[8];
    const float* Cp_w   = (const float*)d_in[9];
    const float* dt_w   = (const float*)d_in[10];
    const float* dt_b   = (const float*)d_in[11];
    const float* gate_w = (const float*)d_in[12];
    float* out = (float*)d_out;

    float *h,*qkv,*attn,*x1,*h2,*zb,*gateb,*Bib,*Cib,*dtb,*yb;
    cudaGetSymbolAddress((void**)&h,    g_h);
    cudaGetSymbolAddress((void**)&qkv,  g_qkv);
    cudaGetSymbolAddress((void**)&attn, g_attn);
    cudaGetSymbolAddress((void**)&x1,   g_x1);
    cudaGetSymbolAddress((void**)&h2,   g_h2);
    cudaGetSymbolAddress((void**)&zb,   g_z);
    cudaGetSymbolAddress((void**)&gateb,g_gate);
    cudaGetSymbolAddress((void**)&Bib,  g_Bi);
    cudaGetSymbolAddress((void**)&Cib,  g_Ci);
    cudaGetSymbolAddress((void**)&dtb,  g_dt);
    cudaGetSymbolAddress((void**)&yb,   g_y);

    const int attn_smem = 2*STAGEF*4;   // 71680 B
    cudaFuncSetAttribute(attn_mma_kernel, cudaFuncAttributeMaxDynamicSharedMemorySize, attn_smem);

    // 1. rmsnorm1
    rmsnorm_kernel<<<Mrows, 256>>>(x, n1w, h);
    // 2. qkv = h @ qkv_w^T   [4096, 3072]
    gemm_tf32<<<dim3(24, 32), 256>>>(h, qkv_w, qkv_w, nullptr, qkv, nullptr, Mrows, 3*Dv, 3*Dv, Dv, 0);
    // 3. attention
    attn_mma_kernel<<<dim3(Tv/128, Hv, Bv), 256, attn_smem>>>(qkv, attn);
    // 4. x1 = x + attn @ o_w^T
    gemm_tf32<<<dim3(8, 32), 256>>>(attn, o_w, o_w, x, x1, nullptr, Mrows, Dv, Dv, Dv, 0);
    // 5. rmsnorm2
    rmsnorm_kernel<<<Mrows, 256>>>(x1, n2w, h2);
    // 6. fused: z = h2 @ in_w^T ; gate = silu(h2 @ gate_w^T)
    gemm_tf32<<<dim3(1, 32), 256>>>(h2, in_w, gate_w, nullptr, zb, gateb, Mrows, 2*SCv, SCv, Dv, 1);
    // 7. Bi = z @ Bp_w^T  [4096,16]
    gemm64_kernel<<<dim3(1,64), 256>>>(zb, Bp_w, nullptr, nullptr, Bib, Mrows, STv, SCv, 0);
    // 8. Ci = z @ Cp_w^T
    gemm64_kernel<<<dim3(1,64), 256>>>(zb, Cp_w, nullptr, nullptr, Cib, Mrows, STv, SCv, 0);
    // 9. dt = softplus(z @ dt_w^T + dt_b)
    gemm64_kernel<<<dim3(1,64), 256>>>(zb, dt_w, dt_b, nullptr, dtb, Mrows, SCv, SCv, 2);
    // 10. parallel scan
    scan_phase1<<<8, 256>>>(dtb, zb, Bib, A_log);
    scan_phase2<<<8, 256>>>();
    scan_phase3<<<8, 256>>>(dtb, zb, Bib, Cib, gateb, A_log, yb);
    // 11. out = x1 + y @ out_w^T
    gemm_tf32<<<dim3(8, 32), 256>>>(yb, out_w, out_w, x1, out, nullptr, Mrows, Dv, Dv, SCv, 0);
}

// round 7
// speedup vs baseline: 2.7584x; 1.1178x over previous
#include <cuda_runtime.h>
#include <cuda_bf16.h>
#include <mma.h>
#include <math.h>
#include <cstdint>

using namespace nvcuda;

#define Bv 2
#define Tv 2048
#define Dv 1024
#define Hv 16
#define HDv 64
#define SCv 64
#define STv 16
#define Mrows (Bv*Tv)   // 4096
#define EPSR 1.1920929e-07f
#define CH 32           // scan chunks
#define TSTEP (Tv/CH)   // 64

// ---------------- scratch (device globals; no allocation allowed) ----------
__device__ float g_h   [Mrows*Dv];
__device__ float g_qkv [Mrows*3*Dv];
__device__ float g_attn[Mrows*Dv];
__device__ float g_x1  [Mrows*Dv];
__device__ float g_h2  [Mrows*Dv];
__device__ float g_z   [Mrows*SCv];
__device__ float g_gate[Mrows*SCv];
__device__ float g_Bi  [Mrows*STv];
__device__ float g_Ci  [Mrows*STv];
__device__ float g_dt  [Mrows*SCv];
__device__ float g_y   [Mrows*SCv];
__device__ float g_scanA[128*CH*16];
__device__ float g_scanB[128*CH*16];
__device__ float g_scanS[128*CH*16];
// rounded weight copies: qkv(3145728) o(1048576) in(65536) gate(65536) out(65536)
__device__ float g_wbuf[4390912];
#define WOFF_Q    0
#define WOFF_O    3145728
#define WOFF_IN   4194304
#define WOFF_GATE 4259840
#define WOFF_OUT  4325376

__device__ __forceinline__ uint32_t f2tf32(float x) {
    uint32_t r;
    asm("cvt.rna.tf32.f32 %0, %1;" : "=r"(r) : "f"(x));
    return r;
}
__device__ __forceinline__ float roundtf(float x) {
    return __uint_as_float(f2tf32(x));
}

__device__ __forceinline__ void mma_tf32(float& d0, float& d1, float& d2, float& d3,
                                         uint32_t a0, uint32_t a1, uint32_t a2, uint32_t a3,
                                         uint32_t b0, uint32_t b1) {
    asm volatile(
        "mma.sync.aligned.m16n8k8.row.col.f32.tf32.tf32.f32 "
        "{%0,%1,%2,%3}, {%4,%5,%6,%7}, {%8,%9}, {%0,%1,%2,%3};"
        : "+f"(d0), "+f"(d1), "+f"(d2), "+f"(d3)
        : "r"(a0), "r"(a1), "r"(a2), "r"(a3), "r"(b0), "r"(b1));
}

__device__ __forceinline__ void cp16(float* dst, const float* src) {
    uint32_t d = (uint32_t)__cvta_generic_to_shared(dst);
    asm volatile("cp.async.cg.shared.global [%0], [%1], 16;" :: "r"(d), "l"(src));
}

// ---------------- tf32 rounding of weights ----------------
__global__ __launch_bounds__(256) void round_tf32_kernel(
    const float* __restrict__ src, float* __restrict__ dst, int n4)
{
    int i = blockIdx.x*256 + threadIdx.x;
    if (i < n4) {
        float4 v = ((const float4*)src)[i];
        ((float4*)dst)[i] = make_float4(roundtf(v.x), roundtf(v.y), roundtf(v.z), roundtf(v.w));
    }
}

// ---------------- RMSNorm (tf32-rounded output) ----------------
__global__ __launch_bounds__(256) void rmsnorm_kernel(
    const float* __restrict__ x, const float* __restrict__ w, float* __restrict__ o)
{
    int row = blockIdx.x;
    const float4* xr = (const float4*)(x + (size_t)row*Dv);
    float4 v = xr[threadIdx.x];
    float ss = v.x*v.x + v.y*v.y + v.z*v.z + v.w*v.w;
    #pragma unroll
    for (int off=16; off; off>>=1) ss += __shfl_xor_sync(0xffffffffu, ss, off);
    __shared__ float sm[8];
    int wid = threadIdx.x>>5, lane = threadIdx.x&31;
    if (lane==0) sm[wid] = ss;
    __syncthreads();
    float tot = sm[0]+sm[1]+sm[2]+sm[3]+sm[4]+sm[5]+sm[6]+sm[7];
    float scale = rsqrtf(tot*(1.0f/Dv) + EPSR);
    const float4* wr = (const float4*)w;
    float4 wv = wr[threadIdx.x];
    float4 ov = make_float4(roundtf(v.x*scale*wv.x), roundtf(v.y*scale*wv.y),
                            roundtf(v.z*scale*wv.z), roundtf(v.w*scale*wv.w));
    ((float4*)(o + (size_t)row*Dv))[threadIdx.x] = ov;
}

// ---------------- TF32 GEMM v2: cp.async double-buffer, raw pre-rounded bits ----
// C = A[M,K] @ [W;W2][N,K]^T ; cols [0,nsplit)->C (ld nsplit), [nsplit,N)->C2 (silu if act2)
__global__ __launch_bounds__(256, 2) void gemm_tf32(
    const float* __restrict__ A, const float* __restrict__ W, const float* __restrict__ W2,
    const float* __restrict__ res, float* __restrict__ C, float* __restrict__ C2,
    int M, int N, int nsplit, int K, int act2)
{
    __shared__ float As[2][128*20];
    __shared__ float Ws[2][128*20];

    const int tid = threadIdx.x;
    const int w   = tid >> 5;
    const int wm  = w >> 1;
    const int wn  = w & 1;
    const int bm  = blockIdx.y * 128;
    const int bn  = blockIdx.x * 128;

    wmma::fragment<wmma::accumulator, 16, 16, 8, float> acc[2][4];
    #pragma unroll
    for (int i = 0; i < 2; i++)
        #pragma unroll
        for (int j = 0; j < 4; j++)
            wmma::fill_fragment(acc[i][j], 0.0f);

    const int lr  = tid >> 2;
    const int lc4 = (tid & 3) << 2;

    int r0 = bn + lr, r1 = bn + lr + 64;
    const float* wr0 = (r0 < nsplit) ? &W[(size_t)r0*K] : &W2[(size_t)(r0 - nsplit)*K];
    const float* wr1 = (r1 < nsplit) ? &W[(size_t)r1*K] : &W2[(size_t)(r1 - nsplit)*K];
    const float* ar0 = &A[(size_t)(bm + lr)*K];
    const float* ar1 = &A[(size_t)(bm + lr + 64)*K];

    // prologue: stage 0
    cp16(&As[0][lr*20 + lc4],      ar0 + lc4);
    cp16(&As[0][(lr+64)*20 + lc4], ar1 + lc4);
    cp16(&Ws[0][lr*20 + lc4],      wr0 + lc4);
    cp16(&Ws[0][(lr+64)*20 + lc4], wr1 + lc4);
    asm volatile("cp.async.commit_group;" ::);

    int s = 0;
    for (int k0 = 0; k0 < K; k0 += 16, s ^= 1) {
        if (k0 + 16 < K) {
            int kn = k0 + 16;
            cp16(&As[s^1][lr*20 + lc4],      ar0 + kn + lc4);
            cp16(&As[s^1][(lr+64)*20 + lc4], ar1 + kn + lc4);
            cp16(&Ws[s^1][lr*20 + lc4],      wr0 + kn + lc4);
            cp16(&Ws[s^1][(lr+64)*20 + lc4], wr1 + kn + lc4);
            asm volatile("cp.async.commit_group;" ::);
            asm volatile("cp.async.wait_group 1;" ::);
        } else {
            asm volatile("cp.async.wait_group 0;" ::);
        }
        __syncthreads();

        #pragma unroll
        for (int ks = 0; ks < 16; ks += 8) {
            wmma::fragment<wmma::matrix_a, 16, 16, 8, wmma::precision::tf32, wmma::row_major> fa[2];
            wmma::fragment<wmma::matrix_b, 16, 16, 8, wmma::precision::tf32, wmma::col_major> fb[4];
            #pragma unroll
            for (int i = 0; i < 2; i++)
                wmma::load_matrix_sync(fa[i], &As[s][(wm*32 + i*16)*20 + ks], 20);
            #pragma unroll
            for (int j = 0; j < 4; j++)
                wmma::load_matrix_sync(fb[j], &Ws[s][(wn*64 + j*16)*20 + ks], 20);
            #pragma unroll
            for (int i = 0; i < 2; i++)
                #pragma unroll
                for (int j = 0; j < 4; j++)
                    wmma::mma_sync(acc[i][j], fa[i], fb[j], acc[i][j]);
        }
        __syncthreads();
    }

    const int ld1 = nsplit;
    const int ld2 = N - nsplit;
    #pragma unroll
    for (int i = 0; i < 2; i++) {
        #pragma unroll
        for (int j = 0; j < 4; j++) {
            int row = bm + wm*32 + i*16;
            int col = bn + wn*64 + j*16;
            if (col < nsplit) {
                if (res) {
                    wmma::fragment<wmma::accumulator, 16, 16, 8, float> r;
                    wmma::load_matrix_sync(r, &res[(size_t)row * N + col], N, wmma::mem_row_major);
                    #pragma unroll
                    for (int e = 0; e < r.num_elements; e++) acc[i][j].x[e] += r.x[e];
                }
                wmma::store_matrix_sync(&C[(size_t)row * ld1 + col], acc[i][j], ld1, wmma::mem_row_major);
            } else {
                if (act2 == 1) {
                    #pragma unroll
                    for (int e = 0; e < acc[i][j].num_elements; e++) {
                        float v = acc[i][j].x[e];
                        acc[i][j].x[e] = v / (1.0f + __expf(-v));
                    }
                }
                wmma::store_matrix_sync(&C2[(size_t)row * ld2 + (col - nsplit)], acc[i][j], ld2, wmma::mem_row_major);
            }
        }
    }
}

// ---------------- fused Bi/Ci/dt: z[4096,64] @ {Bp,Cp,dt}^T ----------------
__global__ __launch_bounds__(256) void gemm_bcd(
    const float* __restrict__ z, const float* __restrict__ Bp_w,
    const float* __restrict__ Cp_w, const float* __restrict__ dt_w,
    const float* __restrict__ dt_b,
    float* __restrict__ Bi, float* __restrict__ Ci, float* __restrict__ dt)
{
    __shared__ float Zs[64*68];
    __shared__ float Wt[64*100];    // [k][outcol 0..95]
    const int tid = threadIdx.x;
    const int bm = blockIdx.x*64;

    for (int t = tid; t < 1024; t += 256) {
        int row = t >> 4, k4 = (t & 15) << 2;
        float4 v = *(const float4*)&z[(size_t)(bm + row)*SCv + k4];
        Zs[row*68 + k4 + 0] = v.x; Zs[row*68 + k4 + 1] = v.y;
        Zs[row*68 + k4 + 2] = v.z; Zs[row*68 + k4 + 3] = v.w;
    }
    for (int idx = tid; idx < 96*64; idx += 256) {
        int r = idx >> 6, c = idx & 63;
        float v = (r < 16) ? Bp_w[r*SCv + c] : (r < 32) ? Cp_w[(r-16)*SCv + c] : dt_w[(r-32)*SCv + c];
        Wt[c*100 + r] = v;
    }
    __syncthreads();

    const int ty = tid >> 4, tx = tid & 15;
    float acc[4][6];
    #pragma unroll
    for (int i=0;i<4;i++)
        #pragma unroll
        for (int j=0;j<6;j++) acc[i][j] = 0.f;

    #pragma unroll 4
    for (int k = 0; k < 64; k++) {
        float a[4], bb[6];
        #pragma unroll
        for (int i=0;i<4;i++) a[i] = Zs[(ty*4+i)*68 + k];
        #pragma unroll
        for (int j=0;j<6;j++) bb[j] = Wt[k*100 + tx*6 + j];
        #pragma unroll
        for (int i=0;i<4;i++)
            #pragma unroll
            for (int j=0;j<6;j++) acc[i][j] = fmaf(a[i], bb[j], acc[i][j]);
    }

    #pragma unroll
    for (int i=0;i<4;i++) {
        int row = bm + ty*4 + i;
        #pragma unroll
        for (int j=0;j<6;j++) {
            int c = tx*6 + j;
            float v = acc[i][j];
            if (c < 16) {
                Bi[(size_t)row*STv + c] = v;
            } else if (c < 32) {
                Ci[(size_t)row*STv + (c-16)] = v;
            } else {
                v += dt_b[c-32];
                dt[(size_t)row*SCv + (c-32)] = (v > 20.f) ? v : log1pf(__expf(v));
            }
        }
    }
}

// ---------------- Flash attention v3 ----------------
#define KS_LD 68
#define VS_LD 72
#define STAGEF (64*KS_LD + 64*VS_LD)
__global__ __launch_bounds__(256, 2) void attn_mma_kernel(
    const float* __restrict__ qkv, float* __restrict__ out)
{
    extern __shared__ float smf[];

    const int tid = threadIdx.x;
    const int w   = tid >> 5;
    const int l   = tid & 31;
    const int g   = l >> 2;
    const int q   = l & 3;
    const int qb  = (int)gridDim.x - 1 - (int)blockIdx.x;
    const int h = blockIdx.y, b = blockIdx.z;
    const int qrow0 = qb*128 + w*16;

    uint32_t qa[8][4];
    {
        const float* Qbase = qkv + ((size_t)(b*Tv + qrow0))*(3*Dv) + h*HDv;
        #pragma unroll
        for (int kc = 0; kc < 8; kc++) {
            qa[kc][0] = f2tf32(0.125f * Qbase[(size_t)(g    )*(3*Dv) + kc*8 + q    ]);
            qa[kc][1] = f2tf32(0.125f * Qbase[(size_t)(g + 8)*(3*Dv) + kc*8 + q    ]);
            qa[kc][2] = f2tf32(0.125f * Qbase[(size_t)(g    )*(3*Dv) + kc*8 + q + 4]);
            qa[kc][3] = f2tf32(0.125f * Qbase[(size_t)(g + 8)*(3*Dv) + kc*8 + q + 4]);
        }
    }

    float o[8][4];
    #pragma unroll
    for (int nc = 0; nc < 8; nc++)
        #pragma unroll
        for (int e = 0; e < 4; e++) o[nc][e] = 0.f;
    float mA = -1e30f, mB = -1e30f, lA = 0.f, lB = 0.f;

    const int ntiles = 2*qb + 2;

    {
        float* Kb = smf;
        float* Vb = Kb + 64*KS_LD;
        #pragma unroll
        for (int i = 0; i < 4; i++) {
            int idx = tid + i*256;
            int r = idx >> 4, c4 = (idx & 15) << 2;
            const float* src = qkv + ((size_t)(b*Tv + r))*(3*Dv) + h*HDv + c4;
            cp16(Kb + r*KS_LD + c4, src + Dv);
            cp16(Vb + r*VS_LD + c4, src + 2*Dv);
        }
        asm volatile("cp.async.commit_group;" ::);
    }

    for (int kt = 0; kt < ntiles; kt++) {
        const int kbase = kt*64;
        if (kt + 1 < ntiles) {
            float* Kb = smf + ((kt+1)&1)*STAGEF;
            float* Vb = Kb + 64*KS_LD;
            #pragma unroll
            for (int i = 0; i < 4; i++) {
                int idx = tid + i*256;
                int r = idx >> 4, c4 = (idx & 15) << 2;
                const float* src = qkv + ((size_t)(b*Tv + kbase + 64 + r))*(3*Dv) + h*HDv + c4;
                cp16(Kb + r*KS_LD + c4, src + Dv);
                cp16(Vb + r*VS_LD + c4, src + 2*Dv);
            }
            asm volatile("cp.async.commit_group;" ::);
            asm volatile("cp.async.wait_group 1;" ::);
        } else {
            asm volatile("cp.async.wait_group 0;" ::);
        }
        __syncthreads();

        const float* Kb = smf + (kt&1)*STAGEF;
        const float* Vb = Kb + 64*KS_LD;

        float s[8][4];
        #pragma unroll
        for (int nc = 0; nc < 8; nc++) {
            s[nc][0] = 0.f; s[nc][1] = 0.f; s[nc][2] = 0.f; s[nc][3] = 0.f;
            #pragma unroll
            for (int kc = 0; kc < 8; kc++) {
                uint32_t kb0 = __float_as_uint(Kb[(nc*8 + g)*KS_LD + kc*8 + q]);
                uint32_t kb1 = __float_as_uint(Kb[(nc*8 + g)*KS_LD + kc*8 + q + 4]);
                mma_tf32(s[nc][0], s[nc][1], s[nc][2], s[nc][3],
                         qa[kc][0], qa[kc][1], qa[kc][2], qa[kc][3], kb0, kb1);
            }
        }

        if (kbase + 63 > qrow0) {
            int rowA = qrow0 + g, rowB = qrow0 + g + 8;
            #pragma unroll
            for (int nc = 0; nc < 8; nc++) {
                int c0 = kbase + nc*8 + 2*q, c1 = c0 + 1;
                if (c0 > rowA) s[nc][0] = -1e30f;
                if (c1 > rowA) s[nc][1] = -1e30f;
                if (c0 > rowB) s[nc][2] = -1e30f;
                if (c1 > rowB) s[nc][3] = -1e30f;
            }
        }

        float rmA = -1e30f, rmB = -1e30f;
        #pragma unroll
        for (int nc = 0; nc < 8; nc++) {
            rmA = fmaxf(rmA, fmaxf(s[nc][0], s[nc][1]));
            rmB = fmaxf(rmB, fmaxf(s[nc][2], s[nc][3]));
        }
        rmA = fmaxf(rmA, __shfl_xor_sync(0xffffffffu, rmA, 1));
        rmA = fmaxf(rmA, __shfl_xor_sync(0xffffffffu, rmA, 2));
        rmB = fmaxf(rmB, __shfl_xor_sync(0xffffffffu, rmB, 1));
        rmB = fmaxf(rmB, __shfl_xor_sync(0xffffffffu, rmB, 2));
        float mnA = fmaxf(mA, rmA), mnB = fmaxf(mB, rmB);
        float corrA = __expf(mA - mnA), corrB = __expf(mB - mnB);
        mA = mnA; mB = mnB;

        float rsA = 0.f, rsB = 0.f;
        #pragma unroll
        for (int nc = 0; nc < 8; nc++) {
            s[nc][0] = __expf(s[nc][0] - mnA);
            s[nc][1] = __expf(s[nc][1] - mnA);
            s[nc][2] = __expf(s[nc][2] - mnB);
            s[nc][3] = __expf(s[nc][3] - mnB);
            rsA += s[nc][0] + s[nc][1];
            rsB += s[nc][2] + s[nc][3];
        }
        rsA += __shfl_xor_sync(0xffffffffu, rsA, 1);
        rsA += __shfl_xor_sync(0xffffffffu, rsA, 2);
        rsB += __shfl_xor_sync(0xffffffffu, rsB, 1);
        rsB += __shfl_xor_sync(0xffffffffu, rsB, 2);
        lA = lA*corrA + rsA;
        lB = lB*corrB + rsB;

        #pragma unroll
        for (int nc = 0; nc < 8; nc++) {
            o[nc][0] *= corrA; o[nc][1] *= corrA;
            o[nc][2] *= corrB; o[nc][3] *= corrB;
        }

        const int src0 = (l & 28) | (q >> 1);
        const bool odd = (q & 1);
        #pragma unroll
        for (int kc = 0; kc < 8; kc++) {
            float e0 = __shfl_sync(0xffffffffu, s[kc][0], src0);
            float e1 = __shfl_sync(0xffffffffu, s[kc][1], src0);
            float e2 = __shfl_sync(0xffffffffu, s[kc][2], src0);
            float e3 = __shfl_sync(0xffffffffu, s[kc][3], src0);
            float f0 = __shfl_sync(0xffffffffu, s[kc][0], src0 + 2);
            float f1 = __shfl_sync(0xffffffffu, s[kc][1], src0 + 2);
            float f2 = __shfl_sync(0xffffffffu, s[kc][2], src0 + 2);
            float f3 = __shfl_sync(0xffffffffu, s[kc][3], src0 + 2);
            uint32_t pa0 = f2tf32(odd ? e1 : e0);
            uint32_t pa1 = f2tf32(odd ? e3 : e2);
            uint32_t pa2 = f2tf32(odd ? f1 : f0);
            uint32_t pa3 = f2tf32(odd ? f3 : f2);
            #pragma unroll
            for (int nc = 0; nc < 8; nc++) {
                uint32_t vb0 = __float_as_uint(Vb[(kc*8 + q    )*VS_LD + nc*8 + g]);
                uint32_t vb1 = __float_as_uint(Vb[(kc*8 + q + 4)*VS_LD + nc*8 + g]);
                mma_tf32(o[nc][0], o[nc][1], o[nc][2], o[nc][3],
                         pa0, pa1, pa2, pa3, vb0, vb1);
            }
        }
        __syncthreads();
    }

    float invA = 1.f / lA, invB = 1.f / lB;
    float* obaseA = out + ((size_t)(b*Tv + qrow0 + g    ))*Dv + h*HDv;
    float* obaseB = out + ((size_t)(b*Tv + qrow0 + g + 8))*Dv + h*HDv;
    #pragma unroll
    for (int nc = 0; nc < 8; nc++) {
        int c = nc*8 + 2*q;
        *(float2*)&obaseA[c] = make_float2(roundtf(o[nc][0]*invA), roundtf(o[nc][1]*invA));
        *(float2*)&obaseB[c] = make_float2(roundtf(o[nc][2]*invB), roundtf(o[nc][3]*invB));
    }
}

// ---------------- Parallel selective scan (CH=32 chunks) ----------------
__global__ __launch_bounds__(256) void scan_phase1(
    const float* __restrict__ dt, const float* __restrict__ z,
    const float* __restrict__ Bi, const float* __restrict__ A_log)
{
    int gth = blockIdx.x*256 + threadIdx.x;     // 0..4095
    int chan = gth & 127, chunk = gth >> 7;
    int b = chan >> 6, sc = chan & 63;
    float A[16];
    #pragma unroll
    for (int st = 0; st < 16; st++) A[st] = -__expf(A_log[sc*STv + st]);
    float aP[16], bP[16];
    #pragma unroll
    for (int st = 0; st < 16; st++) { aP[st] = 1.f; bP[st] = 0.f; }
    int t0 = chunk*TSTEP;
    const float* dtp = dt + ((size_t)b*Tv + t0)*SCv + sc;
    const float* zp  = z  + ((size_t)b*Tv + t0)*SCv + sc;
    const float* Bp  = Bi + ((size_t)b*Tv + t0)*STv;
    for (int tt = 0; tt < TSTEP; tt++) {
        float dtc = dtp[(size_t)tt*SCv];
        float zc  = zp [(size_t)tt*SCv];
        float dz  = dtc*zc;
        float4 B0 = *(const float4*)&Bp[tt*STv + 0];
        float4 B1 = *(const float4*)&Bp[tt*STv + 4];
        float4 B2 = *(const float4*)&Bp[tt*STv + 8];
        float4 B3 = *(const float4*)&Bp[tt*STv + 12];
        float Bvv[16] = {B0.x,B0.y,B0.z,B0.w, B1.x,B1.y,B1.z,B1.w,
                         B2.x,B2.y,B2.z,B2.w, B3.x,B3.y,B3.z,B3.w};
        #pragma unroll
        for (int st = 0; st < 16; st++) {
            float ab = fmaf(dtc, A[st], 1.f);
            aP[st] *= ab;
            bP[st] = fmaf(ab, bP[st], dz*Bvv[st]);
        }
    }
    int base = (chan*CH + chunk)*16;
    #pragma unroll
    for (int st = 0; st < 16; st++) { g_scanA[base+st] = aP[st]; g_scanB[base+st] = bP[st]; }
}

__global__ __launch_bounds__(256) void scan_phase2()
{
    int gth = blockIdx.x*256 + threadIdx.x;     // 0..2047
    int chan = gth >> 4, st = gth & 15;
    float s = 0.f;
    #pragma unroll
    for (int ch = 0; ch < CH; ch++) {
        int idx = (chan*CH + ch)*16 + st;
        g_scanS[idx] = s;
        s = fmaf(g_scanA[idx], s, g_scanB[idx]);
    }
}

__global__ __launch_bounds__(256) void scan_phase3(
    const float* __restrict__ dt, const float* __restrict__ z,
    const float* __restrict__ Bi, const float* __restrict__ Ci,
    const float* __restrict__ gate, const float* __restrict__ A_log,
    float* __restrict__ y)
{
    int gth = blockIdx.x*256 + threadIdx.x;
    int chan = gth & 127, chunk = gth >> 7;
    int b = chan >> 6, sc = chan & 63;
    float A[16];
    #pragma unroll
    for (int st = 0; st < 16; st++) A[st] = -__expf(A_log[sc*STv + st]);
    float state[16];
    {
        int base = (chan*CH + chunk)*16;
        #pragma unroll
        for (int st = 0; st < 16; st++) state[st] = g_scanS[base+st];
    }
    int t0 = chunk*TSTEP;
    const float* dtp = dt   + ((size_t)b*Tv + t0)*SCv + sc;
    const float* zp  = z    + ((size_t)b*Tv + t0)*SCv + sc;
    const float* gp  = gate + ((size_t)b*Tv + t0)*SCv + sc;
    const float* Bp  = Bi + ((size_t)b*Tv + t0)*STv;
    const float* Cp  = Ci + ((size_t)b*Tv + t0)*STv;
    float* yp = y + ((size_t)b*Tv + t0)*SCv + sc;
    for (int tt = 0; tt < TSTEP; tt++) {
        float dtc = dtp[(size_t)tt*SCv];
        float zc  = zp [(size_t)tt*SCv];
        float dz  = dtc*zc;
        float4 B0 = *(const float4*)&Bp[tt*STv + 0];
        float4 B1 = *(const float4*)&Bp[tt*STv + 4];
        float4 B2 = *(const float4*)&Bp[tt*STv + 8];
        float4 B3 = *(const float4*)&Bp[tt*STv + 12];
        float4 C0 = *(const float4*)&Cp[tt*STv + 0];
        float4 C1 = *(const float4*)&Cp[tt*STv + 4];
        float4 C2 = *(const float4*)&Cp[tt*STv + 8];
        float4 C3 = *(const float4*)&Cp[tt*STv + 12];
        float Bvv[16] = {B0.x,B0.y,B0.z,B0.w, B1.x,B1.y,B1.z,B1.w,
                         B2.x,B2.y,B2.z,B2.w, B3.x,B3.y,B3.z,B3.w};
        float Cvv[16] = {C0.x,C0.y,C0.z,C0.w, C1.x,C1.y,C1.z,C1.w,
                         C2.x,C2.y,C2.z,C2.w, C3.x,C3.y,C3.z,C3.w};
        float p0 = 0.f, p1 = 0.f, p2 = 0.f, p3 = 0.f;
        #pragma unroll
        for (int st = 0; st < 16; st += 4) {
            float ab;
            ab = fmaf(dtc, A[st+0], 1.f); state[st+0] = fmaf(ab, state[st+0], dz*Bvv[st+0]); p0 = fmaf(state[st+0], Cvv[st+0], p0);
            ab = fmaf(dtc, A[st+1], 1.f); state[st+1] = fmaf(ab, state[st+1], dz*Bvv[st+1]); p1 = fmaf(state[st+1], Cvv[st+1], p1);
            ab = fmaf(dtc, A[st+2], 1.f); state[st+2] = fmaf(ab, state[st+2], dz*Bvv[st+2]); p2 = fmaf(state[st+2], Cvv[st+2], p2);
            ab = fmaf(dtc, A[st+3], 1.f); state[st+3] = fmaf(ab, state[st+3], dz*Bvv[st+3]); p3 = fmaf(state[st+3], Cvv[st+3], p3);
        }
        float p = (p0 + p1) + (p2 + p3);
        yp[(size_t)tt*SCv] = roundtf(p * gp[(size_t)tt*SCv]);
    }
}

// ---------------- launch ----------------
extern "C" void kernel_launch(void* const* d_in, const int* in_sizes, int n_in,
                              void* d_out, int out_size)
{
    const float* x      = (const float*)d_in[0];
    const float* qkv_w  = (const float*)d_in[1];
    const float* o_w    = (const float*)d_in[2];
    const float* n1w    = (const float*)d_in[3];
    const float* n2w    = (const float*)d_in[4];
    const float* in_w   = (const float*)d_in[5];
    const float* out_w  = (const float*)d_in[6];
    const float* A_log  = (const float*)d_in[7];
    const float* Bp_w   = (const float*)d_in[8];
    const float* Cp_w   = (const float*)d_in[9];
    const float* dt_w   = (const float*)d_in[10];
    const float* dt_b   = (const float*)d_in[11];
    const float* gate_w = (const float*)d_in[12];
    float* out = (float*)d_out;

    float *h,*qkv,*attn,*x1,*h2,*zb,*gateb,*Bib,*Cib,*dtb,*yb,*wb;
    cudaGetSymbolAddress((void**)&h,    g_h);
    cudaGetSymbolAddress((void**)&qkv,  g_qkv);
    cudaGetSymbolAddress((void**)&attn, g_attn);
    cudaGetSymbolAddress((void**)&x1,   g_x1);
    cudaGetSymbolAddress((void**)&h2,   g_h2);
    cudaGetSymbolAddress((void**)&zb,   g_z);
    cudaGetSymbolAddress((void**)&gateb,g_gate);
    cudaGetSymbolAddress((void**)&Bib,  g_Bi);
    cudaGetSymbolAddress((void**)&Cib,  g_Ci);
    cudaGetSymbolAddress((void**)&dtb,  g_dt);
    cudaGetSymbolAddress((void**)&yb,   g_y);
    cudaGetSymbolAddress((void**)&wb,   g_wbuf);

    float* wq    = wb + WOFF_Q;
    float* wo    = wb + WOFF_O;
    float* win   = wb + WOFF_IN;
    float* wgate = wb + WOFF_GATE;
    float* wout  = wb + WOFF_OUT;

    const int attn_smem = 2*STAGEF*4;
    cudaFuncSetAttribute(attn_mma_kernel, cudaFuncAttributeMaxDynamicSharedMemorySize, attn_smem);

    // 0. round weights to tf32 (rna) once per launch
    round_tf32_kernel<<<3072, 256>>>(qkv_w,  wq,    3145728/4);
    round_tf32_kernel<<<1024, 256>>>(o_w,    wo,    1048576/4);
    round_tf32_kernel<<<64,   256>>>(in_w,   win,   65536/4);
    round_tf32_kernel<<<64,   256>>>(gate_w, wgate, 65536/4);
    round_tf32_kernel<<<64,   256>>>(out_w,  wout,  65536/4);

    // 1. rmsnorm1 (rounded out)
    rmsnorm_kernel<<<Mrows, 256>>>(x, n1w, h);
    // 2. qkv = h @ qkv_w^T
    gemm_tf32<<<dim3(24, 32), 256>>>(h, wq, wq, nullptr, qkv, nullptr, Mrows, 3*Dv, 3*Dv, Dv, 0);
    // 3. attention (rounded out)
    attn_mma_kernel<<<dim3(Tv/128, Hv, Bv), 256, attn_smem>>>(qkv, attn);
    // 4. x1 = x + attn @ o_w^T
    gemm_tf32<<<dim3(8, 32), 256>>>(attn, wo, wo, x, x1, nullptr, Mrows, Dv, Dv, Dv, 0);
    // 5. rmsnorm2 (rounded out)
    rmsnorm_kernel<<<Mrows, 256>>>(x1, n2w, h2);
    // 6. fused z / gate
    gemm_tf32<<<dim3(1, 32), 256>>>(h2, win, wgate, nullptr, zb, gateb, Mrows, 2*SCv, SCv, Dv, 1);
    // 7. fused Bi/Ci/dt
    gemm_bcd<<<64, 256>>>(zb, Bp_w, Cp_w, dt_w, dt_b, Bib, Cib, dtb);
    // 8. parallel scan (y rounded)
    scan_phase1<<<16, 256>>>(dtb, zb, Bib, A_log);
    scan_phase2<<<8, 256>>>();
    scan_phase3<<<16, 256>>>(dtb, zb, Bib, Cib, gateb, A_log, yb);
    // 9. out = x1 + y @ out_w^T
    gemm_tf32<<<dim3(8, 32), 256>>>(yb, wout, wout, x1, out, nullptr, Mrows, Dv, Dv, SCv, 0);
}

// round 8
// speedup vs baseline: 5.8863x; 2.1340x over previous
#include <cuda_runtime.h>
#include <cuda_bf16.h>
#include <math.h>
#include <cstdint>

#define Bv 2
#define Tv 2048
#define Dv 1024
#define Hv 16
#define HDv 64
#define SCv 64
#define STv 16
#define Mrows (Bv*Tv)   // 4096
#define EPSR 1.1920929e-07f
#define CH 32
#define TSTEP (Tv/CH)   // 64

// ---------------- scratch (device globals) ----------------
__device__ __nv_bfloat16 g_h   [Mrows*Dv];        // rmsnorm1 out
__device__ __nv_bfloat16 g_qk  [Mrows*2*Dv];      // Q,K (cols 0..2047 of qkv)
__device__ __nv_bfloat16 g_vT  [Dv*Mrows];        // V transposed: [h*64+dim][token]
__device__ __nv_bfloat16 g_attn[Mrows*Dv];
__device__ float         g_x1  [Mrows*Dv];
__device__ __nv_bfloat16 g_h2  [Mrows*Dv];
__device__ float g_z   [Mrows*SCv];
__device__ float g_gate[Mrows*SCv];
__device__ float g_Bi  [Mrows*STv];
__device__ float g_Ci  [Mrows*STv];
__device__ float g_dt  [Mrows*SCv];
__device__ __nv_bfloat16 g_y [Mrows*SCv];
__device__ float g_scanA[128*CH*16];
__device__ float g_scanB[128*CH*16];
__device__ float g_scanS[128*CH*16];
// bf16 weights: qkv(3145728) o(1048576) zgate(131072) out(65536)
__device__ __nv_bfloat16 g_wq  [3*Dv*Dv];
__device__ __nv_bfloat16 g_wo  [Dv*Dv];
__device__ __nv_bfloat16 g_wzg [2*SCv*Dv];
__device__ __nv_bfloat16 g_wout[Dv*SCv];

__device__ __forceinline__ uint32_t packbf(float a, float b) {
    __nv_bfloat162 t = __floats2bfloat162_rn(a, b);
    return *reinterpret_cast<uint32_t*>(&t);
}
__device__ __forceinline__ uint32_t mulbf2(uint32_t v, __nv_bfloat162 s) {
    __nv_bfloat162 t = *reinterpret_cast<__nv_bfloat162*>(&v);
    t = __hmul2(t, s);
    return *reinterpret_cast<uint32_t*>(&t);
}

__device__ __forceinline__ void mma_bf16(float& d0, float& d1, float& d2, float& d3,
                                         uint32_t a0, uint32_t a1, uint32_t a2, uint32_t a3,
                                         uint32_t b0, uint32_t b1) {
    asm volatile(
        "mma.sync.aligned.m16n8k16.row.col.f32.bf16.bf16.f32 "
        "{%0,%1,%2,%3}, {%4,%5,%6,%7}, {%8,%9}, {%0,%1,%2,%3};"
        : "+f"(d0), "+f"(d1), "+f"(d2), "+f"(d3)
        : "r"(a0), "r"(a1), "r"(a2), "r"(a3), "r"(b0), "r"(b1));
}

__device__ __forceinline__ void cp16h(__nv_bfloat16* dst, const __nv_bfloat16* src) {
    uint32_t d = (uint32_t)__cvta_generic_to_shared(dst);
    asm volatile("cp.async.cg.shared.global [%0], [%1], 16;" :: "r"(d), "l"(src));
}

// ---------------- f32 -> bf16 convert ----------------
__global__ __launch_bounds__(256) void f32_to_bf16(
    const float* __restrict__ src, __nv_bfloat16* __restrict__ dst, int n2)
{
    int i = blockIdx.x*256 + threadIdx.x;
    if (i < n2) {
        float2 v = ((const float2*)src)[i];
        ((__nv_bfloat162*)dst)[i] = __floats2bfloat162_rn(v.x, v.y);
    }
}

// ---------------- RMSNorm -> bf16 ----------------
__global__ __launch_bounds__(256) void rmsnorm_kernel(
    const float* __restrict__ x, const float* __restrict__ w, __nv_bfloat16* __restrict__ o)
{
    int row = blockIdx.x;
    const float4* xr = (const float4*)(x + (size_t)row*Dv);
    float4 v = xr[threadIdx.x];
    float ss = v.x*v.x + v.y*v.y + v.z*v.z + v.w*v.w;
    #pragma unroll
    for (int off=16; off; off>>=1) ss += __shfl_xor_sync(0xffffffffu, ss, off);
    __shared__ float sm[8];
    int wid = threadIdx.x>>5, lane = threadIdx.x&31;
    if (lane==0) sm[wid] = ss;
    __syncthreads();
    float tot = sm[0]+sm[1]+sm[2]+sm[3]+sm[4]+sm[5]+sm[6]+sm[7];
    float scale = rsqrtf(tot*(1.0f/Dv) + EPSR);
    const float4* wr = (const float4*)w;
    float4 wv = wr[threadIdx.x];
    uint2 st = make_uint2(packbf(v.x*scale*wv.x, v.y*scale*wv.y),
                          packbf(v.z*scale*wv.z, v.w*scale*wv.w));
    *(uint2*)&o[(size_t)row*Dv + threadIdx.x*4] = st;
}

// ---------------- bf16 GEMM: C = A[M,K] @ W[N,K]^T (raw mma m16n8k16) --------
// modes (per column range, split at nsplit):
//   0 = fp32 store; 1 = fp32 + res (res ld = N); 2 = bf16 store; 3 = bf16 transposed
//   (C2[(col-nsplit)*M + row]); 4 = fp32 silu
#define GLDH 40
#define GLDW 20
__global__ __launch_bounds__(256, 2) void gemm_bf16(
    const __nv_bfloat16* __restrict__ A, const __nv_bfloat16* __restrict__ W,
    const float* __restrict__ res, void* __restrict__ Cp, void* __restrict__ C2p,
    int M, int N, int nsplit, int K, int mode1, int mode2, int ld1, int ld2)
{
    __shared__ __nv_bfloat16 As[2][128*GLDH];
    __shared__ __nv_bfloat16 Ws[2][128*GLDH];

    const int tid = threadIdx.x;
    const int w   = tid >> 5;
    const int l   = tid & 31;
    const int g   = l >> 2;
    const int q   = l & 3;
    const int wm  = w >> 1;
    const int wn  = w & 1;
    const int bm  = blockIdx.y * 128;
    const int bn  = blockIdx.x * 128;

    float c[2][8][4];
    #pragma unroll
    for (int i=0;i<2;i++)
        #pragma unroll
        for (int nj=0;nj<8;nj++)
            #pragma unroll
            for (int e=0;e<4;e++) c[i][nj][e] = 0.f;

    // prologue: stage 0
    #pragma unroll
    for (int i = 0; i < 2; i++) {
        int idx = tid + i*256;            // 0..511
        int row = idx >> 2, seg = (idx & 3) * 8;
        cp16h(&As[0][row*GLDH + seg], A + (size_t)(bm + row)*K + seg);
        cp16h(&Ws[0][row*GLDH + seg], W + (size_t)(bn + row)*K + seg);
    }
    asm volatile("cp.async.commit_group;" ::);

    int s = 0;
    for (int k0 = 0; k0 < K; k0 += 32, s ^= 1) {
        if (k0 + 32 < K) {
            int kn = k0 + 32;
            #pragma unroll
            for (int i = 0; i < 2; i++) {
                int idx = tid + i*256;
                int row = idx >> 2, seg = (idx & 3) * 8;
                cp16h(&As[s^1][row*GLDH + seg], A + (size_t)(bm + row)*K + kn + seg);
                cp16h(&Ws[s^1][row*GLDH + seg], W + (size_t)(bn + row)*K + kn + seg);
            }
            asm volatile("cp.async.commit_group;" ::);
            asm volatile("cp.async.wait_group 1;" ::);
        } else {
            asm volatile("cp.async.wait_group 0;" ::);
        }
        __syncthreads();

        const uint32_t* Aw = (const uint32_t*)As[s];
        const uint32_t* Ww = (const uint32_t*)Ws[s];
        #pragma unroll
        for (int kc2 = 0; kc2 < 2; kc2++) {
            uint32_t a[2][4], bf[8][2];
            #pragma unroll
            for (int i = 0; i < 2; i++) {
                int base = wm*32 + i*16;
                a[i][0] = Aw[(base + g    )*GLDW + kc2*8 + q    ];
                a[i][1] = Aw[(base + g + 8)*GLDW + kc2*8 + q    ];
                a[i][2] = Aw[(base + g    )*GLDW + kc2*8 + q + 4];
                a[i][3] = Aw[(base + g + 8)*GLDW + kc2*8 + q + 4];
            }
            #pragma unroll
            for (int nj = 0; nj < 8; nj++) {
                int col = wn*64 + nj*8 + g;
                bf[nj][0] = Ww[col*GLDW + kc2*8 + q    ];
                bf[nj][1] = Ww[col*GLDW + kc2*8 + q + 4];
            }
            #pragma unroll
            for (int i = 0; i < 2; i++)
                #pragma unroll
                for (int nj = 0; nj < 8; nj++)
                    mma_bf16(c[i][nj][0], c[i][nj][1], c[i][nj][2], c[i][nj][3],
                             a[i][0], a[i][1], a[i][2], a[i][3], bf[nj][0], bf[nj][1]);
        }
        __syncthreads();
    }

    // epilogue
    #pragma unroll
    for (int i = 0; i < 2; i++) {
        #pragma unroll
        for (int nj = 0; nj < 8; nj++) {
            int row0 = bm + wm*32 + i*16 + g;
            int row1 = row0 + 8;
            int col  = bn + wn*64 + nj*8 + 2*q;
            bool first = (col < nsplit);
            int mode = first ? mode1 : mode2;
            float v0 = c[i][nj][0], v1 = c[i][nj][1], v2 = c[i][nj][2], v3 = c[i][nj][3];
            if (mode == 1) {
                v0 += res[(size_t)row0*N + col];
                v1 += res[(size_t)row0*N + col + 1];
                v2 += res[(size_t)row1*N + col];
                v3 += res[(size_t)row1*N + col + 1];
            } else if (mode == 4) {
                v0 = v0 / (1.f + __expf(-v0));
                v1 = v1 / (1.f + __expf(-v1));
                v2 = v2 / (1.f + __expf(-v2));
                v3 = v3 / (1.f + __expf(-v3));
            }
            if (mode == 2) {
                __nv_bfloat16* O = (__nv_bfloat16*)(first ? Cp : C2p);
                int ld = first ? ld1 : ld2;
                int cc = first ? col : col - nsplit;
                *(uint32_t*)&O[(size_t)row0*ld + cc] = packbf(v0, v1);
                *(uint32_t*)&O[(size_t)row1*ld + cc] = packbf(v2, v3);
            } else if (mode == 3) {
                __nv_bfloat16* O = (__nv_bfloat16*)C2p;
                int cc = col - nsplit;
                O[(size_t)cc*M + row0]     = __float2bfloat16(v0);
                O[(size_t)(cc+1)*M + row0] = __float2bfloat16(v1);
                O[(size_t)cc*M + row1]     = __float2bfloat16(v2);
                O[(size_t)(cc+1)*M + row1] = __float2bfloat16(v3);
            } else {
                float* O = (float*)(first ? Cp : C2p);
                int ld = first ? ld1 : ld2;
                int cc = first ? col : col - nsplit;
                *(float2*)&O[(size_t)row0*ld + cc] = make_float2(v0, v1);
                *(float2*)&O[(size_t)row1*ld + cc] = make_float2(v2, v3);
            }
        }
    }
}

// ---------------- fused Bi/Ci/dt (fp32) ----------------
__global__ __launch_bounds__(256) void gemm_bcd(
    const float* __restrict__ z, const float* __restrict__ Bp_w,
    const float* __restrict__ Cp_w, const float* __restrict__ dt_w,
    const float* __restrict__ dt_b,
    float* __restrict__ Bi, float* __restrict__ Ci, float* __restrict__ dt)
{
    __shared__ float Zs[64*68];
    __shared__ float Wt[64*100];
    const int tid = threadIdx.x;
    const int bm = blockIdx.x*64;

    for (int t = tid; t < 1024; t += 256) {
        int row = t >> 4, k4 = (t & 15) << 2;
        float4 v = *(const float4*)&z[(size_t)(bm + row)*SCv + k4];
        Zs[row*68 + k4 + 0] = v.x; Zs[row*68 + k4 + 1] = v.y;
        Zs[row*68 + k4 + 2] = v.z; Zs[row*68 + k4 + 3] = v.w;
    }
    for (int idx = tid; idx < 96*64; idx += 256) {
        int r = idx >> 6, c = idx & 63;
        float v = (r < 16) ? Bp_w[r*SCv + c] : (r < 32) ? Cp_w[(r-16)*SCv + c] : dt_w[(r-32)*SCv + c];
        Wt[c*100 + r] = v;
    }
    __syncthreads();

    const int ty = tid >> 4, tx = tid & 15;
    float acc[4][6];
    #pragma unroll
    for (int i=0;i<4;i++)
        #pragma unroll
        for (int j=0;j<6;j++) acc[i][j] = 0.f;

    #pragma unroll 4
    for (int k = 0; k < 64; k++) {
        float a[4], bb[6];
        #pragma unroll
        for (int i=0;i<4;i++) a[i] = Zs[(ty*4+i)*68 + k];
        #pragma unroll
        for (int j=0;j<6;j++) bb[j] = Wt[k*100 + tx*6 + j];
        #pragma unroll
        for (int i=0;i<4;i++)
            #pragma unroll
            for (int j=0;j<6;j++) acc[i][j] = fmaf(a[i], bb[j], acc[i][j]);
    }

    #pragma unroll
    for (int i=0;i<4;i++) {
        int row = bm + ty*4 + i;
        #pragma unroll
        for (int j=0;j<6;j++) {
            int c = tx*6 + j;
            float v = acc[i][j];
            if (c < 16) {
                Bi[(size_t)row*STv + c] = v;
            } else if (c < 32) {
                Ci[(size_t)row*STv + (c-16)] = v;
            } else {
                v += dt_b[c-32];
                dt[(size_t)row*SCv + (c-32)] = (v > 20.f) ? v : log1pf(__expf(v));
            }
        }
    }
}

// ---------------- Flash attention v4: bf16 m16n8k16, no shuffles for P -------
#define KS_LDH 72                    // halves per K row (64 data + 8 pad)
#define STAGEH (64*KS_LDH*2)         // K + V per stage, in halves
__global__ __launch_bounds__(256, 2) void attn_mma_kernel(
    const __nv_bfloat16* __restrict__ qk, const __nv_bfloat16* __restrict__ vT,
    __nv_bfloat16* __restrict__ out)
{
    extern __shared__ __nv_bfloat16 smh[];

    const int tid = threadIdx.x;
    const int w   = tid >> 5;
    const int l   = tid & 31;
    const int g   = l >> 2;
    const int q   = l & 3;
    const int qb  = (int)gridDim.x - 1 - (int)blockIdx.x;  // heavy CTAs first
    const int h = blockIdx.y, b = blockIdx.z;
    const int qrow0 = qb*128 + w*16;

    // ---- Q fragments (bf16, scaled by 1/8 exactly) ----
    uint32_t qa[4][4];
    {
        const uint32_t* Qw0 = (const uint32_t*)(qk + ((size_t)(b*Tv + qrow0 + g    ))*(2*Dv) + h*HDv);
        const uint32_t* Qw1 = (const uint32_t*)(qk + ((size_t)(b*Tv + qrow0 + g + 8))*(2*Dv) + h*HDv);
        __nv_bfloat162 sc = __floats2bfloat162_rn(0.125f, 0.125f);
        #pragma unroll
        for (int kc = 0; kc < 4; kc++) {
            qa[kc][0] = mulbf2(Qw0[kc*8 + q    ], sc);
            qa[kc][1] = mulbf2(Qw1[kc*8 + q    ], sc);
            qa[kc][2] = mulbf2(Qw0[kc*8 + q + 4], sc);
            qa[kc][3] = mulbf2(Qw1[kc*8 + q + 4], sc);
        }
    }

    float o[8][4];
    #pragma unroll
    for (int nc = 0; nc < 8; nc++)
        #pragma unroll
        for (int e = 0; e < 4; e++) o[nc][e] = 0.f;
    float mA = -1e30f, mB = -1e30f, lA = 0.f, lB = 0.f;

    const int ntiles = 2*qb + 2;

    // prologue: tile 0
    {
        __nv_bfloat16* Kb = smh;
        __nv_bfloat16* Vb = Kb + 64*KS_LDH;
        #pragma unroll
        for (int i = 0; i < 2; i++) {
            int idx = tid + i*256;             // 0..511
            int r = idx >> 3, seg = (idx & 7) * 8;
            cp16h(Kb + r*KS_LDH + seg, qk + ((size_t)(b*Tv + r))*(2*Dv) + Dv + h*HDv + seg);
            cp16h(Vb + r*KS_LDH + seg, vT + ((size_t)(h*HDv + r))*Mrows + b*Tv + seg);
        }
        asm volatile("cp.async.commit_group;" ::);
    }

    for (int kt = 0; kt < ntiles; kt++) {
        const int kbase = kt*64;
        if (kt + 1 < ntiles) {
            __nv_bfloat16* Kb = smh + ((kt+1)&1)*STAGEH;
            __nv_bfloat16* Vb = Kb + 64*KS_LDH;
            #pragma unroll
            for (int i = 0; i < 2; i++) {
                int idx = tid + i*256;
                int r = idx >> 3, seg = (idx & 7) * 8;
                cp16h(Kb + r*KS_LDH + seg, qk + ((size_t)(b*Tv + kbase + 64 + r))*(2*Dv) + Dv + h*HDv + seg);
                cp16h(Vb + r*KS_LDH + seg, vT + ((size_t)(h*HDv + r))*Mrows + b*Tv + kbase + 64 + seg);
            }
            asm volatile("cp.async.commit_group;" ::);
            asm volatile("cp.async.wait_group 1;" ::);
        } else {
            asm volatile("cp.async.wait_group 0;" ::);
        }
        __syncthreads();

        const uint32_t* Kw = (const uint32_t*)(smh + (kt&1)*STAGEH);
        const uint32_t* Vw = Kw + 64*(KS_LDH/2);

        // ---- S = Q @ K^T (16 x 64 per warp) ----
        float s[8][4];
        #pragma unroll
        for (int nc = 0; nc < 8; nc++) {
            s[nc][0] = 0.f; s[nc][1] = 0.f; s[nc][2] = 0.f; s[nc][3] = 0.f;
            #pragma unroll
            for (int kc = 0; kc < 4; kc++) {
                uint32_t kb0 = Kw[(nc*8 + g)*(KS_LDH/2) + kc*8 + q    ];
                uint32_t kb1 = Kw[(nc*8 + g)*(KS_LDH/2) + kc*8 + q + 4];
                mma_bf16(s[nc][0], s[nc][1], s[nc][2], s[nc][3],
                         qa[kc][0], qa[kc][1], qa[kc][2], qa[kc][3], kb0, kb1);
            }
        }

        // ---- causal mask ----
        if (kbase + 63 > qrow0) {
            int rowA = qrow0 + g, rowB = qrow0 + g + 8;
            #pragma unroll
            for (int nc = 0; nc < 8; nc++) {
                int c0 = kbase + nc*8 + 2*q, c1 = c0 + 1;
                if (c0 > rowA) s[nc][0] = -1e30f;
                if (c1 > rowA) s[nc][1] = -1e30f;
                if (c0 > rowB) s[nc][2] = -1e30f;
                if (c1 > rowB) s[nc][3] = -1e30f;
            }
        }

        // ---- online softmax (registers) ----
        float rmA = -1e30f, rmB = -1e30f;
        #pragma unroll
        for (int nc = 0; nc < 8; nc++) {
            rmA = fmaxf(rmA, fmaxf(s[nc][0], s[nc][1]));
            rmB = fmaxf(rmB, fmaxf(s[nc][2], s[nc][3]));
        }
        rmA = fmaxf(rmA, __shfl_xor_sync(0xffffffffu, rmA, 1));
        rmA = fmaxf(rmA, __shfl_xor_sync(0xffffffffu, rmA, 2));
        rmB = fmaxf(rmB, __shfl_xor_sync(0xffffffffu, rmB, 1));
        rmB = fmaxf(rmB, __shfl_xor_sync(0xffffffffu, rmB, 2));
        float mnA = fmaxf(mA, rmA), mnB = fmaxf(mB, rmB);
        float corrA = __expf(mA - mnA), corrB = __expf(mB - mnB);
        mA = mnA; mB = mnB;

        float rsA = 0.f, rsB = 0.f;
        #pragma unroll
        for (int nc = 0; nc < 8; nc++) {
            s[nc][0] = __expf(s[nc][0] - mnA);
            s[nc][1] = __expf(s[nc][1] - mnA);
            s[nc][2] = __expf(s[nc][2] - mnB);
            s[nc][3] = __expf(s[nc][3] - mnB);
            rsA += s[nc][0] + s[nc][1];
            rsB += s[nc][2] + s[nc][3];
        }
        rsA += __shfl_xor_sync(0xffffffffu, rsA, 1);
        rsA += __shfl_xor_sync(0xffffffffu, rsA, 2);
        rsB += __shfl_xor_sync(0xffffffffu, rsB, 1);
        rsB += __shfl_xor_sync(0xffffffffu, rsB, 2);
        lA = lA*corrA + rsA;
        lB = lB*corrB + rsB;

        #pragma unroll
        for (int nc = 0; nc < 8; nc++) {
            o[nc][0] *= corrA; o[nc][1] *= corrA;
            o[nc][2] *= corrB; o[nc][3] *= corrB;
        }

        // ---- O += P @ V : C-frag -> A-frag is a pure pack for m16n8k16 ----
        #pragma unroll
        for (int kc = 0; kc < 4; kc++) {
            uint32_t pa0 = packbf(s[2*kc][0],   s[2*kc][1]);
            uint32_t pa1 = packbf(s[2*kc][2],   s[2*kc][3]);
            uint32_t pa2 = packbf(s[2*kc+1][0], s[2*kc+1][1]);
            uint32_t pa3 = packbf(s[2*kc+1][2], s[2*kc+1][3]);
            #pragma unroll
            for (int nc = 0; nc < 8; nc++) {
                uint32_t vb0 = Vw[(nc*8 + g)*(KS_LDH/2) + kc*8 + q    ];
                uint32_t vb1 = Vw[(nc*8 + g)*(KS_LDH/2) + kc*8 + q + 4];
                mma_bf16(o[nc][0], o[nc][1], o[nc][2], o[nc][3],
                         pa0, pa1, pa2, pa3, vb0, vb1);
            }
        }
        __syncthreads();
    }

    // ---- write O / l (bf16) ----
    float invA = 1.f / lA, invB = 1.f / lB;
    __nv_bfloat16* ob0 = out + ((size_t)(b*Tv + qrow0 + g    ))*Dv + h*HDv;
    __nv_bfloat16* ob1 = out + ((size_t)(b*Tv + qrow0 + g + 8))*Dv + h*HDv;
    #pragma unroll
    for (int nc = 0; nc < 8; nc++) {
        int c = nc*8 + 2*q;
        *(uint32_t*)&ob0[c] = packbf(o[nc][0]*invA, o[nc][1]*invA);
        *(uint32_t*)&ob1[c] = packbf(o[nc][2]*invB, o[nc][3]*invB);
    }
}

// ---------------- Parallel selective scan ----------------
__global__ __launch_bounds__(256) void scan_phase1(
    const float* __restrict__ dt, const float* __restrict__ z,
    const float* __restrict__ Bi, const float* __restrict__ A_log)
{
    int gth = blockIdx.x*256 + threadIdx.x;
    int chan = gth & 127, chunk = gth >> 7;
    int b = chan >> 6, sc = chan & 63;
    float A[16];
    #pragma unroll
    for (int st = 0; st < 16; st++) A[st] = -__expf(A_log[sc*STv + st]);
    float aP[16], bP[16];
    #pragma unroll
    for (int st = 0; st < 16; st++) { aP[st] = 1.f; bP[st] = 0.f; }
    int t0 = chunk*TSTEP;
    const float* dtp = dt + ((size_t)b*Tv + t0)*SCv + sc;
    const float* zp  = z  + ((size_t)b*Tv + t0)*SCv + sc;
    const float* Bp  = Bi + ((size_t)b*Tv + t0)*STv;
    for (int tt = 0; tt < TSTEP; tt++) {
        float dtc = dtp[(size_t)tt*SCv];
        float zc  = zp [(size_t)tt*SCv];
        float dz  = dtc*zc;
        float4 B0 = *(const float4*)&Bp[tt*STv + 0];
        float4 B1 = *(const float4*)&Bp[tt*STv + 4];
        float4 B2 = *(const float4*)&Bp[tt*STv + 8];
        float4 B3 = *(const float4*)&Bp[tt*STv + 12];
        float Bvv[16] = {B0.x,B0.y,B0.z,B0.w, B1.x,B1.y,B1.z,B1.w,
                         B2.x,B2.y,B2.z,B2.w, B3.x,B3.y,B3.z,B3.w};
        #pragma unroll
        for (int st = 0; st < 16; st++) {
            float ab = fmaf(dtc, A[st], 1.f);
            aP[st] *= ab;
            bP[st] = fmaf(ab, bP[st], dz*Bvv[st]);
        }
    }
    int base = (chan*CH + chunk)*16;
    #pragma unroll
    for (int st = 0; st < 16; st++) { g_scanA[base+st] = aP[st]; g_scanB[base+st] = bP[st]; }
}

__global__ __launch_bounds__(256) void scan_phase2()
{
    int gth = blockIdx.x*256 + threadIdx.x;
    int chan = gth >> 4, st = gth & 15;
    float s = 0.f;
    #pragma unroll
    for (int ch = 0; ch < CH; ch++) {
        int idx = (chan*CH + ch)*16 + st;
        g_scanS[idx] = s;
        s = fmaf(g_scanA[idx], s, g_scanB[idx]);
    }
}

__global__ __launch_bounds__(256) void scan_phase3(
    const float* __restrict__ dt, const float* __restrict__ z,
    const float* __restrict__ Bi, const float* __restrict__ Ci,
    const float* __restrict__ gate, const float* __restrict__ A_log,
    __nv_bfloat16* __restrict__ y)
{
    int gth = blockIdx.x*256 + threadIdx.x;
    int chan = gth & 127, chunk = gth >> 7;
    int b = chan >> 6, sc = chan & 63;
    float A[16];
    #pragma unroll
    for (int st = 0; st < 16; st++) A[st] = -__expf(A_log[sc*STv + st]);
    float state[16];
    {
        int base = (chan*CH + chunk)*16;
        #pragma unroll
        for (int st = 0; st < 16; st++) state[st] = g_scanS[base+st];
    }
    int t0 = chunk*TSTEP;
    const float* dtp = dt   + ((size_t)b*Tv + t0)*SCv + sc;
    const float* zp  = z    + ((size_t)b*Tv + t0)*SCv + sc;
    const float* gp  = gate + ((size_t)b*Tv + t0)*SCv + sc;
    const float* Bp  = Bi + ((size_t)b*Tv + t0)*STv;
    const float* Cp  = Ci + ((size_t)b*Tv + t0)*STv;
    __nv_bfloat16* yp = y + ((size_t)b*Tv + t0)*SCv + sc;
    for (int tt = 0; tt < TSTEP; tt++) {
        float dtc = dtp[(size_t)tt*SCv];
        float zc  = zp [(size_t)tt*SCv];
        float dz  = dtc*zc;
        float4 B0 = *(const float4*)&Bp[tt*STv + 0];
        float4 B1 = *(const float4*)&Bp[tt*STv + 4];
        float4 B2 = *(const float4*)&Bp[tt*STv + 8];
        float4 B3 = *(const float4*)&Bp[tt*STv + 12];
        float4 C0 = *(const float4*)&Cp[tt*STv + 0];
        float4 C1 = *(const float4*)&Cp[tt*STv + 4];
        float4 C2 = *(const float4*)&Cp[tt*STv + 8];
        float4 C3 = *(const float4*)&Cp[tt*STv + 12];
        float Bvv[16] = {B0.x,B0.y,B0.z,B0.w, B1.x,B1.y,B1.z,B1.w,
                         B2.x,B2.y,B2.z,B2.w, B3.x,B3.y,B3.z,B3.w};
        float Cvv[16] = {C0.x,C0.y,C0.z,C0.w, C1.x,C1.y,C1.z,C1.w,
                         C2.x,C2.y,C2.z,C2.w, C3.x,C3.y,C3.z,C3.w};
        float p0 = 0.f, p1 = 0.f, p2 = 0.f, p3 = 0.f;
        #pragma unroll
        for (int st = 0; st < 16; st += 4) {
            float ab;
            ab = fmaf(dtc, A[st+0], 1.f); state[st+0] = fmaf(ab, state[st+0], dz*Bvv[st+0]); p0 = fmaf(state[st+0], Cvv[st+0], p0);
            ab = fmaf(dtc, A[st+1], 1.f); state[st+1] = fmaf(ab, state[st+1], dz*Bvv[st+1]); p1 = fmaf(state[st+1], Cvv[st+1], p1);
            ab = fmaf(dtc, A[st+2], 1.f); state[st+2] = fmaf(ab, state[st+2], dz*Bvv[st+2]); p2 = fmaf(state[st+2], Cvv[st+2], p2);
            ab = fmaf(dtc, A[st+3], 1.f); state[st+3] = fmaf(ab, state[st+3], dz*Bvv[st+3]); p3 = fmaf(state[st+3], Cvv[st+3], p3);
        }
        float p = (p0 + p1) + (p2 + p3);
        yp[(size_t)tt*SCv] = __float2bfloat16(p * gp[(size_t)tt*SCv]);
    }
}

// ---------------- launch ----------------
extern "C" void kernel_launch(void* const* d_in, const int* in_sizes, int n_in,
                              void* d_out, int out_size)
{
    const float* x      = (const float*)d_in[0];
    const float* qkv_w  = (const float*)d_in[1];
    const float* o_w    = (const float*)d_in[2];
    const float* n1w    = (const float*)d_in[3];
    const float* n2w    = (const float*)d_in[4];
    const float* in_w   = (const float*)d_in[5];
    const float* out_w  = (const float*)d_in[6];
    const float* A_log  = (const float*)d_in[7];
    const float* Bp_w   = (const float*)d_in[8];
    const float* Cp_w   = (const float*)d_in[9];
    const float* dt_w   = (const float*)d_in[10];
    const float* dt_b   = (const float*)d_in[11];
    const float* gate_w = (const float*)d_in[12];
    float* out = (float*)d_out;

    __nv_bfloat16 *hb,*qkb,*vTb,*attnb,*h2b,*yb16,*wq,*wo,*wzg,*wout;
    float *x1,*zb,*gateb,*Bib,*Cib,*dtb;
    cudaGetSymbolAddress((void**)&hb,   g_h);
    cudaGetSymbolAddress((void**)&qkb,  g_qk);
    cudaGetSymbolAddress((void**)&vTb,  g_vT);
    cudaGetSymbolAddress((void**)&attnb,g_attn);
    cudaGetSymbolAddress((void**)&x1,   g_x1);
    cudaGetSymbolAddress((void**)&h2b,  g_h2);
    cudaGetSymbolAddress((void**)&zb,   g_z);
    cudaGetSymbolAddress((void**)&gateb,g_gate);
    cudaGetSymbolAddress((void**)&Bib,  g_Bi);
    cudaGetSymbolAddress((void**)&Cib,  g_Ci);
    cudaGetSymbolAddress((void**)&dtb,  g_dt);
    cudaGetSymbolAddress((void**)&yb16, g_y);
    cudaGetSymbolAddress((void**)&wq,   g_wq);
    cudaGetSymbolAddress((void**)&wo,   g_wo);
    cudaGetSymbolAddress((void**)&wzg,  g_wzg);
    cudaGetSymbolAddress((void**)&wout, g_wout);

    const int attn_smem = 2*STAGEH*2;   // 36864 B
    cudaFuncSetAttribute(attn_mma_kernel, cudaFuncAttributeMaxDynamicSharedMemorySize, attn_smem);

    // 0. convert weights to bf16
    f32_to_bf16<<<6144, 256>>>(qkv_w,  wq,   1572864);
    f32_to_bf16<<<2048, 256>>>(o_w,    wo,   524288);
    f32_to_bf16<<<128,  256>>>(in_w,   wzg,          32768);
    f32_to_bf16<<<128,  256>>>(gate_w, wzg + 65536,  32768);
    f32_to_bf16<<<128,  256>>>(out_w,  wout, 32768);

    // 1. rmsnorm1 -> bf16
    rmsnorm_kernel<<<Mrows, 256>>>(x, n1w, hb);
    // 2. qkv: Q,K -> g_qk (bf16), V -> g_vT (transposed bf16)
    gemm_bf16<<<dim3(24, 32), 256>>>(hb, wq, nullptr, qkb, vTb,
                                     Mrows, 3*Dv, 2*Dv, Dv, 2, 3, 2*Dv, 0);
    // 3. attention -> bf16
    attn_mma_kernel<<<dim3(Tv/128, Hv, Bv), 256, attn_smem>>>(qkb, vTb, attnb);
    // 4. x1 = x + attn @ o_w^T (fp32)
    gemm_bf16<<<dim3(8, 32), 256>>>(attnb, wo, x, x1, nullptr,
                                    Mrows, Dv, Dv, Dv, 1, 0, Dv, 0);
    // 5. rmsnorm2 -> bf16
    rmsnorm_kernel<<<Mrows, 256>>>(x1, n2w, h2b);
    // 6. fused z (fp32) / gate (fp32 silu)
    gemm_bf16<<<dim3(1, 32), 256>>>(h2b, wzg, nullptr, zb, gateb,
                                    Mrows, 2*SCv, SCv, Dv, 0, 4, SCv, SCv);
    // 7. fused Bi/Ci/dt
    gemm_bcd<<<64, 256>>>(zb, Bp_w, Cp_w, dt_w, dt_b, Bib, Cib, dtb);
    // 8. parallel scan -> y bf16
    scan_phase1<<<16, 256>>>(dtb, zb, Bib, A_log);
    scan_phase2<<<8, 256>>>();
    scan_phase3<<<16, 256>>>(dtb, zb, Bib, Cib, gateb, A_log, yb16);
    // 9. out = x1 + y @ out_w^T (fp32)
    gemm_bf16<<<dim3(8, 32), 256>>>(yb16, wout, x1, out, nullptr,
                                    Mrows, Dv, Dv, SCv, 1, 0, Dv, 0);
}

// round 9
// speedup vs baseline: 6.2540x; 1.0625x over previous
#include <cuda_runtime.h>
#include <cuda_bf16.h>
#include <math.h>
#include <cstdint>

#define Bv 2
#define Tv 2048
#define Dv 1024
#define Hv 16
#define HDv 64
#define SCv 64
#define STv 16
#define Mrows (Bv*Tv)   // 4096
#define EPSR 1.1920929e-07f
#define CH 32
#define TSTEP (Tv/CH)   // 64

// ---------------- scratch (device globals) ----------------
__device__ __nv_bfloat16 g_h   [Mrows*Dv];
__device__ __nv_bfloat16 g_qk  [Mrows*2*Dv];
__device__ __nv_bfloat16 g_vT  [Dv*Mrows];
__device__ __nv_bfloat16 g_attn[Mrows*Dv];
__device__ float         g_x1  [Mrows*Dv];
__device__ __nv_bfloat16 g_h2  [Mrows*Dv];
__device__ float g_z   [Mrows*SCv];
__device__ float g_gate[Mrows*SCv];
__device__ float g_Bi  [Mrows*STv];
__device__ float g_Ci  [Mrows*STv];
__device__ float g_dt  [Mrows*SCv];
__device__ __nv_bfloat16 g_y [Mrows*SCv];
__device__ float g_scanA[128*CH*16];
__device__ float g_scanB[128*CH*16];
__device__ float g_scanS[128*CH*16];
__device__ __nv_bfloat16 g_wq  [3*Dv*Dv];
__device__ __nv_bfloat16 g_wo  [Dv*Dv];
__device__ __nv_bfloat16 g_wzg [2*SCv*Dv];
__device__ __nv_bfloat16 g_wout[Dv*SCv];

__device__ __forceinline__ uint32_t packbf(float a, float b) {
    __nv_bfloat162 t = __floats2bfloat162_rn(a, b);
    return *reinterpret_cast<uint32_t*>(&t);
}
__device__ __forceinline__ float ex2(float x) {
    float y;
    asm("ex2.approx.f32 %0, %1;" : "=f"(y) : "f"(x));
    return y;
}
__device__ __forceinline__ uint32_t scale_pack(uint32_t w, float s) {
    __nv_bfloat162 t = *reinterpret_cast<__nv_bfloat162*>(&w);
    return packbf(__bfloat162float(t.x)*s, __bfloat162float(t.y)*s);
}

__device__ __forceinline__ void mma_bf16(float& d0, float& d1, float& d2, float& d3,
                                         uint32_t a0, uint32_t a1, uint32_t a2, uint32_t a3,
                                         uint32_t b0, uint32_t b1) {
    asm volatile(
        "mma.sync.aligned.m16n8k16.row.col.f32.bf16.bf16.f32 "
        "{%0,%1,%2,%3}, {%4,%5,%6,%7}, {%8,%9}, {%0,%1,%2,%3};"
        : "+f"(d0), "+f"(d1), "+f"(d2), "+f"(d3)
        : "r"(a0), "r"(a1), "r"(a2), "r"(a3), "r"(b0), "r"(b1));
}

__device__ __forceinline__ void ldsm4(uint32_t& r0, uint32_t& r1, uint32_t& r2, uint32_t& r3,
                                      uint32_t addr) {
    asm volatile("ldmatrix.sync.aligned.m8n8.x4.shared.b16 {%0,%1,%2,%3}, [%4];"
        : "=r"(r0), "=r"(r1), "=r"(r2), "=r"(r3) : "r"(addr));
}

__device__ __forceinline__ void cp16h(__nv_bfloat16* dst, const __nv_bfloat16* src) {
    uint32_t d = (uint32_t)__cvta_generic_to_shared(dst);
    asm volatile("cp.async.cg.shared.global [%0], [%1], 16;" :: "r"(d), "l"(src));
}

// ---------------- merged f32 -> bf16 convert of ALL weights ----------------
#define N2_Q   1572864
#define N2_O   524288
#define N2_S   32768
__global__ __launch_bounds__(256) void conv_all(
    const float* __restrict__ qkv_w, const float* __restrict__ o_w,
    const float* __restrict__ in_w, const float* __restrict__ gate_w,
    const float* __restrict__ out_w)
{
    int i = blockIdx.x*256 + threadIdx.x;   // float2 index
    const float* src; __nv_bfloat162* dst; int j;
    if (i < N2_Q)                        { src = qkv_w;  dst = (__nv_bfloat162*)g_wq;   j = i; }
    else if ((j = i - N2_Q) < N2_O)      { src = o_w;    dst = (__nv_bfloat162*)g_wo; }
    else if ((j = j - N2_O) < N2_S)      { src = in_w;   dst = (__nv_bfloat162*)g_wzg; }
    else if ((j = j - N2_S) < N2_S)      { src = gate_w; dst = (__nv_bfloat162*)g_wzg + N2_S; }
    else if ((j = j - N2_S) < N2_S)      { src = out_w;  dst = (__nv_bfloat162*)g_wout; }
    else return;
    float2 v = ((const float2*)src)[j];
    dst[j] = __floats2bfloat162_rn(v.x, v.y);
}

// ---------------- RMSNorm -> bf16 ----------------
__global__ __launch_bounds__(256) void rmsnorm_kernel(
    const float* __restrict__ x, const float* __restrict__ w, __nv_bfloat16* __restrict__ o)
{
    int row = blockIdx.x;
    const float4* xr = (const float4*)(x + (size_t)row*Dv);
    float4 v = xr[threadIdx.x];
    float ss = v.x*v.x + v.y*v.y + v.z*v.z + v.w*v.w;
    #pragma unroll
    for (int off=16; off; off>>=1) ss += __shfl_xor_sync(0xffffffffu, ss, off);
    __shared__ float sm[8];
    int wid = threadIdx.x>>5, lane = threadIdx.x&31;
    if (lane==0) sm[wid] = ss;
    __syncthreads();
    float tot = sm[0]+sm[1]+sm[2]+sm[3]+sm[4]+sm[5]+sm[6]+sm[7];
    float scale = rsqrtf(tot*(1.0f/Dv) + EPSR);
    const float4* wr = (const float4*)w;
    float4 wv = wr[threadIdx.x];
    uint2 st = make_uint2(packbf(v.x*scale*wv.x, v.y*scale*wv.y),
                          packbf(v.z*scale*wv.z, v.w*scale*wv.w));
    *(uint2*)&o[(size_t)row*Dv + threadIdx.x*4] = st;
}

// ---------------- bf16 GEMM with ldmatrix fragment loads --------------------
// modes: 0 fp32; 1 fp32+res; 2 bf16; 3 bf16 transposed; 4 fp32 silu
#define GLDH 40
__global__ __launch_bounds__(256, 2) void gemm_bf16(
    const __nv_bfloat16* __restrict__ A, const __nv_bfloat16* __restrict__ W,
    const float* __restrict__ res, void* __restrict__ Cp, void* __restrict__ C2p,
    int M, int N, int nsplit, int K, int mode1, int mode2, int ld1, int ld2)
{
    __shared__ __nv_bfloat16 As[2][128*GLDH];
    __shared__ __nv_bfloat16 Ws[2][128*GLDH];

    const int tid = threadIdx.x;
    const int w   = tid >> 5;
    const int l   = tid & 31;
    const int g   = l >> 2;
    const int q   = l & 3;
    const int wm  = w >> 1;
    const int wn  = w & 1;
    const int bm  = blockIdx.y * 128;
    const int bn  = blockIdx.x * 128;

    const int lr = l & 7, lt = l >> 3;
    const uint32_t sA0 = (uint32_t)__cvta_generic_to_shared(As[0]);
    const uint32_t sA1 = (uint32_t)__cvta_generic_to_shared(As[1]);
    const uint32_t sW0 = (uint32_t)__cvta_generic_to_shared(Ws[0]);
    const uint32_t sW1 = (uint32_t)__cvta_generic_to_shared(Ws[1]);
    // A-frag lane offset: bit0 of tile -> row block, bit1 -> col block
    const uint32_t aOff = (uint32_t)((((lt & 1)*8 + lr)*GLDH + (lt >> 1)*8) * 2);
    // B-frag lane offset: bit1 -> row(n) block, bit0 -> col(k) block
    const uint32_t bOff = (uint32_t)((((lt >> 1)*8 + lr)*GLDH + (lt & 1)*8) * 2);

    float c[2][8][4];
    #pragma unroll
    for (int i=0;i<2;i++)
        #pragma unroll
        for (int nj=0;nj<8;nj++)
            #pragma unroll
            for (int e=0;e<4;e++) c[i][nj][e] = 0.f;

    // prologue: stage 0
    #pragma unroll
    for (int i = 0; i < 2; i++) {
        int idx = tid + i*256;
        int row = idx >> 2, seg = (idx & 3) * 8;
        cp16h(&As[0][row*GLDH + seg], A + (size_t)(bm + row)*K + seg);
        cp16h(&Ws[0][row*GLDH + seg], W + (size_t)(bn + row)*K + seg);
    }
    asm volatile("cp.async.commit_group;" ::);

    int s = 0;
    for (int k0 = 0; k0 < K; k0 += 32, s ^= 1) {
        if (k0 + 32 < K) {
            int kn = k0 + 32;
            #pragma unroll
            for (int i = 0; i < 2; i++) {
                int idx = tid + i*256;
                int row = idx >> 2, seg = (idx & 3) * 8;
                cp16h(&As[s^1][row*GLDH + seg], A + (size_t)(bm + row)*K + kn + seg);
                cp16h(&Ws[s^1][row*GLDH + seg], W + (size_t)(bn + row)*K + kn + seg);
            }
            asm volatile("cp.async.commit_group;" ::);
            asm volatile("cp.async.wait_group 1;" ::);
        } else {
            asm volatile("cp.async.wait_group 0;" ::);
        }
        __syncthreads();

        const uint32_t sa = s ? sA1 : sA0;
        const uint32_t sw = s ? sW1 : sW0;
        #pragma unroll
        for (int kc2 = 0; kc2 < 2; kc2++) {
            uint32_t a[2][4];
            #pragma unroll
            for (int i = 0; i < 2; i++)
                ldsm4(a[i][0], a[i][1], a[i][2], a[i][3],
                      sa + aOff + (uint32_t)(((wm*32 + i*16)*GLDH + kc2*16) * 2));
            uint32_t bfr[8][2];
            #pragma unroll
            for (int ncp = 0; ncp < 4; ncp++) {
                uint32_t x0, x1, x2, x3;
                ldsm4(x0, x1, x2, x3,
                      sw + bOff + (uint32_t)(((wn*64 + ncp*16)*GLDH + kc2*16) * 2));
                bfr[2*ncp][0] = x0; bfr[2*ncp][1] = x1;
                bfr[2*ncp+1][0] = x2; bfr[2*ncp+1][1] = x3;
            }
            #pragma unroll
            for (int i = 0; i < 2; i++)
                #pragma unroll
                for (int nj = 0; nj < 8; nj++)
                    mma_bf16(c[i][nj][0], c[i][nj][1], c[i][nj][2], c[i][nj][3],
                             a[i][0], a[i][1], a[i][2], a[i][3], bfr[nj][0], bfr[nj][1]);
        }
        __syncthreads();
    }

    // epilogue
    #pragma unroll
    for (int i = 0; i < 2; i++) {
        #pragma unroll
        for (int nj = 0; nj < 8; nj++) {
            int row0 = bm + wm*32 + i*16 + g;
            int row1 = row0 + 8;
            int col  = bn + wn*64 + nj*8 + 2*q;
            bool first = (col < nsplit);
            int mode = first ? mode1 : mode2;
            float v0 = c[i][nj][0], v1 = c[i][nj][1], v2 = c[i][nj][2], v3 = c[i][nj][3];
            if (mode == 1) {
                v0 += res[(size_t)row0*N + col];
                v1 += res[(size_t)row0*N + col + 1];
                v2 += res[(size_t)row1*N + col];
                v3 += res[(size_t)row1*N + col + 1];
            } else if (mode == 4) {
                v0 = v0 / (1.f + __expf(-v0));
                v1 = v1 / (1.f + __expf(-v1));
                v2 = v2 / (1.f + __expf(-v2));
                v3 = v3 / (1.f + __expf(-v3));
            }
            if (mode == 2) {
                __nv_bfloat16* O = (__nv_bfloat16*)(first ? Cp : C2p);
                int ld = first ? ld1 : ld2;
                int cc = first ? col : col - nsplit;
                *(uint32_t*)&O[(size_t)row0*ld + cc] = packbf(v0, v1);
                *(uint32_t*)&O[(size_t)row1*ld + cc] = packbf(v2, v3);
            } else if (mode == 3) {
                __nv_bfloat16* O = (__nv_bfloat16*)C2p;
                int cc = col - nsplit;
                O[(size_t)cc*M + row0]     = __float2bfloat16(v0);
                O[(size_t)(cc+1)*M + row0] = __float2bfloat16(v1);
                O[(size_t)cc*M + row1]     = __float2bfloat16(v2);
                O[(size_t)(cc+1)*M + row1] = __float2bfloat16(v3);
            } else {
                float* O = (float*)(first ? Cp : C2p);
                int ld = first ? ld1 : ld2;
                int cc = first ? col : col - nsplit;
                *(float2*)&O[(size_t)row0*ld + cc] = make_float2(v0, v1);
                *(float2*)&O[(size_t)row1*ld + cc] = make_float2(v2, v3);
            }
        }
    }
}

// ---------------- fused Bi/Ci/dt (fp32) ----------------
__global__ __launch_bounds__(256) void gemm_bcd(
    const float* __restrict__ z, const float* __restrict__ Bp_w,
    const float* __restrict__ Cp_w, const float* __restrict__ dt_w,
    const float* __restrict__ dt_b,
    float* __restrict__ Bi, float* __restrict__ Ci, float* __restrict__ dt)
{
    __shared__ float Zs[64*68];
    __shared__ float Wt[64*100];
    const int tid = threadIdx.x;
    const int bm = blockIdx.x*64;

    for (int t = tid; t < 1024; t += 256) {
        int row = t >> 4, k4 = (t & 15) << 2;
        float4 v = *(const float4*)&z[(size_t)(bm + row)*SCv + k4];
        Zs[row*68 + k4 + 0] = v.x; Zs[row*68 + k4 + 1] = v.y;
        Zs[row*68 + k4 + 2] = v.z; Zs[row*68 + k4 + 3] = v.w;
    }
    for (int idx = tid; idx < 96*64; idx += 256) {
        int r = idx >> 6, c = idx & 63;
        float v = (r < 16) ? Bp_w[r*SCv + c] : (r < 32) ? Cp_w[(r-16)*SCv + c] : dt_w[(r-32)*SCv + c];
        Wt[c*100 + r] = v;
    }
    __syncthreads();

    const int ty = tid >> 4, tx = tid & 15;
    float acc[4][6];
    #pragma unroll
    for (int i=0;i<4;i++)
        #pragma unroll
        for (int j=0;j<6;j++) acc[i][j] = 0.f;

    #pragma unroll 4
    for (int k = 0; k < 64; k++) {
        float a[4], bb[6];
        #pragma unroll
        for (int i=0;i<4;i++) a[i] = Zs[(ty*4+i)*68 + k];
        #pragma unroll
        for (int j=0;j<6;j++) bb[j] = Wt[k*100 + tx*6 + j];
        #pragma unroll
        for (int i=0;i<4;i++)
            #pragma unroll
            for (int j=0;j<6;j++) acc[i][j] = fmaf(a[i], bb[j], acc[i][j]);
    }

    #pragma unroll
    for (int i=0;i<4;i++) {
        int row = bm + ty*4 + i;
        #pragma unroll
        for (int j=0;j<6;j++) {
            int c = tx*6 + j;
            float v = acc[i][j];
            if (c < 16) {
                Bi[(size_t)row*STv + c] = v;
            } else if (c < 32) {
                Ci[(size_t)row*STv + (c-16)] = v;
            } else {
                v += dt_b[c-32];
                dt[(size_t)row*SCv + (c-32)] = (v > 20.f) ? v : log1pf(__expf(v));
            }
        }
    }
}

// ---------------- Flash attention v5: ldmatrix + base-2 softmax -------------
#define KS_LDH 72
#define STAGEH (64*KS_LDH*2)
__global__ __launch_bounds__(256, 2) void attn_mma_kernel(
    const __nv_bfloat16* __restrict__ qk, const __nv_bfloat16* __restrict__ vT,
    __nv_bfloat16* __restrict__ out)
{
    extern __shared__ __nv_bfloat16 smh[];

    const int tid = threadIdx.x;
    const int w   = tid >> 5;
    const int l   = tid & 31;
    const int g   = l >> 2;
    const int q   = l & 3;
    const int qb  = (int)gridDim.x - 1 - (int)blockIdx.x;
    const int h = blockIdx.y, b = blockIdx.z;
    const int qrow0 = qb*128 + w*16;

    const int lr = l & 7, lt = l >> 3;
    const uint32_t smbase = (uint32_t)__cvta_generic_to_shared(smh);
    const uint32_t bOff = (uint32_t)((((lt >> 1)*8 + lr)*KS_LDH + (lt & 1)*8) * 2);

    // ---- Q fragments (fp32 scale by 0.125*log2e, then pack bf16) ----
    const float QSC = 0.125f * 1.4426950408889634f;
    uint32_t qa[4][4];
    {
        const uint32_t* Qw0 = (const uint32_t*)(qk + ((size_t)(b*Tv + qrow0 + g    ))*(2*Dv) + h*HDv);
        const uint32_t* Qw1 = (const uint32_t*)(qk + ((size_t)(b*Tv + qrow0 + g + 8))*(2*Dv) + h*HDv);
        #pragma unroll
        for (int kc = 0; kc < 4; kc++) {
            qa[kc][0] = scale_pack(Qw0[kc*8 + q    ], QSC);
            qa[kc][1] = scale_pack(Qw1[kc*8 + q    ], QSC);
            qa[kc][2] = scale_pack(Qw0[kc*8 + q + 4], QSC);
            qa[kc][3] = scale_pack(Qw1[kc*8 + q + 4], QSC);
        }
    }

    float o[8][4];
    #pragma unroll
    for (int nc = 0; nc < 8; nc++)
        #pragma unroll
        for (int e = 0; e < 4; e++) o[nc][e] = 0.f;
    float mA = -1e30f, mB = -1e30f, lA = 0.f, lB = 0.f;

    const int ntiles = 2*qb + 2;

    // prologue: tile 0
    {
        __nv_bfloat16* Kb = smh;
        __nv_bfloat16* Vb = Kb + 64*KS_LDH;
        #pragma unroll
        for (int i = 0; i < 2; i++) {
            int idx = tid + i*256;
            int r = idx >> 3, seg = (idx & 7) * 8;
            cp16h(Kb + r*KS_LDH + seg, qk + ((size_t)(b*Tv + r))*(2*Dv) + Dv + h*HDv + seg);
            cp16h(Vb + r*KS_LDH + seg, vT + ((size_t)(h*HDv + r))*Mrows + b*Tv + seg);
        }
        asm volatile("cp.async.commit_group;" ::);
    }

    for (int kt = 0; kt < ntiles; kt++) {
        const int kbase = kt*64;
        if (kt + 1 < ntiles) {
            __nv_bfloat16* Kb = smh + ((kt+1)&1)*STAGEH;
            __nv_bfloat16* Vb = Kb + 64*KS_LDH;
            #pragma unroll
            for (int i = 0; i < 2; i++) {
                int idx = tid + i*256;
                int r = idx >> 3, seg = (idx & 7) * 8;
                cp16h(Kb + r*KS_LDH + seg, qk + ((size_t)(b*Tv + kbase + 64 + r))*(2*Dv) + Dv + h*HDv + seg);
                cp16h(Vb + r*KS_LDH + seg, vT + ((size_t)(h*HDv + r))*Mrows + b*Tv + kbase + 64 + seg);
            }
            asm volatile("cp.async.commit_group;" ::);
            asm volatile("cp.async.wait_group 1;" ::);
        } else {
            asm volatile("cp.async.wait_group 0;" ::);
        }
        __syncthreads();

        const uint32_t kst = smbase + (uint32_t)(((kt&1)*STAGEH) * 2);
        const uint32_t vst = kst + (uint32_t)(64*KS_LDH*2);

        // ---- S = Q @ K^T via ldmatrix ----
        float s[8][4];
        #pragma unroll
        for (int nc = 0; nc < 8; nc++) {
            s[nc][0] = 0.f; s[nc][1] = 0.f; s[nc][2] = 0.f; s[nc][3] = 0.f;
        }
        #pragma unroll
        for (int ncp = 0; ncp < 4; ncp++) {
            #pragma unroll
            for (int kc = 0; kc < 4; kc++) {
                uint32_t b0, b1, b2, b3;
                ldsm4(b0, b1, b2, b3, kst + bOff + (uint32_t)(((ncp*16)*KS_LDH + kc*16) * 2));
                mma_bf16(s[2*ncp][0], s[2*ncp][1], s[2*ncp][2], s[2*ncp][3],
                         qa[kc][0], qa[kc][1], qa[kc][2], qa[kc][3], b0, b1);
                mma_bf16(s[2*ncp+1][0], s[2*ncp+1][1], s[2*ncp+1][2], s[2*ncp+1][3],
                         qa[kc][0], qa[kc][1], qa[kc][2], qa[kc][3], b2, b3);
            }
        }

        // ---- causal mask ----
        if (kbase + 63 > qrow0) {
            int rowA = qrow0 + g, rowB = qrow0 + g + 8;
            #pragma unroll
            for (int nc = 0; nc < 8; nc++) {
                int c0 = kbase + nc*8 + 2*q, c1 = c0 + 1;
                if (c0 > rowA) s[nc][0] = -1e30f;
                if (c1 > rowA) s[nc][1] = -1e30f;
                if (c0 > rowB) s[nc][2] = -1e30f;
                if (c1 > rowB) s[nc][3] = -1e30f;
            }
        }

        // ---- online softmax (base 2, registers) ----
        float rmA = -1e30f, rmB = -1e30f;
        #pragma unroll
        for (int nc = 0; nc < 8; nc++) {
            rmA = fmaxf(rmA, fmaxf(s[nc][0], s[nc][1]));
            rmB = fmaxf(rmB, fmaxf(s[nc][2], s[nc][3]));
        }
        rmA = fmaxf(rmA, __shfl_xor_sync(0xffffffffu, rmA, 1));
        rmA = fmaxf(rmA, __shfl_xor_sync(0xffffffffu, rmA, 2));
        rmB = fmaxf(rmB, __shfl_xor_sync(0xffffffffu, rmB, 1));
        rmB = fmaxf(rmB, __shfl_xor_sync(0xffffffffu, rmB, 2));
        float mnA = fmaxf(mA, rmA), mnB = fmaxf(mB, rmB);
        float corrA = ex2(mA - mnA), corrB = ex2(mB - mnB);
        mA = mnA; mB = mnB;

        float rsA = 0.f, rsB = 0.f;
        #pragma unroll
        for (int nc = 0; nc < 8; nc++) {
            s[nc][0] = ex2(s[nc][0] - mnA);
            s[nc][1] = ex2(s[nc][1] - mnA);
            s[nc][2] = ex2(s[nc][2] - mnB);
            s[nc][3] = ex2(s[nc][3] - mnB);
            rsA += s[nc][0] + s[nc][1];
            rsB += s[nc][2] + s[nc][3];
        }
        rsA += __shfl_xor_sync(0xffffffffu, rsA, 1);
        rsA += __shfl_xor_sync(0xffffffffu, rsA, 2);
        rsB += __shfl_xor_sync(0xffffffffu, rsB, 1);
        rsB += __shfl_xor_sync(0xffffffffu, rsB, 2);
        lA = lA*corrA + rsA;
        lB = lB*corrB + rsB;

        #pragma unroll
        for (int nc = 0; nc < 8; nc++) {
            o[nc][0] *= corrA; o[nc][1] *= corrA;
            o[nc][2] *= corrB; o[nc][3] *= corrB;
        }

        // ---- P pack (C-frag -> A-frag, no shuffles) ----
        uint32_t pa[4][4];
        #pragma unroll
        for (int kc = 0; kc < 4; kc++) {
            pa[kc][0] = packbf(s[2*kc][0],   s[2*kc][1]);
            pa[kc][1] = packbf(s[2*kc][2],   s[2*kc][3]);
            pa[kc][2] = packbf(s[2*kc+1][0], s[2*kc+1][1]);
            pa[kc][3] = packbf(s[2*kc+1][2], s[2*kc+1][3]);
        }

        // ---- O += P @ V via ldmatrix ----
        #pragma unroll
        for (int ncp = 0; ncp < 4; ncp++) {
            #pragma unroll
            for (int kc = 0; kc < 4; kc++) {
                uint32_t v0, v1, v2, v3;
                ldsm4(v0, v1, v2, v3, vst + bOff + (uint32_t)(((ncp*16)*KS_LDH + kc*16) * 2));
                mma_bf16(o[2*ncp][0], o[2*ncp][1], o[2*ncp][2], o[2*ncp][3],
                         pa[kc][0], pa[kc][1], pa[kc][2], pa[kc][3], v0, v1);
                mma_bf16(o[2*ncp+1][0], o[2*ncp+1][1], o[2*ncp+1][2], o[2*ncp+1][3],
                         pa[kc][0], pa[kc][1], pa[kc][2], pa[kc][3], v2, v3);
            }
        }
        __syncthreads();
    }

    // ---- write O / l (bf16) ----
    float invA = 1.f / lA, invB = 1.f / lB;
    __nv_bfloat16* ob0 = out + ((size_t)(b*Tv + qrow0 + g    ))*Dv + h*HDv;
    __nv_bfloat16* ob1 = out + ((size_t)(b*Tv + qrow0 + g + 8))*Dv + h*HDv;
    #pragma unroll
    for (int nc = 0; nc < 8; nc++) {
        int c = nc*8 + 2*q;
        *(uint32_t*)&ob0[c] = packbf(o[nc][0]*invA, o[nc][1]*invA);
        *(uint32_t*)&ob1[c] = packbf(o[nc][2]*invB, o[nc][3]*invB);
    }
}

// ---------------- Parallel selective scan ----------------
__global__ __launch_bounds__(256) void scan_phase1(
    const float* __restrict__ dt, const float* __restrict__ z,
    const float* __restrict__ Bi, const float* __restrict__ A_log)
{
    int gth = blockIdx.x*256 + threadIdx.x;
    int chan = gth & 127, chunk = gth >> 7;
    int b = chan >> 6, sc = chan & 63;
    float A[16];
    #pragma unroll
    for (int st = 0; st < 16; st++) A[st] = -__expf(A_log[sc*STv + st]);
    float aP[16], bP[16];
    #pragma unroll
    for (int st = 0; st < 16; st++) { aP[st] = 1.f; bP[st] = 0.f; }
    int t0 = chunk*TSTEP;
    const float* dtp = dt + ((size_t)b*Tv + t0)*SCv + sc;
    const float* zp  = z  + ((size_t)b*Tv + t0)*SCv + sc;
    const float* Bp  = Bi + ((size_t)b*Tv + t0)*STv;
    for (int tt = 0; tt < TSTEP; tt++) {
        float dtc = dtp[(size_t)tt*SCv];
        float zc  = zp [(size_t)tt*SCv];
        float dz  = dtc*zc;
        float4 B0 = *(const float4*)&Bp[tt*STv + 0];
        float4 B1 = *(const float4*)&Bp[tt*STv + 4];
        float4 B2 = *(const float4*)&Bp[tt*STv + 8];
        float4 B3 = *(const float4*)&Bp[tt*STv + 12];
        float Bvv[16] = {B0.x,B0.y,B0.z,B0.w, B1.x,B1.y,B1.z,B1.w,
                         B2.x,B2.y,B2.z,B2.w, B3.x,B3.y,B3.z,B3.w};
        #pragma unroll
        for (int st = 0; st < 16; st++) {
            float ab = fmaf(dtc, A[st], 1.f);
            aP[st] *= ab;
            bP[st] = fmaf(ab, bP[st], dz*Bvv[st]);
        }
    }
    int base = (chan*CH + chunk)*16;
    #pragma unroll
    for (int st = 0; st < 16; st++) { g_scanA[base+st] = aP[st]; g_scanB[base+st] = bP[st]; }
}

__global__ __launch_bounds__(256) void scan_phase2()
{
    int gth = blockIdx.x*256 + threadIdx.x;
    int chan = gth >> 4, st = gth & 15;
    float s = 0.f;
    #pragma unroll
    for (int ch = 0; ch < CH; ch++) {
        int idx = (chan*CH + ch)*16 + st;
        g_scanS[idx] = s;
        s = fmaf(g_scanA[idx], s, g_scanB[idx]);
    }
}

__global__ __launch_bounds__(256) void scan_phase3(
    const float* __restrict__ dt, const float* __restrict__ z,
    const float* __restrict__ Bi, const float* __restrict__ Ci,
    const float* __restrict__ gate, const float* __restrict__ A_log,
    __nv_bfloat16* __restrict__ y)
{
    int gth = blockIdx.x*256 + threadIdx.x;
    int chan = gth & 127, chunk = gth >> 7;
    int b = chan >> 6, sc = chan & 63;
    float A[16];
    #pragma unroll
    for (int st = 0; st < 16; st++) A[st] = -__expf(A_log[sc*STv + st]);
    float state[16];
    {
        int base = (chan*CH + chunk)*16;
        #pragma unroll
        for (int st = 0; st < 16; st++) state[st] = g_scanS[base+st];
    }
    int t0 = chunk*TSTEP;
    const float* dtp = dt   + ((size_t)b*Tv + t0)*SCv + sc;
    const float* zp  = z    + ((size_t)b*Tv + t0)*SCv + sc;
    const float* gp  = gate + ((size_t)b*Tv + t0)*SCv + sc;
    const float* Bp  = Bi + ((size_t)b*Tv + t0)*STv;
    const float* Cp  = Ci + ((size_t)b*Tv + t0)*STv;
    __nv_bfloat16* yp = y + ((size_t)b*Tv + t0)*SCv + sc;
    for (int tt = 0; tt < TSTEP; tt++) {
        float dtc = dtp[(size_t)tt*SCv];
        float zc  = zp [(size_t)tt*SCv];
        float dz  = dtc*zc;
        float4 B0 = *(const float4*)&Bp[tt*STv + 0];
        float4 B1 = *(const float4*)&Bp[tt*STv + 4];
        float4 B2 = *(const float4*)&Bp[tt*STv + 8];
        float4 B3 = *(const float4*)&Bp[tt*STv + 12];
        float4 C0 = *(const float4*)&Cp[tt*STv + 0];
        float4 C1 = *(const float4*)&Cp[tt*STv + 4];
        float4 C2 = *(const float4*)&Cp[tt*STv + 8];
        float4 C3 = *(const float4*)&Cp[tt*STv + 12];
        float Bvv[16] = {B0.x,B0.y,B0.z,B0.w, B1.x,B1.y,B1.z,B1.w,
                         B2.x,B2.y,B2.z,B2.w, B3.x,B3.y,B3.z,B3.w};
        float Cvv[16] = {C0.x,C0.y,C0.z,C0.w, C1.x,C1.y,C1.z,C1.w,
                         C2.x,C2.y,C2.z,C2.w, C3.x,C3.y,C3.z,C3.w};
        float p0 = 0.f, p1 = 0.f, p2 = 0.f, p3 = 0.f;
        #pragma unroll
        for (int st = 0; st < 16; st += 4) {
            float ab;
            ab = fmaf(dtc, A[st+0], 1.f); state[st+0] = fmaf(ab, state[st+0], dz*Bvv[st+0]); p0 = fmaf(state[st+0], Cvv[st+0], p0);
            ab = fmaf(dtc, A[st+1], 1.f); state[st+1] = fmaf(ab, state[st+1], dz*Bvv[st+1]); p1 = fmaf(state[st+1], Cvv[st+1], p1);
            ab = fmaf(dtc, A[st+2], 1.f); state[st+2] = fmaf(ab, state[st+2], dz*Bvv[st+2]); p2 = fmaf(state[st+2], Cvv[st+2], p2);
            ab = fmaf(dtc, A[st+3], 1.f); state[st+3] = fmaf(ab, state[st+3], dz*Bvv[st+3]); p3 = fmaf(state[st+3], Cvv[st+3], p3);
        }
        float p = (p0 + p1) + (p2 + p3);
        yp[(size_t)tt*SCv] = __float2bfloat16(p * gp[(size_t)tt*SCv]);
    }
}

// ---------------- launch ----------------
extern "C" void kernel_launch(void* const* d_in, const int* in_sizes, int n_in,
                              void* d_out, int out_size)
{
    const float* x      = (const float*)d_in[0];
    const float* qkv_w  = (const float*)d_in[1];
    const float* o_w    = (const float*)d_in[2];
    const float* n1w    = (const float*)d_in[3];
    const float* n2w    = (const float*)d_in[4];
    const float* in_w   = (const float*)d_in[5];
    const float* out_w  = (const float*)d_in[6];
    const float* A_log  = (const float*)d_in[7];
    const float* Bp_w   = (const float*)d_in[8];
    const float* Cp_w   = (const float*)d_in[9];
    const float* dt_w   = (const float*)d_in[10];
    const float* dt_b   = (const float*)d_in[11];
    const float* gate_w = (const float*)d_in[12];
    float* out = (float*)d_out;

    __nv_bfloat16 *hb,*qkb,*vTb,*attnb,*h2b,*yb16,*wq,*wo,*wzg,*wout;
    float *x1,*zb,*gateb,*Bib,*Cib,*dtb;
    cudaGetSymbolAddress((void**)&hb,   g_h);
    cudaGetSymbolAddress((void**)&qkb,  g_qk);
    cudaGetSymbolAddress((void**)&vTb,  g_vT);
    cudaGetSymbolAddress((void**)&attnb,g_attn);
    cudaGetSymbolAddress((void**)&x1,   g_x1);
    cudaGetSymbolAddress((void**)&h2b,  g_h2);
    cudaGetSymbolAddress((void**)&zb,   g_z);
    cudaGetSymbolAddress((void**)&gateb,g_gate);
    cudaGetSymbolAddress((void**)&Bib,  g_Bi);
    cudaGetSymbolAddress((void**)&Cib,  g_Ci);
    cudaGetSymbolAddress((void**)&dtb,  g_dt);
    cudaGetSymbolAddress((void**)&yb16, g_y);
    cudaGetSymbolAddress((void**)&wq,   g_wq);
    cudaGetSymbolAddress((void**)&wo,   g_wo);
    cudaGetSymbolAddress((void**)&wzg,  g_wzg);
    cudaGetSymbolAddress((void**)&wout, g_wout);

    const int attn_smem = 2*STAGEH*2;   // 36864 B
    cudaFuncSetAttribute(attn_mma_kernel, cudaFuncAttributeMaxDynamicSharedMemorySize, attn_smem);

    // 0. convert all weights to bf16 (single launch)
    conv_all<<<8576, 256>>>(qkv_w, o_w, in_w, gate_w, out_w);
    // 1. rmsnorm1 -> bf16
    rmsnorm_kernel<<<Mrows, 256>>>(x, n1w, hb);
    // 2. qkv: Q,K -> g_qk (bf16), V -> g_vT (transposed bf16)
    gemm_bf16<<<dim3(24, 32), 256>>>(hb, wq, nullptr, qkb, vTb,
                                     Mrows, 3*Dv, 2*Dv, Dv, 2, 3, 2*Dv, 0);
    // 3. attention -> bf16
    attn_mma_kernel<<<dim3(Tv/128, Hv, Bv), 256, attn_smem>>>(qkb, vTb, attnb);
    // 4. x1 = x + attn @ o_w^T (fp32)
    gemm_bf16<<<dim3(8, 32), 256>>>(attnb, wo, x, x1, nullptr,
                                    Mrows, Dv, Dv, Dv, 1, 0, Dv, 0);
    // 5. rmsnorm2 -> bf16
    rmsnorm_kernel<<<Mrows, 256>>>(x1, n2w, h2b);
    // 6. fused z (fp32) / gate (fp32 silu)
    gemm_bf16<<<dim3(1, 32), 256>>>(h2b, wzg, nullptr, zb, gateb,
                                    Mrows, 2*SCv, SCv, Dv, 0, 4, SCv, SCv);
    // 7. fused Bi/Ci/dt
    gemm_bcd<<<64, 256>>>(zb, Bp_w, Cp_w, dt_w, dt_b, Bib, Cib, dtb);
    // 8. parallel scan -> y bf16
    scan_phase1<<<16, 256>>>(dtb, zb, Bib, A_log);
    scan_phase2<<<8, 256>>>();
    scan_phase3<<<16, 256>>>(dtb, zb, Bib, Cib, gateb, A_log, yb16);
    // 9. out = x1 + y @ out_w^T (fp32)
    gemm_bf16<<<dim3(8, 32), 256>>>(yb16, wout, x1, out, nullptr,
                                    Mrows, Dv, Dv, SCv, 1, 0, Dv, 0);
}

// round 11
// speedup vs baseline: 6.9742x; 1.1152x over previous
#include <cuda_runtime.h>
#include <cuda_bf16.h>
#include <math.h>
#include <cstdint>

#define Bv 2
#define Tv 2048
#define Dv 1024
#define Hv 16
#define HDv 64
#define SCv 64
#define STv 16
#define Mrows (Bv*Tv)   // 4096
#define EPSR 1.1920929e-07f
#define CH 64
#define TSTEP (Tv/CH)   // 32

// ---------------- scratch (device globals) ----------------
__device__ __nv_bfloat16 g_h   [Mrows*Dv];
__device__ __nv_bfloat16 g_qk  [Mrows*2*Dv];
__device__ __nv_bfloat16 g_vT  [Dv*Mrows];
__device__ __nv_bfloat16 g_attn[Mrows*Dv];
__device__ float         g_x1  [Mrows*Dv];
__device__ __nv_bfloat16 g_h2  [Mrows*Dv];
__device__ float g_z   [Mrows*SCv];
__device__ float g_gate[Mrows*SCv];
__device__ float g_Bi  [Mrows*STv];
__device__ float g_Ci  [Mrows*STv];
__device__ float g_dt  [Mrows*SCv];
__device__ __nv_bfloat16 g_y [Mrows*SCv];
__device__ float g_scanA[128*CH*16];
__device__ float g_scanB[128*CH*16];
__device__ float g_scanS[128*CH*16];
__device__ __nv_bfloat16 g_wq  [3*Dv*Dv];
__device__ __nv_bfloat16 g_wo  [Dv*Dv];
__device__ __nv_bfloat16 g_wzg [2*SCv*Dv];
__device__ __nv_bfloat16 g_wout[Dv*SCv];

__device__ __forceinline__ uint32_t packbf(float a, float b) {
    __nv_bfloat162 t = __floats2bfloat162_rn(a, b);
    return *reinterpret_cast<uint32_t*>(&t);
}
__device__ __forceinline__ float ex2(float x) {
    float y;
    asm("ex2.approx.f32 %0, %1;" : "=f"(y) : "f"(x));
    return y;
}
__device__ __forceinline__ uint32_t scale_pack(uint32_t w, float s) {
    __nv_bfloat162 t = *reinterpret_cast<__nv_bfloat162*>(&w);
    return packbf(__bfloat162float(t.x)*s, __bfloat162float(t.y)*s);
}

__device__ __forceinline__ void mma_bf16(float& d0, float& d1, float& d2, float& d3,
                                         uint32_t a0, uint32_t a1, uint32_t a2, uint32_t a3,
                                         uint32_t b0, uint32_t b1) {
    asm volatile(
        "mma.sync.aligned.m16n8k16.row.col.f32.bf16.bf16.f32 "
        "{%0,%1,%2,%3}, {%4,%5,%6,%7}, {%8,%9}, {%0,%1,%2,%3};"
        : "+f"(d0), "+f"(d1), "+f"(d2), "+f"(d3)
        : "r"(a0), "r"(a1), "r"(a2), "r"(a3), "r"(b0), "r"(b1));
}

__device__ __forceinline__ void ldsm4(uint32_t& r0, uint32_t& r1, uint32_t& r2, uint32_t& r3,
                                      uint32_t addr) {
    asm volatile("ldmatrix.sync.aligned.m8n8.x4.shared.b16 {%0,%1,%2,%3}, [%4];"
        : "=r"(r0), "=r"(r1), "=r"(r2), "=r"(r3) : "r"(addr));
}

__device__ __forceinline__ void cp16h(__nv_bfloat16* dst, const __nv_bfloat16* src) {
    uint32_t d = (uint32_t)__cvta_generic_to_shared(dst);
    asm volatile("cp.async.cg.shared.global [%0], [%1], 16;" :: "r"(d), "l"(src));
}
#define CP_COMMIT()  asm volatile("cp.async.commit_group;" ::)
#define CP_WAIT1()   asm volatile("cp.async.wait_group 1;" ::)
#define CP_WAIT0()   asm volatile("cp.async.wait_group 0;" ::)

// ---------------- merged f32 -> bf16 convert of ALL weights ----------------
#define N2_Q   1572864
#define N2_O   524288
#define N2_S   32768
__global__ __launch_bounds__(256) void conv_all(
    const float* __restrict__ qkv_w, const float* __restrict__ o_w,
    const float* __restrict__ in_w, const float* __restrict__ gate_w,
    const float* __restrict__ out_w)
{
    int i = blockIdx.x*256 + threadIdx.x;
    const float* src; __nv_bfloat162* dst; int j;
    if (i < N2_Q)                        { src = qkv_w;  dst = (__nv_bfloat162*)g_wq;   j = i; }
    else if ((j = i - N2_Q) < N2_O)      { src = o_w;    dst = (__nv_bfloat162*)g_wo; }
    else if ((j = j - N2_O) < N2_S)      { src = in_w;   dst = (__nv_bfloat162*)g_wzg; }
    else if ((j = j - N2_S) < N2_S)      { src = gate_w; dst = (__nv_bfloat162*)g_wzg + N2_S; }
    else if ((j = j - N2_S) < N2_S)      { src = out_w;  dst = (__nv_bfloat162*)g_wout; }
    else return;
    float2 v = ((const float2*)src)[j];
    dst[j] = __floats2bfloat162_rn(v.x, v.y);
}

// ---------------- RMSNorm -> bf16 ----------------
__global__ __launch_bounds__(256) void rmsnorm_kernel(
    const float* __restrict__ x, const float* __restrict__ w, __nv_bfloat16* __restrict__ o)
{
    int row = blockIdx.x;
    const float4* xr = (const float4*)(x + (size_t)row*Dv);
    float4 v = xr[threadIdx.x];
    float ss = v.x*v.x + v.y*v.y + v.z*v.z + v.w*v.w;
    #pragma unroll
    for (int off=16; off; off>>=1) ss += __shfl_xor_sync(0xffffffffu, ss, off);
    __shared__ float sm[8];
    int wid = threadIdx.x>>5, lane = threadIdx.x&31;
    if (lane==0) sm[wid] = ss;
    __syncthreads();
    float tot = sm[0]+sm[1]+sm[2]+sm[3]+sm[4]+sm[5]+sm[6]+sm[7];
    float scale = rsqrtf(tot*(1.0f/Dv) + EPSR);
    const float4* wr = (const float4*)w;
    float4 wv = wr[threadIdx.x];
    uint2 st = make_uint2(packbf(v.x*scale*wv.x, v.y*scale*wv.y),
                          packbf(v.z*scale*wv.z, v.w*scale*wv.w));
    *(uint2*)&o[(size_t)row*Dv + threadIdx.x*4] = st;
}

// ---------------- bf16 GEMM: 3-stage cp.async, ONE sync per chunk -----------
// modes: 0 fp32; 1 fp32+res; 2 bf16; 3 bf16 transposed; 4 fp32 silu
#define GLDH 40
#define GSTG (128*GLDH)
__global__ __launch_bounds__(256, 2) void gemm_bf16(
    const __nv_bfloat16* __restrict__ A, const __nv_bfloat16* __restrict__ W,
    const float* __restrict__ res, void* __restrict__ Cp, void* __restrict__ C2p,
    int M, int N, int nsplit, int K, int mode1, int mode2, int ld1, int ld2)
{
    extern __shared__ __nv_bfloat16 smg[];
    __nv_bfloat16* Asm = smg;             // 3 * GSTG
    __nv_bfloat16* Wsm = smg + 3*GSTG;

    const int tid = threadIdx.x;
    const int w   = tid >> 5;
    const int l   = tid & 31;
    const int g   = l >> 2;
    const int q   = l & 3;
    const int wm  = w >> 1;
    const int wn  = w & 1;
    const int bm  = blockIdx.y * 128;
    const int bn  = blockIdx.x * 128;

    const int lr = l & 7, lt = l >> 3;
    const uint32_t sAb = (uint32_t)__cvta_generic_to_shared(Asm);
    const uint32_t sWb = (uint32_t)__cvta_generic_to_shared(Wsm);
    const uint32_t aOff = (uint32_t)((((lt & 1)*8 + lr)*GLDH + (lt >> 1)*8) * 2);
    const uint32_t bOff = (uint32_t)((((lt >> 1)*8 + lr)*GLDH + (lt & 1)*8) * 2);

    const int crow = tid >> 2, cseg = (tid & 3) * 8;

    float c[2][8][4];
    #pragma unroll
    for (int i=0;i<2;i++)
        #pragma unroll
        for (int nj=0;nj<8;nj++)
            #pragma unroll
            for (int e=0;e<4;e++) c[i][nj][e] = 0.f;

    const int nch = K >> 5;

    // prologue: stages 0 and 1
    #pragma unroll
    for (int p = 0; p < 2; p++) {
        #pragma unroll
        for (int ii = 0; ii < 2; ii++) {
            int row = crow + ii*64;
            cp16h(Asm + p*GSTG + row*GLDH + cseg, A + (size_t)(bm + row)*K + p*32 + cseg);
            cp16h(Wsm + p*GSTG + row*GLDH + cseg, W + (size_t)(bn + row)*K + p*32 + cseg);
        }
        CP_COMMIT();
    }

    for (int i = 0; i < nch; i++) {
        if (i == nch - 1) { CP_WAIT0(); } else { CP_WAIT1(); }
        __syncthreads();
        if (i + 2 < nch) {
            int st = (i + 2) % 3, kn = (i + 2) * 32;
            #pragma unroll
            for (int ii = 0; ii < 2; ii++) {
                int row = crow + ii*64;
                cp16h(Asm + st*GSTG + row*GLDH + cseg, A + (size_t)(bm + row)*K + kn + cseg);
                cp16h(Wsm + st*GSTG + row*GLDH + cseg, W + (size_t)(bn + row)*K + kn + cseg);
            }
            CP_COMMIT();
        }

        const uint32_t sa = sAb + (uint32_t)((i % 3) * GSTG * 2);
        const uint32_t sw = sWb + (uint32_t)((i % 3) * GSTG * 2);
        #pragma unroll
        for (int kc2 = 0; kc2 < 2; kc2++) {
            uint32_t a[2][4];
            #pragma unroll
            for (int ii = 0; ii < 2; ii++)
                ldsm4(a[ii][0], a[ii][1], a[ii][2], a[ii][3],
                      sa + aOff + (uint32_t)(((wm*32 + ii*16)*GLDH + kc2*16) * 2));
            uint32_t bfr[8][2];
            #pragma unroll
            for (int ncp = 0; ncp < 4; ncp++) {
                uint32_t x0, x1, x2, x3;
                ldsm4(x0, x1, x2, x3,
                      sw + bOff + (uint32_t)(((wn*64 + ncp*16)*GLDH + kc2*16) * 2));
                bfr[2*ncp][0] = x0; bfr[2*ncp][1] = x1;
                bfr[2*ncp+1][0] = x2; bfr[2*ncp+1][1] = x3;
            }
            #pragma unroll
            for (int ii = 0; ii < 2; ii++)
                #pragma unroll
                for (int nj = 0; nj < 8; nj++)
                    mma_bf16(c[ii][nj][0], c[ii][nj][1], c[ii][nj][2], c[ii][nj][3],
                             a[ii][0], a[ii][1], a[ii][2], a[ii][3], bfr[nj][0], bfr[nj][1]);
        }
    }

    // epilogue
    #pragma unroll
    for (int i = 0; i < 2; i++) {
        #pragma unroll
        for (int nj = 0; nj < 8; nj++) {
            int row0 = bm + wm*32 + i*16 + g;
            int row1 = row0 + 8;
            int col  = bn + wn*64 + nj*8 + 2*q;
            bool first = (col < nsplit);
            int mode = first ? mode1 : mode2;
            float v0 = c[i][nj][0], v1 = c[i][nj][1], v2 = c[i][nj][2], v3 = c[i][nj][3];
            if (mode == 1) {
                v0 += res[(size_t)row0*N + col];
                v1 += res[(size_t)row0*N + col + 1];
                v2 += res[(size_t)row1*N + col];
                v3 += res[(size_t)row1*N + col + 1];
            } else if (mode == 4) {
                v0 = v0 / (1.f + __expf(-v0));
                v1 = v1 / (1.f + __expf(-v1));
                v2 = v2 / (1.f + __expf(-v2));
                v3 = v3 / (1.f + __expf(-v3));
            }
            if (mode == 2) {
                __nv_bfloat16* O = (__nv_bfloat16*)(first ? Cp : C2p);
                int ld = first ? ld1 : ld2;
                int cc = first ? col : col - nsplit;
                *(uint32_t*)&O[(size_t)row0*ld + cc] = packbf(v0, v1);
                *(uint32_t*)&O[(size_t)row1*ld + cc] = packbf(v2, v3);
            } else if (mode == 3) {
                __nv_bfloat16* O = (__nv_bfloat16*)C2p;
                int cc = col - nsplit;
                O[(size_t)cc*M + row0]     = __float2bfloat16(v0);
                O[(size_t)(cc+1)*M + row0] = __float2bfloat16(v1);
                O[(size_t)cc*M + row1]     = __float2bfloat16(v2);
                O[(size_t)(cc+1)*M + row1] = __float2bfloat16(v3);
            } else {
                float* O = (float*)(first ? Cp : C2p);
                int ld = first ? ld1 : ld2;
                int cc = first ? col : col - nsplit;
                *(float2*)&O[(size_t)row0*ld + cc] = make_float2(v0, v1);
                *(float2*)&O[(size_t)row1*ld + cc] = make_float2(v2, v3);
            }
        }
    }
}

// ---------------- fused Bi/Ci/dt (fp32) ----------------
__global__ __launch_bounds__(256) void gemm_bcd(
    const float* __restrict__ z, const float* __restrict__ Bp_w,
    const float* __restrict__ Cp_w, const float* __restrict__ dt_w,
    const float* __restrict__ dt_b,
    float* __restrict__ Bi, float* __restrict__ Ci, float* __restrict__ dt)
{
    __shared__ float Zs[64*68];
    __shared__ float Wt[64*100];
    const int tid = threadIdx.x;
    const int bm = blockIdx.x*64;

    for (int t = tid; t < 1024; t += 256) {
        int row = t >> 4, k4 = (t & 15) << 2;
        float4 v = *(const float4*)&z[(size_t)(bm + row)*SCv + k4];
        Zs[row*68 + k4 + 0] = v.x; Zs[row*68 + k4 + 1] = v.y;
        Zs[row*68 + k4 + 2] = v.z; Zs[row*68 + k4 + 3] = v.w;
    }
    for (int idx = tid; idx < 96*64; idx += 256) {
        int r = idx >> 6, c = idx & 63;
        float v = (r < 16) ? Bp_w[r*SCv + c] : (r < 32) ? Cp_w[(r-16)*SCv + c] : dt_w[(r-32)*SCv + c];
        Wt[c*100 + r] = v;
    }
    __syncthreads();

    const int ty = tid >> 4, tx = tid & 15;
    float acc[4][6];
    #pragma unroll
    for (int i=0;i<4;i++)
        #pragma unroll
        for (int j=0;j<6;j++) acc[i][j] = 0.f;

    #pragma unroll 4
    for (int k = 0; k < 64; k++) {
        float a[4], bb[6];
        #pragma unroll
        for (int i=0;i<4;i++) a[i] = Zs[(ty*4+i)*68 + k];
        #pragma unroll
        for (int j=0;j<6;j++) bb[j] = Wt[k*100 + tx*6 + j];
        #pragma unroll
        for (int i=0;i<4;i++)
            #pragma unroll
            for (int j=0;j<6;j++) acc[i][j] = fmaf(a[i], bb[j], acc[i][j]);
    }

    #pragma unroll
    for (int i=0;i<4;i++) {
        int row = bm + ty*4 + i;
        #pragma unroll
        for (int j=0;j<6;j++) {
            int c = tx*6 + j;
            float v = acc[i][j];
            if (c < 16) {
                Bi[(size_t)row*STv + c] = v;
            } else if (c < 32) {
                Ci[(size_t)row*STv + (c-16)] = v;
            } else {
                v += dt_b[c-32];
                dt[(size_t)row*SCv + (c-32)] = (v > 20.f) ? v : log1pf(__expf(v));
            }
        }
    }
}

// ---------------- Flash attention v6b: 3-stage pipeline, fixed loaders ------
#define KS_LDH 72
#define STAGEH (64*KS_LDH*2)
__global__ __launch_bounds__(256, 2) void attn_mma_kernel(
    const __nv_bfloat16* __restrict__ qk, const __nv_bfloat16* __restrict__ vT,
    __nv_bfloat16* __restrict__ out)
{
    extern __shared__ __nv_bfloat16 smh[];

    const int tid = threadIdx.x;
    const int w   = tid >> 5;
    const int l   = tid & 31;
    const int g   = l >> 2;
    const int q   = l & 3;
    const int qb  = (int)gridDim.x - 1 - (int)blockIdx.x;
    const int h = blockIdx.y, b = blockIdx.z;
    const int qrow0 = qb*128 + w*16;

    const int lr = l & 7, lt = l >> 3;
    const uint32_t smbase = (uint32_t)__cvta_generic_to_shared(smh);
    const uint32_t bOff = (uint32_t)((((lt >> 1)*8 + lr)*KS_LDH + (lt & 1)*8) * 2);

    // ---- Q fragments (fp32 scale by 0.125*log2e, then pack bf16) ----
    const float QSC = 0.125f * 1.4426950408889634f;
    uint32_t qa[4][4];
    {
        const uint32_t* Qw0 = (const uint32_t*)(qk + ((size_t)(b*Tv + qrow0 + g    ))*(2*Dv) + h*HDv);
        const uint32_t* Qw1 = (const uint32_t*)(qk + ((size_t)(b*Tv + qrow0 + g + 8))*(2*Dv) + h*HDv);
        #pragma unroll
        for (int kc = 0; kc < 4; kc++) {
            qa[kc][0] = scale_pack(Qw0[kc*8 + q    ], QSC);
            qa[kc][1] = scale_pack(Qw1[kc*8 + q    ], QSC);
            qa[kc][2] = scale_pack(Qw0[kc*8 + q + 4], QSC);
            qa[kc][3] = scale_pack(Qw1[kc*8 + q + 4], QSC);
        }
    }

    float o[8][4];
    #pragma unroll
    for (int nc = 0; nc < 8; nc++)
        #pragma unroll
        for (int e = 0; e < 4; e++) o[nc][e] = 0.f;
    float mA = -1e30f, mB = -1e30f, lA = 0.f, lB = 0.f;

    const int ntiles = 2*qb + 2;   // >= 2 always

    // prologue: issue tiles 0 and 1 (full 64 rows each: 2 cp16h per thread per buf)
    #pragma unroll
    for (int p = 0; p < 2; p++) {
        __nv_bfloat16* Kb = smh + p*STAGEH;
        __nv_bfloat16* Vb = Kb + 64*KS_LDH;
        #pragma unroll
        for (int i = 0; i < 2; i++) {
            int idx = tid + i*256;               // 0..511
            int r = idx >> 3, seg = (idx & 7) * 8;
            cp16h(Kb + r*KS_LDH + seg, qk + ((size_t)(b*Tv + p*64 + r))*(2*Dv) + Dv + h*HDv + seg);
            cp16h(Vb + r*KS_LDH + seg, vT + ((size_t)(h*HDv + r))*Mrows + b*Tv + p*64 + seg);
        }
        CP_COMMIT();
    }

    for (int kt = 0; kt < ntiles; kt++) {
        const int kbase = kt*64;
        if (kt == ntiles - 1) { CP_WAIT0(); } else { CP_WAIT1(); }
        __syncthreads();
        if (kt + 2 < ntiles) {
            int st = (kt + 2) % 3, kn = (kt + 2) * 64;
            __nv_bfloat16* Kb = smh + st*STAGEH;
            __nv_bfloat16* Vb = Kb + 64*KS_LDH;
            #pragma unroll
            for (int i = 0; i < 2; i++) {
                int idx = tid + i*256;
                int r = idx >> 3, seg = (idx & 7) * 8;
                cp16h(Kb + r*KS_LDH + seg, qk + ((size_t)(b*Tv + kn + r))*(2*Dv) + Dv + h*HDv + seg);
                cp16h(Vb + r*KS_LDH + seg, vT + ((size_t)(h*HDv + r))*Mrows + b*Tv + kn + seg);
            }
            CP_COMMIT();
        }

        const uint32_t kst = smbase + (uint32_t)(((kt % 3)*STAGEH) * 2);
        const uint32_t vst = kst + (uint32_t)(64*KS_LDH*2);

        // ---- S = Q @ K^T via ldmatrix ----
        float s[8][4];
        #pragma unroll
        for (int nc = 0; nc < 8; nc++) {
            s[nc][0] = 0.f; s[nc][1] = 0.f; s[nc][2] = 0.f; s[nc][3] = 0.f;
        }
        #pragma unroll
        for (int ncp = 0; ncp < 4; ncp++) {
            #pragma unroll
            for (int kc = 0; kc < 4; kc++) {
                uint32_t b0, b1, b2, b3;
                ldsm4(b0, b1, b2, b3, kst + bOff + (uint32_t)(((ncp*16)*KS_LDH + kc*16) * 2));
                mma_bf16(s[2*ncp][0], s[2*ncp][1], s[2*ncp][2], s[2*ncp][3],
                         qa[kc][0], qa[kc][1], qa[kc][2], qa[kc][3], b0, b1);
                mma_bf16(s[2*ncp+1][0], s[2*ncp+1][1], s[2*ncp+1][2], s[2*ncp+1][3],
                         qa[kc][0], qa[kc][1], qa[kc][2], qa[kc][3], b2, b3);
            }
        }

        // ---- causal mask ----
        if (kbase + 63 > qrow0) {
            int rowA = qrow0 + g, rowB = qrow0 + g + 8;
            #pragma unroll
            for (int nc = 0; nc < 8; nc++) {
                int c0 = kbase + nc*8 + 2*q, c1 = c0 + 1;
                if (c0 > rowA) s[nc][0] = -1e30f;
                if (c1 > rowA) s[nc][1] = -1e30f;
                if (c0 > rowB) s[nc][2] = -1e30f;
                if (c1 > rowB) s[nc][3] = -1e30f;
            }
        }

        // ---- online softmax (base 2, registers) ----
        float rmA = -1e30f, rmB = -1e30f;
        #pragma unroll
        for (int nc = 0; nc < 8; nc++) {
            rmA = fmaxf(rmA, fmaxf(s[nc][0], s[nc][1]));
            rmB = fmaxf(rmB, fmaxf(s[nc][2], s[nc][3]));
        }
        rmA = fmaxf(rmA, __shfl_xor_sync(0xffffffffu, rmA, 1));
        rmA = fmaxf(rmA, __shfl_xor_sync(0xffffffffu, rmA, 2));
        rmB = fmaxf(rmB, __shfl_xor_sync(0xffffffffu, rmB, 1));
        rmB = fmaxf(rmB, __shfl_xor_sync(0xffffffffu, rmB, 2));
        float mnA = fmaxf(mA, rmA), mnB = fmaxf(mB, rmB);
        float corrA = ex2(mA - mnA), corrB = ex2(mB - mnB);
        mA = mnA; mB = mnB;

        float rsA = 0.f, rsB = 0.f;
        #pragma unroll
        for (int nc = 0; nc < 8; nc++) {
            s[nc][0] = ex2(s[nc][0] - mnA);
            s[nc][1] = ex2(s[nc][1] - mnA);
            s[nc][2] = ex2(s[nc][2] - mnB);
            s[nc][3] = ex2(s[nc][3] - mnB);
            rsA += s[nc][0] + s[nc][1];
            rsB += s[nc][2] + s[nc][3];
        }
        rsA += __shfl_xor_sync(0xffffffffu, rsA, 1);
        rsA += __shfl_xor_sync(0xffffffffu, rsA, 2);
        rsB += __shfl_xor_sync(0xffffffffu, rsB, 1);
        rsB += __shfl_xor_sync(0xffffffffu, rsB, 2);
        lA = lA*corrA + rsA;
        lB = lB*corrB + rsB;

        #pragma unroll
        for (int nc = 0; nc < 8; nc++) {
            o[nc][0] *= corrA; o[nc][1] *= corrA;
            o[nc][2] *= corrB; o[nc][3] *= corrB;
        }

        // ---- P pack (C-frag -> A-frag, no shuffles) ----
        uint32_t pa[4][4];
        #pragma unroll
        for (int kc = 0; kc < 4; kc++) {
            pa[kc][0] = packbf(s[2*kc][0],   s[2*kc][1]);
            pa[kc][1] = packbf(s[2*kc][2],   s[2*kc][3]);
            pa[kc][2] = packbf(s[2*kc+1][0], s[2*kc+1][1]);
            pa[kc][3] = packbf(s[2*kc+1][2], s[2*kc+1][3]);
        }

        // ---- O += P @ V via ldmatrix ----
        #pragma unroll
        for (int ncp = 0; ncp < 4; ncp++) {
            #pragma unroll
            for (int kc = 0; kc < 4; kc++) {
                uint32_t v0, v1, v2, v3;
                ldsm4(v0, v1, v2, v3, vst + bOff + (uint32_t)(((ncp*16)*KS_LDH + kc*16) * 2));
                mma_bf16(o[2*ncp][0], o[2*ncp][1], o[2*ncp][2], o[2*ncp][3],
                         pa[kc][0], pa[kc][1], pa[kc][2], pa[kc][3], v0, v1);
                mma_bf16(o[2*ncp+1][0], o[2*ncp+1][1], o[2*ncp+1][2], o[2*ncp+1][3],
                         pa[kc][0], pa[kc][1], pa[kc][2], pa[kc][3], v2, v3);
            }
        }
    }

    // ---- write O / l (bf16) ----
    float invA = 1.f / lA, invB = 1.f / lB;
    __nv_bfloat16* ob0 = out + ((size_t)(b*Tv + qrow0 + g    ))*Dv + h*HDv;
    __nv_bfloat16* ob1 = out + ((size_t)(b*Tv + qrow0 + g + 8))*Dv + h*HDv;
    #pragma unroll
    for (int nc = 0; nc < 8; nc++) {
        int c = nc*8 + 2*q;
        *(uint32_t*)&ob0[c] = packbf(o[nc][0]*invA, o[nc][1]*invA);
        *(uint32_t*)&ob1[c] = packbf(o[nc][2]*invB, o[nc][3]*invB);
    }
}

// ---------------- Parallel selective scan (CH=64) ----------------
__global__ __launch_bounds__(256) void scan_phase1(
    const float* __restrict__ dt, const float* __restrict__ z,
    const float* __restrict__ Bi, const float* __restrict__ A_log)
{
    int gth = blockIdx.x*256 + threadIdx.x;
    int chan = gth & 127, chunk = gth >> 7;
    int b = chan >> 6, sc = chan & 63;
    float A[16];
    #pragma unroll
    for (int st = 0; st < 16; st++) A[st] = -__expf(A_log[sc*STv + st]);
    float aP[16], bP[16];
    #pragma unroll
    for (int st = 0; st < 16; st++) { aP[st] = 1.f; bP[st] = 0.f; }
    int t0 = chunk*TSTEP;
    const float* dtp = dt + ((size_t)b*Tv + t0)*SCv + sc;
    const float* zp  = z  + ((size_t)b*Tv + t0)*SCv + sc;
    const float* Bp  = Bi + ((size_t)b*Tv + t0)*STv;
    for (int tt = 0; tt < TSTEP; tt++) {
        float dtc = dtp[(size_t)tt*SCv];
        float zc  = zp [(size_t)tt*SCv];
        float dz  = dtc*zc;
        float4 B0 = *(const float4*)&Bp[tt*STv + 0];
        float4 B1 = *(const float4*)&Bp[tt*STv + 4];
        float4 B2 = *(const float4*)&Bp[tt*STv + 8];
        float4 B3 = *(const float4*)&Bp[tt*STv + 12];
        float Bvv[16] = {B0.x,B0.y,B0.z,B0.w, B1.x,B1.y,B1.z,B1.w,
                         B2.x,B2.y,B2.z,B2.w, B3.x,B3.y,B3.z,B3.w};
        #pragma unroll
        for (int st = 0; st < 16; st++) {
            float ab = fmaf(dtc, A[st], 1.f);
            aP[st] *= ab;
            bP[st] = fmaf(ab, bP[st], dz*Bvv[st]);
        }
    }
    int base = (chan*CH + chunk)*16;
    #pragma unroll
    for (int st = 0; st < 16; st++) { g_scanA[base+st] = aP[st]; g_scanB[base+st] = bP[st]; }
}

__global__ __launch_bounds__(256) void scan_phase2()
{
    int gth = blockIdx.x*256 + threadIdx.x;
    int chan = gth >> 4, st = gth & 15;
    float s = 0.f;
    #pragma unroll 8
    for (int ch = 0; ch < CH; ch++) {
        int idx = (chan*CH + ch)*16 + st;
        g_scanS[idx] = s;
        s = fmaf(g_scanA[idx], s, g_scanB[idx]);
    }
}

__global__ __launch_bounds__(256) void scan_phase3(
    const float* __restrict__ dt, const float* __restrict__ z,
    const float* __restrict__ Bi, const float* __restrict__ Ci,
    const float* __restrict__ gate, const float* __restrict__ A_log,
    __nv_bfloat16* __restrict__ y)
{
    int gth = blockIdx.x*256 + threadIdx.x;
    int chan = gth & 127, chunk = gth >> 7;
    int b = chan >> 6, sc = chan & 63;
    float A[16];
    #pragma unroll
    for (int st = 0; st < 16; st++) A[st] = -__expf(A_log[sc*STv + st]);
    float state[16];
    {
        int base = (chan*CH + chunk)*16;
        #pragma unroll
        for (int st = 0; st < 16; st++) state[st] = g_scanS[base+st];
    }
    int t0 = chunk*TSTEP;
    const float* dtp = dt   + ((size_t)b*Tv + t0)*SCv + sc;
    const float* zp  = z    + ((size_t)b*Tv + t0)*SCv + sc;
    const float* gp  = gate + ((size_t)b*Tv + t0)*SCv + sc;
    const float* Bp  = Bi + ((size_t)b*Tv + t0)*STv;
    const float* Cp  = Ci + ((size_t)b*Tv + t0)*STv;
    __nv_bfloat16* yp = y + ((size_t)b*Tv + t0)*SCv + sc;
    for (int tt = 0; tt < TSTEP; tt++) {
        float dtc = dtp[(size_t)tt*SCv];
        float zc  = zp [(size_t)tt*SCv];
        float dz  = dtc*zc;
        float4 B0 = *(const float4*)&Bp[tt*STv + 0];
        float4 B1 = *(const float4*)&Bp[tt*STv + 4];
        float4 B2 = *(const float4*)&Bp[tt*STv + 8];
        float4 B3 = *(const float4*)&Bp[tt*STv + 12];
        float4 C0 = *(const float4*)&Cp[tt*STv + 0];
        float4 C1 = *(const float4*)&Cp[tt*STv + 4];
        float4 C2 = *(const float4*)&Cp[tt*STv + 8];
        float4 C3 = *(const float4*)&Cp[tt*STv + 12];
        float Bvv[16] = {B0.x,B0.y,B0.z,B0.w, B1.x,B1.y,B1.z,B1.w,
                         B2.x,B2.y,B2.z,B2.w, B3.x,B3.y,B3.z,B3.w};
        float Cvv[16] = {C0.x,C0.y,C0.z,C0.w, C1.x,C1.y,C1.z,C1.w,
                         C2.x,C2.y,C2.z,C2.w, C3.x,C3.y,C3.z,C3.w};
        float p0 = 0.f, p1 = 0.f, p2 = 0.f, p3 = 0.f;
        #pragma unroll
        for (int st = 0; st < 16; st += 4) {
            float ab;
            ab = fmaf(dtc, A[st+0], 1.f); state[st+0] = fmaf(ab, state[st+0], dz*Bvv[st+0]); p0 = fmaf(state[st+0], Cvv[st+0], p0);
            ab = fmaf(dtc, A[st+1], 1.f); state[st+1] = fmaf(ab, state[st+1], dz*Bvv[st+1]); p1 = fmaf(state[st+1], Cvv[st+1], p1);
            ab = fmaf(dtc, A[st+2], 1.f); state[st+2] = fmaf(ab, state[st+2], dz*Bvv[st+2]); p2 = fmaf(state[st+2], Cvv[st+2], p2);
            ab = fmaf(dtc, A[st+3], 1.f); state[st+3] = fmaf(ab, state[st+3], dz*Bvv[st+3]); p3 = fmaf(state[st+3], Cvv[st+3], p3);
        }
        float p = (p0 + p1) + (p2 + p3);
        yp[(size_t)tt*SCv] = __float2bfloat16(p * gp[(size_t)tt*SCv]);
    }
}

// ---------------- launch ----------------
extern "C" void kernel_launch(void* const* d_in, const int* in_sizes, int n_in,
                              void* d_out, int out_size)
{
    const float* x      = (const float*)d_in[0];
    const float* qkv_w  = (const float*)d_in[1];
    const float* o_w    = (const float*)d_in[2];
    const float* n1w    = (const float*)d_in[3];
    const float* n2w    = (const float*)d_in[4];
    const float* in_w   = (const float*)d_in[5];
    const float* out_w  = (const float*)d_in[6];
    const float* A_log  = (const float*)d_in[7];
    const float* Bp_w   = (const float*)d_in[8];
    const float* Cp_w   = (const float*)d_in[9];
    const float* dt_w   = (const float*)d_in[10];
    const float* dt_b   = (const float*)d_in[11];
    const float* gate_w = (const float*)d_in[12];
    float* out = (float*)d_out;

    __nv_bfloat16 *hb,*qkb,*vTb,*attnb,*h2b,*yb16,*wq,*wo,*wzg,*wout;
    float *x1,*zb,*gateb,*Bib,*Cib,*dtb;
    cudaGetSymbolAddress((void**)&hb,   g_h);
    cudaGetSymbolAddress((void**)&qkb,  g_qk);
    cudaGetSymbolAddress((void**)&vTb,  g_vT);
    cudaGetSymbolAddress((void**)&attnb,g_attn);
    cudaGetSymbolAddress((void**)&x1,   g_x1);
    cudaGetSymbolAddress((void**)&h2b,  g_h2);
    cudaGetSymbolAddress((void**)&zb,   g_z);
    cudaGetSymbolAddress((void**)&gateb,g_gate);
    cudaGetSymbolAddress((void**)&Bib,  g_Bi);
    cudaGetSymbolAddress((void**)&Cib,  g_Ci);
    cudaGetSymbolAddress((void**)&dtb,  g_dt);
    cudaGetSymbolAddress((void**)&yb16, g_y);
    cudaGetSymbolAddress((void**)&wq,   g_wq);
    cudaGetSymbolAddress((void**)&wo,   g_wo);
    cudaGetSymbolAddress((void**)&wzg,  g_wzg);
    cudaGetSymbolAddress((void**)&wout, g_wout);

    const int gemm_smem = 6*GSTG*2;     // 61440 B
    const int attn_smem = 3*STAGEH*2;   // 55296 B
    cudaFuncSetAttribute(gemm_bf16, cudaFuncAttributeMaxDynamicSharedMemorySize, gemm_smem);
    cudaFuncSetAttribute(attn_mma_kernel, cudaFuncAttributeMaxDynamicSharedMemorySize, attn_smem);

    // 0. convert all weights to bf16 (single launch)
    conv_all<<<8576, 256>>>(qkv_w, o_w, in_w, gate_w, out_w);
    // 1. rmsnorm1 -> bf16
    rmsnorm_kernel<<<Mrows, 256>>>(x, n1w, hb);
    // 2. qkv: Q,K -> g_qk (bf16), V -> g_vT (transposed bf16)
    gemm_bf16<<<dim3(24, 32), 256, gemm_smem>>>(hb, wq, nullptr, qkb, vTb,
                                     Mrows, 3*Dv, 2*Dv, Dv, 2, 3, 2*Dv, 0);
    // 3. attention -> bf16
    attn_mma_kernel<<<dim3(Tv/128, Hv, Bv), 256, attn_smem>>>(qkb, vTb, attnb);
    // 4. x1 = x + attn @ o_w^T (fp32)
    gemm_bf16<<<dim3(8, 32), 256, gemm_smem>>>(attnb, wo, x, x1, nullptr,
                                    Mrows, Dv, Dv, Dv, 1, 0, Dv, 0);
    // 5. rmsnorm2 -> bf16
    rmsnorm_kernel<<<Mrows, 256>>>(x1, n2w, h2b);
    // 6. fused z (fp32) / gate (fp32 silu)
    gemm_bf16<<<dim3(1, 32), 256, gemm_smem>>>(h2b, wzg, nullptr, zb, gateb,
                                    Mrows, 2*SCv, SCv, Dv, 0, 4, SCv, SCv);
    // 7. fused Bi/Ci/dt
    gemm_bcd<<<64, 256>>>(zb, Bp_w, Cp_w, dt_w, dt_b, Bib, Cib, dtb);
    // 8. parallel scan -> y bf16
    scan_phase1<<<32, 256>>>(dtb, zb, Bib, A_log);
    scan_phase2<<<8, 256>>>();
    scan_phase3<<<32, 256>>>(dtb, zb, Bib, Cib, gateb, A_log, yb16);
    // 9. out = x1 + y @ out_w^T (fp32)
    gemm_bf16<<<dim3(8, 32), 256, gemm_smem>>>(yb16, wout, x1, out, nullptr,
                                    Mrows, Dv, Dv, SCv, 1, 0, Dv, 0);
}

// round 12
// speedup vs baseline: 7.3388x; 1.0523x over previous
#include <cuda_runtime.h>
#include <cuda_bf16.h>
#include <math.h>
#include <cstdint>

#define Bv 2
#define Tv 2048
#define Dv 1024
#define Hv 16
#define HDv 64
#define SCv 64
#define STv 16
#define Mrows (Bv*Tv)   // 4096
#define EPSR 1.1920929e-07f
#define CH 64
#define TSTEP (Tv/CH)   // 32
#define ZSPLIT 8

// ---------------- scratch (device globals) ----------------
__device__ __nv_bfloat16 g_h   [Mrows*Dv];
__device__ __nv_bfloat16 g_qk  [Mrows*2*Dv];
__device__ __nv_bfloat16 g_vT  [Dv*Mrows];
__device__ __nv_bfloat16 g_attn[Mrows*Dv];
__device__ float         g_x1  [Mrows*Dv];
__device__ __nv_bfloat16 g_h2  [Mrows*Dv];
__device__ float g_z   [Mrows*SCv];
__device__ float g_gate[Mrows*SCv];
__device__ float g_Bi  [Mrows*STv];
__device__ float g_Ci  [Mrows*STv];
__device__ float g_dt  [Mrows*SCv];
__device__ __nv_bfloat16 g_y [Mrows*SCv];
__device__ float g_scanA[128*CH*16];
__device__ float g_scanB[128*CH*16];
__device__ float g_scanS[128*CH*16];
__device__ float g_zgacc[ZSPLIT*Mrows*128];   // split-K partials for z/gate
__device__ __nv_bfloat16 g_wq  [3*Dv*Dv];
__device__ __nv_bfloat16 g_wo  [Dv*Dv];
__device__ __nv_bfloat16 g_wzg [2*SCv*Dv];
__device__ __nv_bfloat16 g_wout[Dv*SCv];

__device__ __forceinline__ uint32_t packbf(float a, float b) {
    __nv_bfloat162 t = __floats2bfloat162_rn(a, b);
    return *reinterpret_cast<uint32_t*>(&t);
}
__device__ __forceinline__ float ex2(float x) {
    float y;
    asm("ex2.approx.f32 %0, %1;" : "=f"(y) : "f"(x));
    return y;
}
__device__ __forceinline__ uint32_t ex2b2(uint32_t x) {
    uint32_t y;
    asm("ex2.approx.ftz.bf16x2 %0, %1;" : "=r"(y) : "r"(x));
    return y;
}
__device__ __forceinline__ float bf2sum(uint32_t w) {
    float lo = __uint_as_float(w << 16);
    float hi = __uint_as_float(w & 0xffff0000u);
    return lo + hi;
}
__device__ __forceinline__ uint32_t scale_pack(uint32_t w, float s) {
    __nv_bfloat162 t = *reinterpret_cast<__nv_bfloat162*>(&w);
    return packbf(__bfloat162float(t.x)*s, __bfloat162float(t.y)*s);
}

__device__ __forceinline__ void mma_bf16(float& d0, float& d1, float& d2, float& d3,
                                         uint32_t a0, uint32_t a1, uint32_t a2, uint32_t a3,
                                         uint32_t b0, uint32_t b1) {
    asm volatile(
        "mma.sync.aligned.m16n8k16.row.col.f32.bf16.bf16.f32 "
        "{%0,%1,%2,%3}, {%4,%5,%6,%7}, {%8,%9}, {%0,%1,%2,%3};"
        : "+f"(d0), "+f"(d1), "+f"(d2), "+f"(d3)
        : "r"(a0), "r"(a1), "r"(a2), "r"(a3), "r"(b0), "r"(b1));
}

__device__ __forceinline__ void ldsm4(uint32_t& r0, uint32_t& r1, uint32_t& r2, uint32_t& r3,
                                      uint32_t addr) {
    asm volatile("ldmatrix.sync.aligned.m8n8.x4.shared.b16 {%0,%1,%2,%3}, [%4];"
        : "=r"(r0), "=r"(r1), "=r"(r2), "=r"(r3) : "r"(addr));
}

__device__ __forceinline__ void cp16h(__nv_bfloat16* dst, const __nv_bfloat16* src) {
    uint32_t d = (uint32_t)__cvta_generic_to_shared(dst);
    asm volatile("cp.async.cg.shared.global [%0], [%1], 16;" :: "r"(d), "l"(src));
}
#define CP_COMMIT()  asm volatile("cp.async.commit_group;" ::)
#define CP_WAIT1()   asm volatile("cp.async.wait_group 1;" ::)
#define CP_WAIT0()   asm volatile("cp.async.wait_group 0;" ::)

// ---------------- merged f32 -> bf16 convert of ALL weights ----------------
#define N2_Q   1572864
#define N2_O   524288
#define N2_S   32768
__global__ __launch_bounds__(256) void conv_all(
    const float* __restrict__ qkv_w, const float* __restrict__ o_w,
    const float* __restrict__ in_w, const float* __restrict__ gate_w,
    const float* __restrict__ out_w)
{
    int i = blockIdx.x*256 + threadIdx.x;
    const float* src; __nv_bfloat162* dst; int j;
    if (i < N2_Q)                        { src = qkv_w;  dst = (__nv_bfloat162*)g_wq;   j = i; }
    else if ((j = i - N2_Q) < N2_O)      { src = o_w;    dst = (__nv_bfloat162*)g_wo; }
    else if ((j = j - N2_O) < N2_S)      { src = in_w;   dst = (__nv_bfloat162*)g_wzg; }
    else if ((j = j - N2_S) < N2_S)      { src = gate_w; dst = (__nv_bfloat162*)g_wzg + N2_S; }
    else if ((j = j - N2_S) < N2_S)      { src = out_w;  dst = (__nv_bfloat162*)g_wout; }
    else return;
    float2 v = ((const float2*)src)[j];
    dst[j] = __floats2bfloat162_rn(v.x, v.y);
}

// ---------------- RMSNorm -> bf16 ----------------
__global__ __launch_bounds__(256) void rmsnorm_kernel(
    const float* __restrict__ x, const float* __restrict__ w, __nv_bfloat16* __restrict__ o)
{
    int row = blockIdx.x;
    const float4* xr = (const float4*)(x + (size_t)row*Dv);
    float4 v = xr[threadIdx.x];
    float ss = v.x*v.x + v.y*v.y + v.z*v.z + v.w*v.w;
    #pragma unroll
    for (int off=16; off; off>>=1) ss += __shfl_xor_sync(0xffffffffu, ss, off);
    __shared__ float sm[8];
    int wid = threadIdx.x>>5, lane = threadIdx.x&31;
    if (lane==0) sm[wid] = ss;
    __syncthreads();
    float tot = sm[0]+sm[1]+sm[2]+sm[3]+sm[4]+sm[5]+sm[6]+sm[7];
    float scale = rsqrtf(tot*(1.0f/Dv) + EPSR);
    const float4* wr = (const float4*)w;
    float4 wv = wr[threadIdx.x];
    uint2 st = make_uint2(packbf(v.x*scale*wv.x, v.y*scale*wv.y),
                          packbf(v.z*scale*wv.z, v.w*scale*wv.w));
    *(uint2*)&o[(size_t)row*Dv + threadIdx.x*4] = st;
}

// ---------------- bf16 GEMM: 3-stage cp.async, split-K capable --------------
// modes: 0 fp32 (with split-K offset); 1 fp32+res; 2 bf16; 3 bf16 transposed; 4 fp32 silu
#define GLDH 40
#define GSTG (128*GLDH)
__global__ __launch_bounds__(256, 2) void gemm_bf16(
    const __nv_bfloat16* __restrict__ A, const __nv_bfloat16* __restrict__ W,
    const float* __restrict__ res, void* __restrict__ Cp, void* __restrict__ C2p,
    int M, int N, int nsplit, int K, int Kstride, int mode1, int mode2, int ld1, int ld2)
{
    extern __shared__ __nv_bfloat16 smg[];
    __nv_bfloat16* Asm = smg;
    __nv_bfloat16* Wsm = smg + 3*GSTG;

    const int tid = threadIdx.x;
    const int w   = tid >> 5;
    const int l   = tid & 31;
    const int g   = l >> 2;
    const int q   = l & 3;
    const int wm  = w >> 1;
    const int wn  = w & 1;
    const int bm  = blockIdx.y * 128;
    const int bn  = blockIdx.x * 128;

    const __nv_bfloat16* Ab = A + (size_t)blockIdx.z * K;
    const __nv_bfloat16* Wb = W + (size_t)blockIdx.z * K;

    const int lr = l & 7, lt = l >> 3;
    const uint32_t sAb = (uint32_t)__cvta_generic_to_shared(Asm);
    const uint32_t sWb = (uint32_t)__cvta_generic_to_shared(Wsm);
    const uint32_t aOff = (uint32_t)((((lt & 1)*8 + lr)*GLDH + (lt >> 1)*8) * 2);
    const uint32_t bOff = (uint32_t)((((lt >> 1)*8 + lr)*GLDH + (lt & 1)*8) * 2);

    const int crow = tid >> 2, cseg = (tid & 3) * 8;

    float c[2][8][4];
    #pragma unroll
    for (int i=0;i<2;i++)
        #pragma unroll
        for (int nj=0;nj<8;nj++)
            #pragma unroll
            for (int e=0;e<4;e++) c[i][nj][e] = 0.f;

    const int nch = K >> 5;

    #pragma unroll
    for (int p = 0; p < 2; p++) {
        #pragma unroll
        for (int ii = 0; ii < 2; ii++) {
            int row = crow + ii*64;
            cp16h(Asm + p*GSTG + row*GLDH + cseg, Ab + (size_t)(bm + row)*Kstride + p*32 + cseg);
            cp16h(Wsm + p*GSTG + row*GLDH + cseg, Wb + (size_t)(bn + row)*Kstride + p*32 + cseg);
        }
        CP_COMMIT();
    }

    for (int i = 0; i < nch; i++) {
        if (i == nch - 1) { CP_WAIT0(); } else { CP_WAIT1(); }
        __syncthreads();
        if (i + 2 < nch) {
            int st = (i + 2) % 3, kn = (i + 2) * 32;
            #pragma unroll
            for (int ii = 0; ii < 2; ii++) {
                int row = crow + ii*64;
                cp16h(Asm + st*GSTG + row*GLDH + cseg, Ab + (size_t)(bm + row)*Kstride + kn + cseg);
                cp16h(Wsm + st*GSTG + row*GLDH + cseg, Wb + (size_t)(bn + row)*Kstride + kn + cseg);
            }
            CP_COMMIT();
        }

        const uint32_t sa = sAb + (uint32_t)((i % 3) * GSTG * 2);
        const uint32_t sw = sWb + (uint32_t)((i % 3) * GSTG * 2);
        #pragma unroll
        for (int kc2 = 0; kc2 < 2; kc2++) {
            uint32_t a[2][4];
            #pragma unroll
            for (int ii = 0; ii < 2; ii++)
                ldsm4(a[ii][0], a[ii][1], a[ii][2], a[ii][3],
                      sa + aOff + (uint32_t)(((wm*32 + ii*16)*GLDH + kc2*16) * 2));
            uint32_t bfr[8][2];
            #pragma unroll
            for (int ncp = 0; ncp < 4; ncp++) {
                uint32_t x0, x1, x2, x3;
                ldsm4(x0, x1, x2, x3,
                      sw + bOff + (uint32_t)(((wn*64 + ncp*16)*GLDH + kc2*16) * 2));
                bfr[2*ncp][0] = x0; bfr[2*ncp][1] = x1;
                bfr[2*ncp+1][0] = x2; bfr[2*ncp+1][1] = x3;
            }
            #pragma unroll
            for (int ii = 0; ii < 2; ii++)
                #pragma unroll
                for (int nj = 0; nj < 8; nj++)
                    mma_bf16(c[ii][nj][0], c[ii][nj][1], c[ii][nj][2], c[ii][nj][3],
                             a[ii][0], a[ii][1], a[ii][2], a[ii][3], bfr[nj][0], bfr[nj][1]);
        }
    }

    #pragma unroll
    for (int i = 0; i < 2; i++) {
        #pragma unroll
        for (int nj = 0; nj < 8; nj++) {
            int row0 = bm + wm*32 + i*16 + g;
            int row1 = row0 + 8;
            int col  = bn + wn*64 + nj*8 + 2*q;
            bool first = (col < nsplit);
            int mode = first ? mode1 : mode2;
            float v0 = c[i][nj][0], v1 = c[i][nj][1], v2 = c[i][nj][2], v3 = c[i][nj][3];
            if (mode == 1) {
                v0 += res[(size_t)row0*N + col];
                v1 += res[(size_t)row0*N + col + 1];
                v2 += res[(size_t)row1*N + col];
                v3 += res[(size_t)row1*N + col + 1];
            } else if (mode == 4) {
                v0 = v0 / (1.f + __expf(-v0));
                v1 = v1 / (1.f + __expf(-v1));
                v2 = v2 / (1.f + __expf(-v2));
                v3 = v3 / (1.f + __expf(-v3));
            }
            if (mode == 2) {
                __nv_bfloat16* O = (__nv_bfloat16*)(first ? Cp : C2p);
                int ld = first ? ld1 : ld2;
                int cc = first ? col : col - nsplit;
                *(uint32_t*)&O[(size_t)row0*ld + cc] = packbf(v0, v1);
                *(uint32_t*)&O[(size_t)row1*ld + cc] = packbf(v2, v3);
            } else if (mode == 3) {
                __nv_bfloat16* O = (__nv_bfloat16*)C2p;
                int cc = col - nsplit;
                O[(size_t)cc*M + row0]     = __float2bfloat16(v0);
                O[(size_t)(cc+1)*M + row0] = __float2bfloat16(v1);
                O[(size_t)cc*M + row1]     = __float2bfloat16(v2);
                O[(size_t)(cc+1)*M + row1] = __float2bfloat16(v3);
            } else {
                float* O = (float*)(first ? Cp : C2p);
                int ld = first ? ld1 : ld2;
                int cc = first ? col : col - nsplit;
                if (mode == 0) O += (size_t)blockIdx.z * M * ld;
                *(float2*)&O[(size_t)row0*ld + cc] = make_float2(v0, v1);
                *(float2*)&O[(size_t)row1*ld + cc] = make_float2(v2, v3);
            }
        }
    }
}

// ---------------- z/gate split-K reduce + silu ----------------
__global__ __launch_bounds__(256) void zg_reduce(
    float* __restrict__ z, float* __restrict__ gate)
{
    int idx = blockIdx.x*256 + threadIdx.x;   // 0..Mrows*128-1
    float s = 0.f;
    #pragma unroll
    for (int p = 0; p < ZSPLIT; p++) s += g_zgacc[(size_t)p*Mrows*128 + idx];
    int row = idx >> 7, col = idx & 127;
    if (col < SCv) z[(size_t)row*SCv + col] = s;
    else gate[(size_t)row*SCv + col - SCv] = s / (1.f + __expf(-s));
}

// ---------------- fused Bi/Ci/dt (fp32) ----------------
__global__ __launch_bounds__(256) void gemm_bcd(
    const float* __restrict__ z, const float* __restrict__ Bp_w,
    const float* __restrict__ Cp_w, const float* __restrict__ dt_w,
    const float* __restrict__ dt_b,
    float* __restrict__ Bi, float* __restrict__ Ci, float* __restrict__ dt)
{
    __shared__ float Zs[64*68];
    __shared__ float Wt[64*100];
    const int tid = threadIdx.x;
    const int bm = blockIdx.x*64;

    for (int t = tid; t < 1024; t += 256) {
        int row = t >> 4, k4 = (t & 15) << 2;
        float4 v = *(const float4*)&z[(size_t)(bm + row)*SCv + k4];
        Zs[row*68 + k4 + 0] = v.x; Zs[row*68 + k4 + 1] = v.y;
        Zs[row*68 + k4 + 2] = v.z; Zs[row*68 + k4 + 3] = v.w;
    }
    for (int idx = tid; idx < 96*64; idx += 256) {
        int r = idx >> 6, c = idx & 63;
        float v = (r < 16) ? Bp_w[r*SCv + c] : (r < 32) ? Cp_w[(r-16)*SCv + c] : dt_w[(r-32)*SCv + c];
        Wt[c*100 + r] = v;
    }
    __syncthreads();

    const int ty = tid >> 4, tx = tid & 15;
    float acc[4][6];
    #pragma unroll
    for (int i=0;i<4;i++)
        #pragma unroll
        for (int j=0;j<6;j++) acc[i][j] = 0.f;

    #pragma unroll 4
    for (int k = 0; k < 64; k++) {
        float a[4], bb[6];
        #pragma unroll
        for (int i=0;i<4;i++) a[i] = Zs[(ty*4+i)*68 + k];
        #pragma unroll
        for (int j=0;j<6;j++) bb[j] = Wt[k*100 + tx*6 + j];
        #pragma unroll
        for (int i=0;i<4;i++)
            #pragma unroll
            for (int j=0;j<6;j++) acc[i][j] = fmaf(a[i], bb[j], acc[i][j]);
    }

    #pragma unroll
    for (int i=0;i<4;i++) {
        int row = bm + ty*4 + i;
        #pragma unroll
        for (int j=0;j<6;j++) {
            int c = tx*6 + j;
            float v = acc[i][j];
            if (c < 16) {
                Bi[(size_t)row*STv + c] = v;
            } else if (c < 32) {
                Ci[(size_t)row*STv + (c-16)] = v;
            } else {
                v += dt_b[c-32];
                dt[(size_t)row*SCv + (c-32)] = (v > 20.f) ? v : log1pf(__expf(v));
            }
        }
    }
}

// ---------------- Flash attention v7: bf16x2 ex2 softmax ----------------
#define KS_LDH 72
#define STAGEH (64*KS_LDH*2)
__global__ __launch_bounds__(256, 2) void attn_mma_kernel(
    const __nv_bfloat16* __restrict__ qk, const __nv_bfloat16* __restrict__ vT,
    __nv_bfloat16* __restrict__ out)
{
    extern __shared__ __nv_bfloat16 smh[];

    const int tid = threadIdx.x;
    const int w   = tid >> 5;
    const int l   = tid & 31;
    const int g   = l >> 2;
    const int q   = l & 3;
    const int qb  = (int)gridDim.x - 1 - (int)blockIdx.x;
    const int h = blockIdx.y, b = blockIdx.z;
    const int qrow0 = qb*128 + w*16;

    const int lr = l & 7, lt = l >> 3;
    const uint32_t smbase = (uint32_t)__cvta_generic_to_shared(smh);
    const uint32_t bOff = (uint32_t)((((lt >> 1)*8 + lr)*KS_LDH + (lt & 1)*8) * 2);

    const float QSC = 0.125f * 1.4426950408889634f;
    uint32_t qa[4][4];
    {
        const uint32_t* Qw0 = (const uint32_t*)(qk + ((size_t)(b*Tv + qrow0 + g    ))*(2*Dv) + h*HDv);
        const uint32_t* Qw1 = (const uint32_t*)(qk + ((size_t)(b*Tv + qrow0 + g + 8))*(2*Dv) + h*HDv);
        #pragma unroll
        for (int kc = 0; kc < 4; kc++) {
            qa[kc][0] = scale_pack(Qw0[kc*8 + q    ], QSC);
            qa[kc][1] = scale_pack(Qw1[kc*8 + q    ], QSC);
            qa[kc][2] = scale_pack(Qw0[kc*8 + q + 4], QSC);
            qa[kc][3] = scale_pack(Qw1[kc*8 + q + 4], QSC);
        }
    }

    float o[8][4];
    #pragma unroll
    for (int nc = 0; nc < 8; nc++)
        #pragma unroll
        for (int e = 0; e < 4; e++) o[nc][e] = 0.f;
    float mA = -1e30f, mB = -1e30f, lA = 0.f, lB = 0.f;

    const int ntiles = 2*qb + 2;

    #pragma unroll
    for (int p = 0; p < 2; p++) {
        __nv_bfloat16* Kb = smh + p*STAGEH;
        __nv_bfloat16* Vb = Kb + 64*KS_LDH;
        #pragma unroll
        for (int i = 0; i < 2; i++) {
            int idx = tid + i*256;
            int r = idx >> 3, seg = (idx & 7) * 8;
            cp16h(Kb + r*KS_LDH + seg, qk + ((size_t)(b*Tv + p*64 + r))*(2*Dv) + Dv + h*HDv + seg);
            cp16h(Vb + r*KS_LDH + seg, vT + ((size_t)(h*HDv + r))*Mrows + b*Tv + p*64 + seg);
        }
        CP_COMMIT();
    }

    for (int kt = 0; kt < ntiles; kt++) {
        const int kbase = kt*64;
        if (kt == ntiles - 1) { CP_WAIT0(); } else { CP_WAIT1(); }
        __syncthreads();
        if (kt + 2 < ntiles) {
            int st = (kt + 2) % 3, kn = (kt + 2) * 64;
            __nv_bfloat16* Kb = smh + st*STAGEH;
            __nv_bfloat16* Vb = Kb + 64*KS_LDH;
            #pragma unroll
            for (int i = 0; i < 2; i++) {
                int idx = tid + i*256;
                int r = idx >> 3, seg = (idx & 7) * 8;
                cp16h(Kb + r*KS_LDH + seg, qk + ((size_t)(b*Tv + kn + r))*(2*Dv) + Dv + h*HDv + seg);
                cp16h(Vb + r*KS_LDH + seg, vT + ((size_t)(h*HDv + r))*Mrows + b*Tv + kn + seg);
            }
            CP_COMMIT();
        }

        const uint32_t kst = smbase + (uint32_t)(((kt % 3)*STAGEH) * 2);
        const uint32_t vst = kst + (uint32_t)(64*KS_LDH*2);

        // ---- S = Q @ K^T via ldmatrix ----
        float s[8][4];
        #pragma unroll
        for (int nc = 0; nc < 8; nc++) {
            s[nc][0] = 0.f; s[nc][1] = 0.f; s[nc][2] = 0.f; s[nc][3] = 0.f;
        }
        #pragma unroll
        for (int ncp = 0; ncp < 4; ncp++) {
            #pragma unroll
            for (int kc = 0; kc < 4; kc++) {
                uint32_t b0, b1, b2, b3;
                ldsm4(b0, b1, b2, b3, kst + bOff + (uint32_t)(((ncp*16)*KS_LDH + kc*16) * 2));
                mma_bf16(s[2*ncp][0], s[2*ncp][1], s[2*ncp][2], s[2*ncp][3],
                         qa[kc][0], qa[kc][1], qa[kc][2], qa[kc][3], b0, b1);
                mma_bf16(s[2*ncp+1][0], s[2*ncp+1][1], s[2*ncp+1][2], s[2*ncp+1][3],
                         qa[kc][0], qa[kc][1], qa[kc][2], qa[kc][3], b2, b3);
            }
        }

        // ---- causal mask ----
        if (kbase + 63 > qrow0) {
            int rowA = qrow0 + g, rowB = qrow0 + g + 8;
            #pragma unroll
            for (int nc = 0; nc < 8; nc++) {
                int c0 = kbase + nc*8 + 2*q, c1 = c0 + 1;
                if (c0 > rowA) s[nc][0] = -1e30f;
                if (c1 > rowA) s[nc][1] = -1e30f;
                if (c0 > rowB) s[nc][2] = -1e30f;
                if (c1 > rowB) s[nc][3] = -1e30f;
            }
        }

        // ---- online softmax: max in fp32, p via bf16x2 ex2 (packed A-frag) ----
        float rmA = -1e30f, rmB = -1e30f;
        #pragma unroll
        for (int nc = 0; nc < 8; nc++) {
            rmA = fmaxf(rmA, fmaxf(s[nc][0], s[nc][1]));
            rmB = fmaxf(rmB, fmaxf(s[nc][2], s[nc][3]));
        }
        rmA = fmaxf(rmA, __shfl_xor_sync(0xffffffffu, rmA, 1));
        rmA = fmaxf(rmA, __shfl_xor_sync(0xffffffffu, rmA, 2));
        rmB = fmaxf(rmB, __shfl_xor_sync(0xffffffffu, rmB, 1));
        rmB = fmaxf(rmB, __shfl_xor_sync(0xffffffffu, rmB, 2));
        float mnA = fmaxf(mA, rmA), mnB = fmaxf(mB, rmB);
        float corrA = ex2(mA - mnA), corrB = ex2(mB - mnB);
        mA = mnA; mB = mnB;

        float rsA = 0.f, rsB = 0.f;
        uint32_t pa[4][4];
        #pragma unroll
        for (int kc = 0; kc < 4; kc++) {
            uint32_t d0 = packbf(s[2*kc][0]   - mnA, s[2*kc][1]   - mnA);
            uint32_t d1 = packbf(s[2*kc][2]   - mnB, s[2*kc][3]   - mnB);
            uint32_t d2 = packbf(s[2*kc+1][0] - mnA, s[2*kc+1][1] - mnA);
            uint32_t d3 = packbf(s[2*kc+1][2] - mnB, s[2*kc+1][3] - mnB);
            pa[kc][0] = ex2b2(d0);
            pa[kc][1] = ex2b2(d1);
            pa[kc][2] = ex2b2(d2);
            pa[kc][3] = ex2b2(d3);
            rsA += bf2sum(pa[kc][0]) + bf2sum(pa[kc][2]);
            rsB += bf2sum(pa[kc][1]) + bf2sum(pa[kc][3]);
        }
        rsA += __shfl_xor_sync(0xffffffffu, rsA, 1);
        rsA += __shfl_xor_sync(0xffffffffu, rsA, 2);
        rsB += __shfl_xor_sync(0xffffffffu, rsB, 1);
        rsB += __shfl_xor_sync(0xffffffffu, rsB, 2);
        lA = lA*corrA + rsA;
        lB = lB*corrB + rsB;

        #pragma unroll
        for (int nc = 0; nc < 8; nc++) {
            o[nc][0] *= corrA; o[nc][1] *= corrA;
            o[nc][2] *= corrB; o[nc][3] *= corrB;
        }

        // ---- O += P @ V via ldmatrix ----
        #pragma unroll
        for (int ncp = 0; ncp < 4; ncp++) {
            #pragma unroll
            for (int kc = 0; kc < 4; kc++) {
                uint32_t v0, v1, v2, v3;
                ldsm4(v0, v1, v2, v3, vst + bOff + (uint32_t)(((ncp*16)*KS_LDH + kc*16) * 2));
                mma_bf16(o[2*ncp][0], o[2*ncp][1], o[2*ncp][2], o[2*ncp][3],
                         pa[kc][0], pa[kc][1], pa[kc][2], pa[kc][3], v0, v1);
                mma_bf16(o[2*ncp+1][0], o[2*ncp+1][1], o[2*ncp+1][2], o[2*ncp+1][3],
                         pa[kc][0], pa[kc][1], pa[kc][2], pa[kc][3], v2, v3);
            }
        }
    }

    // ---- write O / l (bf16) ----
    float invA = 1.f / lA, invB = 1.f / lB;
    __nv_bfloat16* ob0 = out + ((size_t)(b*Tv + qrow0 + g    ))*Dv + h*HDv;
    __nv_bfloat16* ob1 = out + ((size_t)(b*Tv + qrow0 + g + 8))*Dv + h*HDv;
    #pragma unroll
    for (int nc = 0; nc < 8; nc++) {
        int c = nc*8 + 2*q;
        *(uint32_t*)&ob0[c] = packbf(o[nc][0]*invA, o[nc][1]*invA);
        *(uint32_t*)&ob1[c] = packbf(o[nc][2]*invB, o[nc][3]*invB);
    }
}

// ---------------- Parallel selective scan (CH=64) ----------------
__global__ __launch_bounds__(256) void scan_phase1(
    const float* __restrict__ dt, const float* __restrict__ z,
    const float* __restrict__ Bi, const float* __restrict__ A_log)
{
    int gth = blockIdx.x*256 + threadIdx.x;
    int chan = gth & 127, chunk = gth >> 7;
    int b = chan >> 6, sc = chan & 63;
    float A[16];
    #pragma unroll
    for (int st = 0; st < 16; st++) A[st] = -__expf(A_log[sc*STv + st]);
    float aP[16], bP[16];
    #pragma unroll
    for (int st = 0; st < 16; st++) { aP[st] = 1.f; bP[st] = 0.f; }
    int t0 = chunk*TSTEP;
    const float* dtp = dt + ((size_t)b*Tv + t0)*SCv + sc;
    const float* zp  = z  + ((size_t)b*Tv + t0)*SCv + sc;
    const float* Bp  = Bi + ((size_t)b*Tv + t0)*STv;
    for (int tt = 0; tt < TSTEP; tt++) {
        float dtc = dtp[(size_t)tt*SCv];
        float zc  = zp [(size_t)tt*SCv];
        float dz  = dtc*zc;
        float4 B0 = *(const float4*)&Bp[tt*STv + 0];
        float4 B1 = *(const float4*)&Bp[tt*STv + 4];
        float4 B2 = *(const float4*)&Bp[tt*STv + 8];
        float4 B3 = *(const float4*)&Bp[tt*STv + 12];
        float Bvv[16] = {B0.x,B0.y,B0.z,B0.w, B1.x,B1.y,B1.z,B1.w,
                         B2.x,B2.y,B2.z,B2.w, B3.x,B3.y,B3.z,B3.w};
        #pragma unroll
        for (int st = 0; st < 16; st++) {
            float ab = fmaf(dtc, A[st], 1.f);
            aP[st] *= ab;
            bP[st] = fmaf(ab, bP[st], dz*Bvv[st]);
        }
    }
    int base = (chan*CH + chunk)*16;
    #pragma unroll
    for (int st = 0; st < 16; st++) { g_scanA[base+st] = aP[st]; g_scanB[base+st] = bP[st]; }
}

__global__ __launch_bounds__(256) void scan_phase2()
{
    int gth = blockIdx.x*256 + threadIdx.x;
    int chan = gth >> 4, st = gth & 15;
    float s = 0.f;
    #pragma unroll 8
    for (int ch = 0; ch < CH; ch++) {
        int idx = (chan*CH + ch)*16 + st;
        g_scanS[idx] = s;
        s = fmaf(g_scanA[idx], s, g_scanB[idx]);
    }
}

__global__ __launch_bounds__(256) void scan_phase3(
    const float* __restrict__ dt, const float* __restrict__ z,
    const float* __restrict__ Bi, const float* __restrict__ Ci,
    const float* __restrict__ gate, const float* __restrict__ A_log,
    __nv_bfloat16* __restrict__ y)
{
    int gth = blockIdx.x*256 + threadIdx.x;
    int chan = gth & 127, chunk = gth >> 7;
    int b = chan >> 6, sc = chan & 63;
    float A[16];
    #pragma unroll
    for (int st = 0; st < 16; st++) A[st] = -__expf(A_log[sc*STv + st]);
    float state[16];
    {
        int base = (chan*CH + chunk)*16;
        #pragma unroll
        for (int st = 0; st < 16; st++) state[st] = g_scanS[base+st];
    }
    int t0 = chunk*TSTEP;
    const float* dtp = dt   + ((size_t)b*Tv + t0)*SCv + sc;
    const float* zp  = z    + ((size_t)b*Tv + t0)*SCv + sc;
    const float* gp  = gate + ((size_t)b*Tv + t0)*SCv + sc;
    const float* Bp  = Bi + ((size_t)b*Tv + t0)*STv;
    const float* Cp  = Ci + ((size_t)b*Tv + t0)*STv;
    __nv_bfloat16* yp = y + ((size_t)b*Tv + t0)*SCv + sc;
    for (int tt = 0; tt < TSTEP; tt++) {
        float dtc = dtp[(size_t)tt*SCv];
        float zc  = zp [(size_t)tt*SCv];
        float dz  = dtc*zc;
        float4 B0 = *(const float4*)&Bp[tt*STv + 0];
        float4 B1 = *(const float4*)&Bp[tt*STv + 4];
        float4 B2 = *(const float4*)&Bp[tt*STv + 8];
        float4 B3 = *(const float4*)&Bp[tt*STv + 12];
        float4 C0 = *(const float4*)&Cp[tt*STv + 0];
        float4 C1 = *(const float4*)&Cp[tt*STv + 4];
        float4 C2 = *(const float4*)&Cp[tt*STv + 8];
        float4 C3 = *(const float4*)&Cp[tt*STv + 12];
        float Bvv[16] = {B0.x,B0.y,B0.z,B0.w, B1.x,B1.y,B1.z,B1.w,
                         B2.x,B2.y,B2.z,B2.w, B3.x,B3.y,B3.z,B3.w};
        float Cvv[16] = {C0.x,C0.y,C0.z,C0.w, C1.x,C1.y,C1.z,C1.w,
                         C2.x,C2.y,C2.z,C2.w, C3.x,C3.y,C3.z,C3.w};
        float p0 = 0.f, p1 = 0.f, p2 = 0.f, p3 = 0.f;
        #pragma unroll
        for (int st = 0; st < 16; st += 4) {
            float ab;
            ab = fmaf(dtc, A[st+0], 1.f); state[st+0] = fmaf(ab, state[st+0], dz*Bvv[st+0]); p0 = fmaf(state[st+0], Cvv[st+0], p0);
            ab = fmaf(dtc, A[st+1], 1.f); state[st+1] = fmaf(ab, state[st+1], dz*Bvv[st+1]); p1 = fmaf(state[st+1], Cvv[st+1], p1);
            ab = fmaf(dtc, A[st+2], 1.f); state[st+2] = fmaf(ab, state[st+2], dz*Bvv[st+2]); p2 = fmaf(state[st+2], Cvv[st+2], p2);
            ab = fmaf(dtc, A[st+3], 1.f); state[st+3] = fmaf(ab, state[st+3], dz*Bvv[st+3]); p3 = fmaf(state[st+3], Cvv[st+3], p3);
        }
        float p = (p0 + p1) + (p2 + p3);
        yp[(size_t)tt*SCv] = __float2bfloat16(p * gp[(size_t)tt*SCv]);
    }
}

// ---------------- launch ----------------
extern "C" void kernel_launch(void* const* d_in, const int* in_sizes, int n_in,
                              void* d_out, int out_size)
{
    const float* x      = (const float*)d_in[0];
    const float* qkv_w  = (const float*)d_in[1];
    const float* o_w    = (const float*)d_in[2];
    const float* n1w    = (const float*)d_in[3];
    const float* n2w    = (const float*)d_in[4];
    const float* in_w   = (const float*)d_in[5];
    const float* out_w  = (const float*)d_in[6];
    const float* A_log  = (const float*)d_in[7];
    const float* Bp_w   = (const float*)d_in[8];
    const float* Cp_w   = (const float*)d_in[9];
    const float* dt_w   = (const float*)d_in[10];
    const float* dt_b   = (const float*)d_in[11];
    const float* gate_w = (const float*)d_in[12];
    float* out = (float*)d_out;

    __nv_bfloat16 *hb,*qkb,*vTb,*attnb,*h2b,*yb16,*wq,*wo,*wzg,*wout;
    float *x1,*zb,*gateb,*Bib,*Cib,*dtb,*zgacc;
    cudaGetSymbolAddress((void**)&hb,   g_h);
    cudaGetSymbolAddress((void**)&qkb,  g_qk);
    cudaGetSymbolAddress((void**)&vTb,  g_vT);
    cudaGetSymbolAddress((void**)&attnb,g_attn);
    cudaGetSymbolAddress((void**)&x1,   g_x1);
    cudaGetSymbolAddress((void**)&h2b,  g_h2);
    cudaGetSymbolAddress((void**)&zb,   g_z);
    cudaGetSymbolAddress((void**)&gateb,g_gate);
    cudaGetSymbolAddress((void**)&Bib,  g_Bi);
    cudaGetSymbolAddress((void**)&Cib,  g_Ci);
    cudaGetSymbolAddress((void**)&dtb,  g_dt);
    cudaGetSymbolAddress((void**)&yb16, g_y);
    cudaGetSymbolAddress((void**)&zgacc,g_zgacc);
    cudaGetSymbolAddress((void**)&wq,   g_wq);
    cudaGetSymbolAddress((void**)&wo,   g_wo);
    cudaGetSymbolAddress((void**)&wzg,  g_wzg);
    cudaGetSymbolAddress((void**)&wout, g_wout);

    const int gemm_smem = 6*GSTG*2;     // 61440 B
    const int attn_smem = 3*STAGEH*2;   // 55296 B
    cudaFuncSetAttribute(gemm_bf16, cudaFuncAttributeMaxDynamicSharedMemorySize, gemm_smem);
    cudaFuncSetAttribute(attn_mma_kernel, cudaFuncAttributeMaxDynamicSharedMemorySize, attn_smem);

    // 0. convert all weights to bf16 (single launch)
    conv_all<<<8576, 256>>>(qkv_w, o_w, in_w, gate_w, out_w);
    // 1. rmsnorm1 -> bf16
    rmsnorm_kernel<<<Mrows, 256>>>(x, n1w, hb);
    // 2. qkv: Q,K -> g_qk (bf16), V -> g_vT (transposed bf16)
    gemm_bf16<<<dim3(24, 32), 256, gemm_smem>>>(hb, wq, nullptr, qkb, vTb,
                                     Mrows, 3*Dv, 2*Dv, Dv, Dv, 2, 3, 2*Dv, 0);
    // 3. attention -> bf16
    attn_mma_kernel<<<dim3(Tv/128, Hv, Bv), 256, attn_smem>>>(qkb, vTb, attnb);
    // 4. x1 = x + attn @ o_w^T (fp32)
    gemm_bf16<<<dim3(8, 32), 256, gemm_smem>>>(attnb, wo, x, x1, nullptr,
                                    Mrows, Dv, Dv, Dv, Dv, 1, 1, Dv, 0);
    // 5. rmsnorm2 -> bf16
    rmsnorm_kernel<<<Mrows, 256>>>(x1, n2w, h2b);
    // 6. z/gate split-K (8 splits of K=128) -> partials, then reduce+silu
    gemm_bf16<<<dim3(1, 32, ZSPLIT), 256, gemm_smem>>>(h2b, wzg, nullptr, zgacc, nullptr,
                                    Mrows, 2*SCv, 2*SCv, Dv/ZSPLIT, Dv, 0, 0, 2*SCv, 0);
    zg_reduce<<<Mrows*128/256, 256>>>(zb, gateb);
    // 7. fused Bi/Ci/dt
    gemm_bcd<<<64, 256>>>(zb, Bp_w, Cp_w, dt_w, dt_b, Bib, Cib, dtb);
    // 8. parallel scan -> y bf16
    scan_phase1<<<32, 256>>>(dtb, zb, Bib, A_log);
    scan_phase2<<<8, 256>>>();
    scan_phase3<<<32, 256>>>(dtb, zb, Bib, Cib, gateb, A_log, yb16);
    // 9. out = x1 + y @ out_w^T (fp32)
    gemm_bf16<<<dim3(8, 32), 256, gemm_smem>>>(yb16, wout, x1, out, nullptr,
                                    Mrows, Dv, Dv, SCv, SCv, 1, 1, Dv, 0);
}